// round 10
// baseline (speedup 1.0000x reference)
#include <cuda_runtime.h>
#include <cuda_bf16.h>
#include <math.h>
#include <stdint.h>

#define BB   128
#define SS   256
#define DD   128
#define DIM  256
#define NHH  4
#define BS   (BB*SS)

__device__ float g_h  [BS*DD];
__device__ float g_xn [BS*DD];
__device__ float g_big[BS*512];
__device__ float g_xca[BS*DIM];
__device__ float g_q  [BS*DIM];
__device__ float g_k  [BS*DIM];
__device__ float g_v  [BS*DIM];
__device__ float g_ht [BS*DIM];
__device__ float g_gi [BS*DD];
__device__ float g_gf [BS*DD];
__device__ float g_gz [BS*DD];
__device__ float g_go [BS*DD];
__device__ float g_y  [BS*DD];
__device__ float g_ip [BB*NHH*SS];
__device__ float g_fp [BB*NHH*SS];
__device__ float g_slf[BB*NHH*SS];
__device__ float g_ek [BB*NHH*SS];
__device__ float g_pmx[BB*NHH*SS];
__device__ float g_wT [2*4*4096];

// ---------------- fused embedding + LayerNorm ----------------
__global__ void embed_ln_kernel(const int* __restrict__ x, const float* __restrict__ emb,
                                const float* __restrict__ w,
                                float* __restrict__ h, float* __restrict__ xn) {
    int row = blockIdx.x;
    int tid = threadIdx.x;  // 128
    __shared__ float r1[4], r2[4];
    float v = emb[x[row] * DD + tid];
    h[(size_t)row * DD + tid] = v;
    float s = v;
    #pragma unroll
    for (int o = 16; o; o >>= 1) s += __shfl_xor_sync(0xffffffffu, s, o);
    if ((tid & 31) == 0) r1[tid >> 5] = s;
    __syncthreads();
    float mu = (r1[0] + r1[1] + r1[2] + r1[3]) * (1.0f / DD);
    float d = v - mu;
    float sq = d * d;
    #pragma unroll
    for (int o = 16; o; o >>= 1) sq += __shfl_xor_sync(0xffffffffu, sq, o);
    if ((tid & 31) == 0) r2[tid >> 5] = sq;
    __syncthreads();
    float var = (r2[0] + r2[1] + r2[2] + r2[3]) * (1.0f / DD);
    xn[(size_t)row * DD + tid] = d * rsqrtf(var + 1e-5f) * w[tid];
}

__global__ void ln128_kernel(const float* __restrict__ x, const float* __restrict__ w,
                             float* __restrict__ out) {
    int row = blockIdx.x;
    int tid = threadIdx.x;  // 128
    __shared__ float r1[4], r2[4];
    float v = x[(size_t)row * DD + tid];
    float s = v;
    #pragma unroll
    for (int o = 16; o; o >>= 1) s += __shfl_xor_sync(0xffffffffu, s, o);
    if ((tid & 31) == 0) r1[tid >> 5] = s;
    __syncthreads();
    float mu = (r1[0] + r1[1] + r1[2] + r1[3]) * (1.0f / DD);
    float d = v - mu;
    float sq = d * d;
    #pragma unroll
    for (int o = 16; o; o >>= 1) sq += __shfl_xor_sync(0xffffffffu, sq, o);
    if ((tid & 31) == 0) r2[tid >> 5] = sq;
    __syncthreads();
    float var = (r2[0] + r2[1] + r2[2] + r2[3]) * (1.0f / DD);
    out[(size_t)row * DD + tid] = d * rsqrtf(var + 1e-5f) * w[tid];
}

// one warp per group; optional residual add. Compile-time dims -> no div/mod.
template<int Drow, int GS>
__global__ void groupln_kernel(const float* __restrict__ x, const float* __restrict__ w,
                               const float* __restrict__ addTo, float* __restrict__ out) {
    int gw = (blockIdx.x * blockDim.x + threadIdx.x) >> 5;
    int lane = threadIdx.x & 31;
    constexpr int GPR = Drow / GS;
    int row = gw / GPR, g = gw % GPR;    // GPR is 4 (power of 2) -> shifts
    size_t base = (size_t)row * Drow + g * GS;
    if (GS == 64) {
        float v0 = x[base + lane], v1 = x[base + 32 + lane];
        float s = v0 + v1;
        #pragma unroll
        for (int o = 16; o; o >>= 1) s += __shfl_xor_sync(0xffffffffu, s, o);
        float mu = s * (1.0f / 64.0f);
        float e0 = v0 - mu, e1 = v1 - mu;
        float sq = e0 * e0 + e1 * e1;
        #pragma unroll
        for (int o = 16; o; o >>= 1) sq += __shfl_xor_sync(0xffffffffu, sq, o);
        float r = rsqrtf(sq * (1.0f / 64.0f) + 1e-5f);
        float o0 = e0 * r * w[g * GS + lane];
        float o1 = e1 * r * w[g * GS + 32 + lane];
        if (addTo) { o0 += addTo[base + lane]; o1 += addTo[base + 32 + lane]; }
        out[base + lane] = o0;
        out[base + 32 + lane] = o1;
    } else {
        float v0 = x[base + lane];
        float s = v0;
        #pragma unroll
        for (int o = 16; o; o >>= 1) s += __shfl_xor_sync(0xffffffffu, s, o);
        float mu = s * (1.0f / 32.0f);
        float e0 = v0 - mu;
        float sq = e0 * e0;
        #pragma unroll
        for (int o = 16; o; o >>= 1) sq += __shfl_xor_sync(0xffffffffu, sq, o);
        float r = rsqrtf(sq * (1.0f / 32.0f) + 1e-5f);
        float o0 = e0 * r * w[g * GS + lane];
        if (addTo) o0 += addTo[base + lane];
        out[base + lane] = o0;
    }
}

// compile-time C/LDX -> cheap masks/shifts
template<int LDX, int C>
__global__ void conv_silu_kernel(const float* __restrict__ x,
                                 const float* __restrict__ w, const float* __restrict__ bias,
                                 float* __restrict__ out) {
    int idx = blockIdx.x * blockDim.x + threadIdx.x;
    int c = idx & (C - 1);
    int s = (idx / C) & (SS - 1);
    int b = idx / (C * SS);
    const float* xp = x + ((size_t)b * SS) * LDX + c;
    float acc = bias[c];
    #pragma unroll
    for (int j = 0; j < 4; j++) {
        int sj = s + j - 3;
        if (sj >= 0) acc += xp[(size_t)sj * LDX] * w[c * 4 + j];
    }
    out[idx] = acc / (1.0f + __expf(-acc));
}

// transpose sLSTM block-diag weights, half at a time
__global__ void transpose_w_kernel(const float* __restrict__ ig, const float* __restrict__ fg,
                                   const float* __restrict__ zg, const float* __restrict__ og,
                                   float* __restrict__ wT, int off) {
    int idx = off + blockIdx.x * blockDim.x + threadIdx.x;
    int layer = idx >> 14;
    int arr = (idx >> 12) & 3;
    int r = idx & 4095;
    int h = r >> 10, e = (r >> 5) & 31, d = r & 31;
    const float* src = (arr == 0) ? ig : (arr == 1) ? fg : (arr == 2) ? zg : og;
    wT[layer * 16384 + arr * 4096 + h * 1024 + d * 32 + e] =
        src[layer * 4096 + h * 1024 + e * 32 + d];
}

// ---------------- fused mLSTM qkv + gate projections ----------------
__global__ void __launch_bounds__(256)
qkv_gates_kernel(const float* __restrict__ xca, const float* __restrict__ big,
                 const float* __restrict__ qw, const float* __restrict__ kw,
                 const float* __restrict__ vw,
                 const float* __restrict__ igw, const float* __restrict__ igb,
                 const float* __restrict__ fgw, const float* __restrict__ fgb,
                 float* __restrict__ q, float* __restrict__ k, float* __restrict__ v,
                 float* __restrict__ ip, float* __restrict__ fp) {
    int bs = blockIdx.x;
    int c = threadIdx.x;
    __shared__ float sx[DIM], si[DIM];
    __shared__ float sred[8][256];
    sx[c] = xca[(size_t)bs * DIM + c];
    si[c] = big[(size_t)bs * 512 + c];
    __syncthreads();
    int blk = c >> 3, e = c & 7;
    const float* qp = qw + blk * 64 + e * 8;
    const float* kp = kw + blk * 64 + e * 8;
    const float* vp = vw + blk * 64 + e * 8;
    float aq = 0, ak = 0, av = 0;
    #pragma unroll
    for (int d = 0; d < 8; d++) {
        float xv = sx[blk * 8 + d];
        aq += xv * qp[d];
        ak += xv * kp[d];
        av += si[blk * 8 + d] * vp[d];
    }
    q[(size_t)bs * DIM + c] = aq;
    k[(size_t)bs * DIM + c] = ak;
    v[(size_t)bs * DIM + c] = av;
    #pragma unroll
    for (int h = 0; h < 4; h++) {
        float wi0 = igw[h * 768 + c], wi1 = igw[h * 768 + 256 + c], wi2 = igw[h * 768 + 512 + c];
        float wf0 = fgw[h * 768 + c], wf1 = fgw[h * 768 + 256 + c], wf2 = fgw[h * 768 + 512 + c];
        sred[h][c]     = aq * wi0 + ak * wi1 + av * wi2;
        sred[4 + h][c] = aq * wf0 + ak * wf1 + av * wf2;
    }
    __syncthreads();
    int w = c >> 5, lane = c & 31;
    float s = 0.f;
    #pragma unroll
    for (int t = 0; t < 8; t++) s += sred[w][lane + t * 32];
    #pragma unroll
    for (int o = 16; o; o >>= 1) s += __shfl_xor_sync(0xffffffffu, s, o);
    if (lane == 0) {
        int b = bs >> 8, st = bs & 255;
        int h = w & 3;
        if (w < 4) ip[(b * NHH + h) * SS + st] = s + igb[h];
        else       fp[(b * NHH + h) * SS + st] = s + fgb[h];
    }
}

// ---------------- parallel gate prefix: one warp per (b,h) ----------------
__global__ void mlstm_prefix_kernel(const float* __restrict__ ip, const float* __restrict__ fp,
                                    float* __restrict__ slf, float* __restrict__ ek,
                                    float* __restrict__ pmx) {
    int warp = (blockIdx.x * blockDim.x + threadIdx.x) >> 5;
    int lane = threadIdx.x & 31;
    size_t base = (size_t)warp * SS + lane * 8;
    float fv[8], iv[8];
    {
        float4 a = *(const float4*)(fp + base);
        float4 b = *(const float4*)(fp + base + 4);
        fv[0]=a.x; fv[1]=a.y; fv[2]=a.z; fv[3]=a.w; fv[4]=b.x; fv[5]=b.y; fv[6]=b.z; fv[7]=b.w;
        float4 c = *(const float4*)(ip + base);
        float4 d = *(const float4*)(ip + base + 4);
        iv[0]=c.x; iv[1]=c.y; iv[2]=c.z; iv[3]=c.w; iv[4]=d.x; iv[5]=d.y; iv[6]=d.z; iv[7]=d.w;
    }
    float ls[8], lsum = 0.f;
    #pragma unroll
    for (int t = 0; t < 8; t++) {
        float f = fv[t];
        ls[t] = fminf(f, 0.f) - log1pf(expf(-fabsf(f)));
        lsum += ls[t];
    }
    float run = lsum;
    #pragma unroll
    for (int o = 1; o < 32; o <<= 1) {
        float vv = __shfl_up_sync(0xffffffffu, run, o);
        if (lane >= o) run += vv;
    }
    float c = run - lsum;
    float sl[8], ev[8], lmax = -1e30f;
    #pragma unroll
    for (int t = 0; t < 8; t++) {
        c += ls[t];
        sl[t] = c;
        ev[t] = iv[t] - c;
        lmax = fmaxf(lmax, ev[t]);
    }
    float rmax = lmax;
    #pragma unroll
    for (int o = 1; o < 32; o <<= 1) {
        float vv = __shfl_up_sync(0xffffffffu, rmax, o);
        if (lane >= o) rmax = fmaxf(rmax, vv);
    }
    float exclmax = __shfl_up_sync(0xffffffffu, rmax, 1);
    if (lane == 0) exclmax = -1e30f;
    float pm[8];
    float cm = exclmax;
    #pragma unroll
    for (int t = 0; t < 8; t++) {
        cm = fmaxf(cm, ev[t]);
        pm[t] = cm;
    }
    *(float4*)(slf + base)     = make_float4(sl[0], sl[1], sl[2], sl[3]);
    *(float4*)(slf + base + 4) = make_float4(sl[4], sl[5], sl[6], sl[7]);
    *(float4*)(ek + base)      = make_float4(ev[0], ev[1], ev[2], ev[3]);
    *(float4*)(ek + base + 4)  = make_float4(ev[4], ev[5], ev[6], ev[7]);
    *(float4*)(pmx + base)     = make_float4(pm[0], pm[1], pm[2], pm[3]);
    *(float4*)(pmx + base + 4) = make_float4(pm[4], pm[5], pm[6], pm[7]);
}

// ---------------- attention: 512 threads, 2 lanes per query (split-D) ----------------
// warp w owns 16 queries [r*16, r*16+16); even lane handles dims 0-31, odd lane 32-63.
// Dot combined via shfl_xor(1). Registers ~85/thread -> 16 warps = 4/SMSP.
#define ATTN_SMEM (2 * SS * 64 * sizeof(float))
__global__ void __launch_bounds__(512, 1)
mlstm_attn_kernel(const float* __restrict__ q, const float* __restrict__ k,
                  const float* __restrict__ v,
                  const float* __restrict__ slf, const float* __restrict__ ek,
                  const float* __restrict__ pmx, float* __restrict__ out) {
    int bh = blockIdx.x;
    int b = bh >> 2, h = bh & 3;
    extern __shared__ float sm[];
    float* sk = sm;
    float* sv = sm + SS * 64;
    __shared__ float s_e[SS], s_px[SS], s_lf[SS];
    int tid = threadIdx.x;
    const float* kb = k + (size_t)b * SS * DIM + h * 64;
    const float* vb = v + (size_t)b * SS * DIM + h * 64;
    for (int i = tid; i < SS * 64; i += 512) {
        int s = i >> 6, d = i & 63;
        sk[i] = kb[(size_t)s * DIM + d];
        sv[i] = vb[(size_t)s * DIM + d];
    }
    for (int i = tid; i < SS; i += 512) {
        s_e[i]  = ek [(size_t)bh * SS + i];
        s_px[i] = pmx[(size_t)bh * SS + i];
        s_lf[i] = slf[(size_t)bh * SS + i];
    }
    __syncthreads();

    int w = tid >> 5, lane = tid & 31;
    int r = (w < 8) ? w : (23 - w);     // pair (r, 15-r) on same SMSP
    int qi = r * 16 + (lane >> 1);
    int half = lane & 1;
    const float* qb = q + ((size_t)b * SS + qi) * DIM + h * 64 + half * 32;
    float qreg[32], acc[32];
    #pragma unroll
    for (int d = 0; d < 32; d += 4) {
        float4 t = *(const float4*)(qb + d);
        qreg[d] = t.x; qreg[d+1] = t.y; qreg[d+2] = t.z; qreg[d+3] = t.w;
        acc[d] = 0.f; acc[d+1] = 0.f; acc[d+2] = 0.f; acc[d+3] = 0.f;
    }
    float sc = 0.f;
    float mpx = s_px[qi];
    int kmax = r * 16 + 15;
    for (int kk = 0; kk <= kmax; kk++) {
        const float* kr = sk + kk * 64 + half * 32;
        float d0 = 0, d1 = 0, d2 = 0, d3 = 0;
        #pragma unroll
        for (int d = 0; d < 32; d += 4) {
            float4 kv = *(const float4*)(kr + d);
            d0 += qreg[d] * kv.x;   d1 += qreg[d+1] * kv.y;
            d2 += qreg[d+2] * kv.z; d3 += qreg[d+3] * kv.w;
        }
        float dot = (d0 + d1) + (d2 + d3);
        dot += __shfl_xor_sync(0xffffffffu, dot, 1);    // combine d-halves
        float coeff = dot * 0.125f * __expf(s_e[kk] - mpx);
        if (kk > qi) coeff = 0.f;
        sc += coeff;
        const float* vr = sv + kk * 64 + half * 32;
        #pragma unroll
        for (int d = 0; d < 32; d += 4) {
            float4 vv = *(const float4*)(vr + d);
            acc[d]   += coeff * vv.x; acc[d+1] += coeff * vv.y;
            acc[d+2] += coeff * vv.z; acc[d+3] += coeff * vv.w;
        }
    }
    float maxd = s_lf[qi] + mpx;
    float inv = 1.0f / (fmaxf(fabsf(sc), __expf(-maxd)) + 1e-6f);
    float* ob = out + ((size_t)b * SS + qi) * DIM + h * 64 + half * 32;
    #pragma unroll
    for (int d = 0; d < 32; d += 4) {
        float4 ov;
        ov.x = acc[d] * inv;   ov.y = acc[d+1] * inv;
        ov.z = acc[d+2] * inv; ov.w = acc[d+3] * inv;
        *(float4*)(ob + d) = ov;
    }
}

// sLSTM block-diagonal gates — transposed (lane-contiguous) weights
__global__ void slstm_bd_kernel(const float* __restrict__ xc, const float* __restrict__ xn,
                                const float* __restrict__ wT,
                                float* __restrict__ gi, float* __restrict__ gf,
                                float* __restrict__ gz, float* __restrict__ go) {
    int idx = blockIdx.x * blockDim.x + threadIdx.x;
    int c = idx & 127;
    size_t bs = (size_t)(idx >> 7);
    int h = c >> 5, e = c & 31;
    const float* base = wT + h * 1024 + e;
    const float* xcb = xc + bs * DD + h * 32;
    const float* xnb = xn + bs * DD + h * 32;
    float a1 = 0, a2 = 0, a3 = 0, a4 = 0;
    #pragma unroll
    for (int d = 0; d < 32; d++) {
        float xv = xcb[d], nv = xnb[d];
        int o = d * 32;
        a1 += xv * base[o];
        a2 += xv * base[4096 + o];
        a3 += nv * base[8192 + o];
        a4 += nv * base[12288 + o];
    }
    gi[idx] = a1; gf[idx] = a2; gz[idx] = a3; go[idx] = a4;
}

#define SCAN_SMEM (4 * 32 * 128 * sizeof(float))
__global__ void __launch_bounds__(512, 1)
slstm_scan_kernel(const float* __restrict__ gi, const float* __restrict__ gf,
                  const float* __restrict__ gz, const float* __restrict__ go,
                  const float* __restrict__ rw, const float* __restrict__ bias,
                  float* __restrict__ y) {
    int b = blockIdx.x;
    int tid = threadIdx.x;
    extern __shared__ float srw[];
    __shared__ float hs[128], cs[128], ns[128], ms[128];
    __shared__ float sb[512], srec[512];
    for (int i = tid; i < 16384; i += 512) srw[i] = rw[i];
    sb[tid] = bias[tid];
    if (tid < 128) { hs[tid] = 0.f; cs[tid] = 0.f; ns[tid] = 0.f; ms[tid] = 0.f; }
    __syncthreads();
    int h = tid >> 7, j = tid & 127;
    const float* wp = srw + h * 4096 + j;
    const float* hb = hs + h * 32;
    for (int t = 0; t < SS; t++) {
        float r0 = 0, r1 = 0;
        #pragma unroll
        for (int d = 0; d < 32; d += 2) {
            r0 += hb[d]     * wp[d * 128];
            r1 += hb[d + 1] * wp[(d + 1) * 128];
        }
        srec[tid] = r0 + r1;
        __syncthreads();
        if (tid < 128) {
            size_t gidx = ((size_t)b * SS + t) * DD + tid;
            int hh = tid >> 5, d = tid & 31;
            int rb = hh * 128;
            float ix = gi[gidx] + srec[rb + d]      + sb[rb + d];
            float fx = gf[gidx] + srec[rb + 32 + d] + sb[rb + 32 + d];
            float zx = gz[gidx] + srec[rb + 64 + d] + sb[rb + 64 + d];
            float ox = go[gidx] + srec[rb + 96 + d] + sb[rb + 96 + d];
            float ls  = fminf(fx, 0.f) - log1pf(__expf(-fabsf(fx)));
            float lpm = ms[tid] + ls;
            float mn  = fmaxf(ix, lpm);
            float ig  = __expf(ix - mn);
            float fg  = __expf(lpm - mn);
            float cn  = fg * cs[tid] + ig * tanhf(zx);
            float nn  = fg * ns[tid] + ig;
            float hn  = cn / (nn * (1.0f + __expf(-ox)));
            cs[tid] = cn; ns[tid] = nn; ms[tid] = mn; hs[tid] = hn;
            y[gidx] = hn;
        }
        __syncthreads();
    }
}

// ---------------- tf32 tensor-core GEMM: 128x128 tile, 8 warps x (64x32) ----------------
__device__ __forceinline__ uint32_t f2tf32(float f) {
    uint32_t r;
    asm("cvt.rna.tf32.f32 %0, %1;" : "=r"(r) : "f"(f));
    return r;
}
__device__ __forceinline__ void mma_tf32(float* d, const uint32_t* a, const uint32_t* b) {
    asm volatile(
        "mma.sync.aligned.m16n8k8.row.col.f32.tf32.tf32.f32 "
        "{%0,%1,%2,%3}, {%4,%5,%6,%7}, {%8,%9}, {%0,%1,%2,%3};"
        : "+f"(d[0]), "+f"(d[1]), "+f"(d[2]), "+f"(d[3])
        : "r"(a[0]), "r"(a[1]), "r"(a[2]), "r"(a[3]), "r"(b[0]), "r"(b[1]));
}

template<int AOP>
__global__ void __launch_bounds__(256)
gemm_tf32_kernel(const float* __restrict__ A, const float* __restrict__ A2,
                 const float* __restrict__ A3, const float* __restrict__ Askip,
                 const float* __restrict__ W, float* __restrict__ C,
                 int N, int Kd, int accum) {
    __shared__ __align__(16) uint32_t sA[2][128][20];
    __shared__ __align__(16) uint32_t sB[2][128][20];
    const int bm = blockIdx.y * 128, bn = blockIdx.x * 128;
    const int tid = threadIdx.x;
    const int wid = tid >> 5, lane = tid & 31;
    const int wm = wid & 1, wn = wid >> 1;
    const int g = lane >> 2, t = lane & 3;
    const int arow = tid >> 1;
    const int acg = (tid & 1) << 3;
    float acc[4][4][4] = {};

    auto loadA4 = [&](int gr, int gk) -> float4 {
        float4 r;
        if (AOP == 0) {
            r = *(const float4*)(A + (size_t)gr * Kd + gk);
        } else if (AOP == 1) {
            float4 gg = *(const float4*)(A + (size_t)gr * 512 + gk);
            float4 u  = *(const float4*)(A + (size_t)gr * 512 + 256 + gk);
            r.x = 0.5f * gg.x * (1.0f + erff(gg.x * 0.70710678f)) * u.x;
            r.y = 0.5f * gg.y * (1.0f + erff(gg.y * 0.70710678f)) * u.y;
            r.z = 0.5f * gg.z * (1.0f + erff(gg.z * 0.70710678f)) * u.z;
            r.w = 0.5f * gg.w * (1.0f + erff(gg.w * 0.70710678f)) * u.w;
        } else {
            float4 hv = *(const float4*)(A  + (size_t)gr * 256 + gk);
            float4 xv = *(const float4*)(A2 + (size_t)gr * 256 + gk);
            float4 sk = *(const float4*)(Askip + gk);
            float4 zv = *(const float4*)(A3 + (size_t)gr * 512 + 256 + gk);
            r.x = (hv.x + sk.x * xv.x) * (zv.x / (1.0f + __expf(-zv.x)));
            r.y = (hv.y + sk.y * xv.y) * (zv.y / (1.0f + __expf(-zv.y)));
            r.z = (hv.z + sk.z * xv.z) * (zv.z / (1.0f + __expf(-zv.z)));
            r.w = (hv.w + sk.w * xv.w) * (zv.w / (1.0f + __expf(-zv.w)));
        }
        return r;
    };
    auto cvt4 = [&](float4 f) -> uint4 {
        return make_uint4(f2tf32(f.x), f2tf32(f.y), f2tf32(f.z), f2tf32(f.w));
    };
    auto compute = [&](int bf) {
        #pragma unroll
        for (int ks = 0; ks < 2; ks++) {
            int kb = ks * 8;
            uint32_t af[4][4], bfr[4][2];
            #pragma unroll
            for (int mi = 0; mi < 4; mi++) {
                int r0 = wm * 64 + mi * 16 + g;
                af[mi][0] = sA[bf][r0][kb + t];
                af[mi][1] = sA[bf][r0 + 8][kb + t];
                af[mi][2] = sA[bf][r0][kb + t + 4];
                af[mi][3] = sA[bf][r0 + 8][kb + t + 4];
            }
            #pragma unroll
            for (int ni = 0; ni < 4; ni++) {
                int c0 = wn * 32 + ni * 8 + g;
                bfr[ni][0] = sB[bf][c0][kb + t];
                bfr[ni][1] = sB[bf][c0][kb + t + 4];
            }
            #pragma unroll
            for (int mi = 0; mi < 4; mi++)
                #pragma unroll
                for (int ni = 0; ni < 4; ni++)
                    mma_tf32(acc[mi][ni], af[mi], bfr[ni]);
        }
    };

    {
        float4 alo = loadA4(bm + arow, acg);
        float4 ahi = loadA4(bm + arow, acg + 4);
        float4 wlo = *(const float4*)(W + (size_t)(bn + arow) * Kd + acg);
        float4 whi = *(const float4*)(W + (size_t)(bn + arow) * Kd + acg + 4);
        *(uint4*)&sA[0][arow][acg]     = cvt4(alo);
        *(uint4*)&sA[0][arow][acg + 4] = cvt4(ahi);
        *(uint4*)&sB[0][arow][acg]     = cvt4(wlo);
        *(uint4*)&sB[0][arow][acg + 4] = cvt4(whi);
    }
    __syncthreads();

    int buf = 0;
    for (int k0 = 16; k0 < Kd; k0 += 16) {
        float4 alo = loadA4(bm + arow, k0 + acg);
        float4 ahi = loadA4(bm + arow, k0 + acg + 4);
        float4 wlo = *(const float4*)(W + (size_t)(bn + arow) * Kd + k0 + acg);
        float4 whi = *(const float4*)(W + (size_t)(bn + arow) * Kd + k0 + acg + 4);
        compute(buf);
        int nb = buf ^ 1;
        *(uint4*)&sA[nb][arow][acg]     = cvt4(alo);
        *(uint4*)&sA[nb][arow][acg + 4] = cvt4(ahi);
        *(uint4*)&sB[nb][arow][acg]     = cvt4(wlo);
        *(uint4*)&sB[nb][arow][acg + 4] = cvt4(whi);
        __syncthreads();
        buf = nb;
    }
    compute(buf);

    #pragma unroll
    for (int mi = 0; mi < 4; mi++) {
        #pragma unroll
        for (int ni = 0; ni < 4; ni++) {
            int grow = bm + wm * 64 + mi * 16 + g;
            int gcol = bn + wn * 32 + ni * 8 + t * 2;
            float* p0 = C + (size_t)grow * N + gcol;
            float* p1 = C + (size_t)(grow + 8) * N + gcol;
            if (accum) {
                float2 x0 = *(float2*)p0, x1 = *(float2*)p1;
                x0.x += acc[mi][ni][0]; x0.y += acc[mi][ni][1];
                x1.x += acc[mi][ni][2]; x1.y += acc[mi][ni][3];
                *(float2*)p0 = x0; *(float2*)p1 = x1;
            } else {
                *(float2*)p0 = make_float2(acc[mi][ni][0], acc[mi][ni][1]);
                *(float2*)p1 = make_float2(acc[mi][ni][2], acc[mi][ni][3]);
            }
        }
    }
}

extern "C" void kernel_launch(void* const* d_in, const int* in_sizes, int n_in,
                              void* d_out, int out_size) {
    const int*   x          = (const int*)  d_in[0];
    const float* emb        = (const float*)d_in[1];
    const float* m_ln_w     = (const float*)d_in[2];
    const float* m_up_w     = (const float*)d_in[3];
    const float* m_conv_w   = (const float*)d_in[4];
    const float* m_conv_b   = (const float*)d_in[5];
    const float* m_q_w      = (const float*)d_in[6];
    const float* m_k_w      = (const float*)d_in[7];
    const float* m_v_w      = (const float*)d_in[8];
    const float* m_ig_w     = (const float*)d_in[9];
    const float* m_ig_b     = (const float*)d_in[10];
    const float* m_fg_w     = (const float*)d_in[11];
    const float* m_fg_b     = (const float*)d_in[12];
    const float* m_on_w     = (const float*)d_in[13];
    const float* m_skip     = (const float*)d_in[14];
    const float* m_down_w   = (const float*)d_in[15];
    const float* s_ln1_w    = (const float*)d_in[16];
    const float* s_conv_w   = (const float*)d_in[17];
    const float* s_conv_b   = (const float*)d_in[18];
    const float* s_ig_w     = (const float*)d_in[19];
    const float* s_fg_w     = (const float*)d_in[20];
    const float* s_zg_w     = (const float*)d_in[21];
    const float* s_og_w     = (const float*)d_in[22];
    const float* s_rec_w    = (const float*)d_in[23];
    const float* s_bias     = (const float*)d_in[24];
    const float* s_gn_w     = (const float*)d_in[25];
    const float* s_ln2_w    = (const float*)d_in[26];
    const float* s_ff_up_w  = (const float*)d_in[27];
    const float* s_ff_down_w= (const float*)d_in[28];
    const float* post_norm_w= (const float*)d_in[29];
    float* out = (float*)d_out;

    float *h_, *xn_, *big_, *xca_, *q_, *k_, *v_, *ht_;
    float *gi_, *gf_, *gz_, *go_, *y_, *ip_, *fp_, *slf_, *ek_, *pmx_, *wT_;
    cudaGetSymbolAddress((void**)&h_,   g_h);
    cudaGetSymbolAddress((void**)&xn_,  g_xn);
    cudaGetSymbolAddress((void**)&big_, g_big);
    cudaGetSymbolAddress((void**)&xca_, g_xca);
    cudaGetSymbolAddress((void**)&q_,   g_q);
    cudaGetSymbolAddress((void**)&k_,   g_k);
    cudaGetSymbolAddress((void**)&v_,   g_v);
    cudaGetSymbolAddress((void**)&ht_,  g_ht);
    cudaGetSymbolAddress((void**)&gi_,  g_gi);
    cudaGetSymbolAddress((void**)&gf_,  g_gf);
    cudaGetSymbolAddress((void**)&gz_,  g_gz);
    cudaGetSymbolAddress((void**)&go_,  g_go);
    cudaGetSymbolAddress((void**)&y_,   g_y);
    cudaGetSymbolAddress((void**)&ip_,  g_ip);
    cudaGetSymbolAddress((void**)&fp_,  g_fp);
    cudaGetSymbolAddress((void**)&slf_, g_slf);
    cudaGetSymbolAddress((void**)&ek_,  g_ek);
    cudaGetSymbolAddress((void**)&pmx_, g_pmx);
    cudaGetSymbolAddress((void**)&wT_,  g_wT);

    cudaFuncSetAttribute(mlstm_attn_kernel, cudaFuncAttributeMaxDynamicSharedMemorySize, (int)ATTN_SMEM);
    cudaFuncSetAttribute(slstm_scan_kernel, cudaFuncAttributeMaxDynamicSharedMemorySize, (int)SCAN_SMEM);

    // slots 1-3: embed_ln, up-gemm, conv — slot 4 = qkv_gates (ncu probe target)
    embed_ln_kernel<<<BS, 128>>>(x, emb, m_ln_w, h_, xn_);
    gemm_tf32_kernel<0><<<dim3(4, BS / 128), 256>>>(xn_, nullptr, nullptr, nullptr,
                                                    m_up_w, big_, 512, 128, 0);
    conv_silu_kernel<512, 256><<<BS * DIM / 256, 256>>>(big_, m_conv_w, m_conv_b, xca_);
    qkv_gates_kernel<<<BS, 256>>>(xca_, big_, m_q_w, m_k_w, m_v_w,
                                  m_ig_w, m_ig_b, m_fg_w, m_fg_b,
                                  q_, k_, v_, ip_, fp_);
    mlstm_prefix_kernel<<<64, 256>>>(ip_, fp_, slf_, ek_, pmx_);
    mlstm_attn_kernel<<<BB * NHH, 512, ATTN_SMEM>>>(q_, k_, v_, slf_, ek_, pmx_, ht_);
    groupln_kernel<256, 64><<<BS * NHH * 32 / 256, 256>>>(ht_, m_on_w, nullptr, ht_);
    gemm_tf32_kernel<2><<<dim3(1, BS / 128), 256>>>(ht_, xca_, big_, m_skip,
                                                    m_down_w, h_, 128, 256, 1);

    // transposes moved here (only needed by slstm_bd below)
    transpose_w_kernel<<<64, 256>>>(s_ig_w, s_fg_w, s_zg_w, s_og_w, wT_, 0);
    transpose_w_kernel<<<64, 256>>>(s_ig_w, s_fg_w, s_zg_w, s_og_w, wT_, 16384);

    for (int i = 0; i < 2; i++) {
        ln128_kernel<<<BS, 128>>>(h_, s_ln1_w + i * DD, xn_);
        conv_silu_kernel<128, 128><<<BS * DD / 256, 256>>>(xn_, s_conv_w + i * DD * 4,
                                                           s_conv_b + i * DD, xca_);
        slstm_bd_kernel<<<BS * DD / 256, 256>>>(xca_, xn_, wT_ + i * 16384,
                                                gi_, gf_, gz_, go_);
        slstm_scan_kernel<<<BB, 512, SCAN_SMEM>>>(gi_, gf_, gz_, go_,
            s_rec_w + i * 16384, s_bias + i * 512, y_);
        groupln_kernel<128, 32><<<BS * NHH * 32 / 256, 256>>>(y_, s_gn_w + i * DD, h_, h_);
        ln128_kernel<<<BS, 128>>>(h_, s_ln2_w + i * DD, xn_);
        gemm_tf32_kernel<0><<<dim3(4, BS / 128), 256>>>(xn_, nullptr, nullptr, nullptr,
                                                        s_ff_up_w + i * 512 * 128, big_, 512, 128, 0);
        gemm_tf32_kernel<1><<<dim3(1, BS / 128), 256>>>(big_, nullptr, nullptr, nullptr,
                                                        s_ff_down_w + i * 128 * 256, h_, 128, 256, 1);
    }

    ln128_kernel<<<BS, 128>>>(h_, post_norm_w, out);
}

// round 11
// speedup vs baseline: 1.1186x; 1.1186x over previous
#include <cuda_runtime.h>
#include <cuda_bf16.h>
#include <math.h>
#include <stdint.h>

#define BB   128
#define SS   256
#define DD   128
#define DIM  256
#define NHH  4
#define BS   (BB*SS)

__device__ float g_h  [BS*DD];
__device__ float g_xn [BS*DD];
__device__ float g_big[BS*512];
__device__ float g_xca[BS*DIM];
__device__ float g_q  [BS*DIM];
__device__ float g_k  [BS*DIM];
__device__ float g_v  [BS*DIM];
__device__ float g_ht [BS*DIM];
__device__ float g_gi [BS*DD];
__device__ float g_gf [BS*DD];
__device__ float g_gz [BS*DD];
__device__ float g_go [BS*DD];
__device__ float g_y  [BS*DD];
__device__ float g_ip [BB*NHH*SS];
__device__ float g_fp [BB*NHH*SS];
__device__ float g_slf[BB*NHH*SS];
__device__ float g_ek [BB*NHH*SS];
__device__ float g_pmx[BB*NHH*SS];
__device__ float g_wT [2*4*4096];

// ---------------- tf32 helpers ----------------
__device__ __forceinline__ uint32_t f2tf32(float f) {
    uint32_t r;
    asm("cvt.rna.tf32.f32 %0, %1;" : "=r"(r) : "f"(f));
    return r;
}
__device__ __forceinline__ void mma_tf32(float* d, const uint32_t* a, const uint32_t* b) {
    asm volatile(
        "mma.sync.aligned.m16n8k8.row.col.f32.tf32.tf32.f32 "
        "{%0,%1,%2,%3}, {%4,%5,%6,%7}, {%8,%9}, {%0,%1,%2,%3};"
        : "+f"(d[0]), "+f"(d[1]), "+f"(d[2]), "+f"(d[3])
        : "r"(a[0]), "r"(a[1]), "r"(a[2]), "r"(a[3]), "r"(b[0]), "r"(b[1]));
}

// ---------------- fused embedding + LayerNorm ----------------
__global__ void embed_ln_kernel(const int* __restrict__ x, const float* __restrict__ emb,
                                const float* __restrict__ w,
                                float* __restrict__ h, float* __restrict__ xn) {
    int row = blockIdx.x;
    int tid = threadIdx.x;  // 128
    __shared__ float r1[4], r2[4];
    float v = emb[x[row] * DD + tid];
    h[(size_t)row * DD + tid] = v;
    float s = v;
    #pragma unroll
    for (int o = 16; o; o >>= 1) s += __shfl_xor_sync(0xffffffffu, s, o);
    if ((tid & 31) == 0) r1[tid >> 5] = s;
    __syncthreads();
    float mu = (r1[0] + r1[1] + r1[2] + r1[3]) * (1.0f / DD);
    float d = v - mu;
    float sq = d * d;
    #pragma unroll
    for (int o = 16; o; o >>= 1) sq += __shfl_xor_sync(0xffffffffu, sq, o);
    if ((tid & 31) == 0) r2[tid >> 5] = sq;
    __syncthreads();
    float var = (r2[0] + r2[1] + r2[2] + r2[3]) * (1.0f / DD);
    xn[(size_t)row * DD + tid] = d * rsqrtf(var + 1e-5f) * w[tid];
}

__global__ void ln128_kernel(const float* __restrict__ x, const float* __restrict__ w,
                             float* __restrict__ out) {
    int row = blockIdx.x;
    int tid = threadIdx.x;  // 128
    __shared__ float r1[4], r2[4];
    float v = x[(size_t)row * DD + tid];
    float s = v;
    #pragma unroll
    for (int o = 16; o; o >>= 1) s += __shfl_xor_sync(0xffffffffu, s, o);
    if ((tid & 31) == 0) r1[tid >> 5] = s;
    __syncthreads();
    float mu = (r1[0] + r1[1] + r1[2] + r1[3]) * (1.0f / DD);
    float d = v - mu;
    float sq = d * d;
    #pragma unroll
    for (int o = 16; o; o >>= 1) sq += __shfl_xor_sync(0xffffffffu, sq, o);
    if ((tid & 31) == 0) r2[tid >> 5] = sq;
    __syncthreads();
    float var = (r2[0] + r2[1] + r2[2] + r2[3]) * (1.0f / DD);
    out[(size_t)row * DD + tid] = d * rsqrtf(var + 1e-5f) * w[tid];
}

// one warp per group; optional residual add. Compile-time dims.
template<int Drow, int GS>
__global__ void groupln_kernel(const float* __restrict__ x, const float* __restrict__ w,
                               const float* __restrict__ addTo, float* __restrict__ out) {
    int gw = (blockIdx.x * blockDim.x + threadIdx.x) >> 5;
    int lane = threadIdx.x & 31;
    constexpr int GPR = Drow / GS;
    int row = gw / GPR, g = gw % GPR;
    size_t base = (size_t)row * Drow + g * GS;
    if (GS == 64) {
        float v0 = x[base + lane], v1 = x[base + 32 + lane];
        float s = v0 + v1;
        #pragma unroll
        for (int o = 16; o; o >>= 1) s += __shfl_xor_sync(0xffffffffu, s, o);
        float mu = s * (1.0f / 64.0f);
        float e0 = v0 - mu, e1 = v1 - mu;
        float sq = e0 * e0 + e1 * e1;
        #pragma unroll
        for (int o = 16; o; o >>= 1) sq += __shfl_xor_sync(0xffffffffu, sq, o);
        float r = rsqrtf(sq * (1.0f / 64.0f) + 1e-5f);
        float o0 = e0 * r * w[g * GS + lane];
        float o1 = e1 * r * w[g * GS + 32 + lane];
        if (addTo) { o0 += addTo[base + lane]; o1 += addTo[base + 32 + lane]; }
        out[base + lane] = o0;
        out[base + 32 + lane] = o1;
    } else {
        float v0 = x[base + lane];
        float s = v0;
        #pragma unroll
        for (int o = 16; o; o >>= 1) s += __shfl_xor_sync(0xffffffffu, s, o);
        float mu = s * (1.0f / 32.0f);
        float e0 = v0 - mu;
        float sq = e0 * e0;
        #pragma unroll
        for (int o = 16; o; o >>= 1) sq += __shfl_xor_sync(0xffffffffu, sq, o);
        float r = rsqrtf(sq * (1.0f / 32.0f) + 1e-5f);
        float o0 = e0 * r * w[g * GS + lane];
        if (addTo) o0 += addTo[base + lane];
        out[base + lane] = o0;
    }
}

template<int LDX, int C>
__global__ void conv_silu_kernel(const float* __restrict__ x,
                                 const float* __restrict__ w, const float* __restrict__ bias,
                                 float* __restrict__ out) {
    int idx = blockIdx.x * blockDim.x + threadIdx.x;
    int c = idx & (C - 1);
    int s = (idx / C) & (SS - 1);
    int b = idx / (C * SS);
    const float* xp = x + ((size_t)b * SS) * LDX + c;
    float acc = bias[c];
    #pragma unroll
    for (int j = 0; j < 4; j++) {
        int sj = s + j - 3;
        if (sj >= 0) acc += xp[(size_t)sj * LDX] * w[c * 4 + j];
    }
    out[idx] = acc / (1.0f + __expf(-acc));
}

__global__ void transpose_w_kernel(const float* __restrict__ ig, const float* __restrict__ fg,
                                   const float* __restrict__ zg, const float* __restrict__ og,
                                   float* __restrict__ wT, int off) {
    int idx = off + blockIdx.x * blockDim.x + threadIdx.x;
    int layer = idx >> 14;
    int arr = (idx >> 12) & 3;
    int r = idx & 4095;
    int h = r >> 10, e = (r >> 5) & 31, d = r & 31;
    const float* src = (arr == 0) ? ig : (arr == 1) ? fg : (arr == 2) ? zg : og;
    wT[layer * 16384 + arr * 4096 + h * 1024 + d * 32 + e] =
        src[layer * 4096 + h * 1024 + e * 32 + d];
}

// ---------------- mLSTM block-diagonal qkv (pure elementwise, float4) ----------------
__global__ void __launch_bounds__(256)
mlstm_qkv_kernel(const float* __restrict__ xca, const float* __restrict__ big,
                 const float* __restrict__ qw, const float* __restrict__ kw,
                 const float* __restrict__ vw,
                 float* __restrict__ q, float* __restrict__ k, float* __restrict__ v) {
    int idx = blockIdx.x * blockDim.x + threadIdx.x;   // BS*DIM
    int c = idx & (DIM - 1);
    size_t bs = (size_t)(idx >> 8);
    int blk = c >> 3, e = c & 7;
    const float* xc = xca + bs * DIM + blk * 8;
    const float* xi = big + bs * 512 + blk * 8;
    const float* qp = qw + blk * 64 + e * 8;
    const float* kp = kw + blk * 64 + e * 8;
    const float* vp = vw + blk * 64 + e * 8;
    float4 x0 = *(const float4*)xc,       x1 = *(const float4*)(xc + 4);
    float4 i0 = *(const float4*)xi,       i1 = *(const float4*)(xi + 4);
    float4 q0 = *(const float4*)qp,       q1 = *(const float4*)(qp + 4);
    float4 k0 = *(const float4*)kp,       k1 = *(const float4*)(kp + 4);
    float4 v0 = *(const float4*)vp,       v1 = *(const float4*)(vp + 4);
    float aq = x0.x*q0.x + x0.y*q0.y + x0.z*q0.z + x0.w*q0.w
             + x1.x*q1.x + x1.y*q1.y + x1.z*q1.z + x1.w*q1.w;
    float ak = x0.x*k0.x + x0.y*k0.y + x0.z*k0.z + x0.w*k0.w
             + x1.x*k1.x + x1.y*k1.y + x1.z*k1.z + x1.w*k1.w;
    float av = i0.x*v0.x + i0.y*v0.y + i0.z*v0.z + i0.w*v0.w
             + i1.x*v1.x + i1.y*v1.y + i1.z*v1.z + i1.w*v1.w;
    q[idx] = aq; k[idx] = ak; v[idx] = av;
}

// ---------------- mLSTM gates via tf32 mma: C(BS x 8) = [q|k|v] x W^T ----------------
// one warp = 16 rows; weights staged tf32 in smem (24 KB); 96 mmas/warp.
__global__ void __launch_bounds__(256)
mlstm_gates_mma(const float* __restrict__ q, const float* __restrict__ k,
                const float* __restrict__ v,
                const float* __restrict__ igw, const float* __restrict__ igb,
                const float* __restrict__ fgw, const float* __restrict__ fgb,
                float* __restrict__ ip, float* __restrict__ fp) {
    __shared__ uint32_t sW[8][768];
    int tid = threadIdx.x;
    for (int i = tid; i < 8 * 768; i += 256) {
        int n = i / 768, kk = i - n * 768;
        float wv = (n < 4) ? igw[n * 768 + kk] : fgw[(n - 4) * 768 + kk];
        sW[n][kk] = f2tf32(wv);
    }
    __syncthreads();
    int w = tid >> 5, lane = tid & 31;
    int g = lane >> 2, t = lane & 3;
    int base = blockIdx.x * 128 + w * 16;
    float acc[4] = {0.f, 0.f, 0.f, 0.f};
    const float* arrs[3] = {q, k, v};
    #pragma unroll
    for (int seg = 0; seg < 3; seg++) {
        const float* r0 = arrs[seg] + (size_t)(base + g) * 256;
        const float* r1 = arrs[seg] + (size_t)(base + g + 8) * 256;
        const uint32_t* wrow = &sW[g][seg * 256];
        for (int ks = 0; ks < 32; ks++) {
            int k0 = ks * 8;
            uint32_t a[4], b[2];
            a[0] = f2tf32(r0[k0 + t]);
            a[1] = f2tf32(r1[k0 + t]);
            a[2] = f2tf32(r0[k0 + t + 4]);
            a[3] = f2tf32(r1[k0 + t + 4]);
            b[0] = wrow[k0 + t];
            b[1] = wrow[k0 + t + 4];
            mma_tf32(acc, a, b);
        }
    }
    // c0->(row g, n=2t), c1->(g, 2t+1), c2->(g+8, 2t), c3->(g+8, 2t+1)
    int rows[2] = {base + g, base + g + 8};
    int ns[2] = {2 * t, 2 * t + 1};
    #pragma unroll
    for (int ri = 0; ri < 2; ri++) {
        #pragma unroll
        for (int ci = 0; ci < 2; ci++) {
            float val = acc[ri * 2 + ci];
            int row = rows[ri], n = ns[ci];
            int b_ = row >> 8, s = row & 255;
            if (n < 4) ip[(b_ * NHH + n) * SS + s] = val + igb[n];
            else       fp[(b_ * NHH + (n - 4)) * SS + s] = val + fgb[n - 4];
        }
    }
}

// ---------------- parallel gate prefix: one warp per (b,h) ----------------
__global__ void mlstm_prefix_kernel(const float* __restrict__ ip, const float* __restrict__ fp,
                                    float* __restrict__ slf, float* __restrict__ ek,
                                    float* __restrict__ pmx) {
    int warp = (blockIdx.x * blockDim.x + threadIdx.x) >> 5;
    int lane = threadIdx.x & 31;
    size_t base = (size_t)warp * SS + lane * 8;
    float fv[8], iv[8];
    {
        float4 a = *(const float4*)(fp + base);
        float4 b = *(const float4*)(fp + base + 4);
        fv[0]=a.x; fv[1]=a.y; fv[2]=a.z; fv[3]=a.w; fv[4]=b.x; fv[5]=b.y; fv[6]=b.z; fv[7]=b.w;
        float4 c = *(const float4*)(ip + base);
        float4 d = *(const float4*)(ip + base + 4);
        iv[0]=c.x; iv[1]=c.y; iv[2]=c.z; iv[3]=c.w; iv[4]=d.x; iv[5]=d.y; iv[6]=d.z; iv[7]=d.w;
    }
    float ls[8], lsum = 0.f;
    #pragma unroll
    for (int t = 0; t < 8; t++) {
        float f = fv[t];
        ls[t] = fminf(f, 0.f) - log1pf(expf(-fabsf(f)));
        lsum += ls[t];
    }
    float run = lsum;
    #pragma unroll
    for (int o = 1; o < 32; o <<= 1) {
        float vv = __shfl_up_sync(0xffffffffu, run, o);
        if (lane >= o) run += vv;
    }
    float c = run - lsum;
    float sl[8], ev[8], lmax = -1e30f;
    #pragma unroll
    for (int t = 0; t < 8; t++) {
        c += ls[t];
        sl[t] = c;
        ev[t] = iv[t] - c;
        lmax = fmaxf(lmax, ev[t]);
    }
    float rmax = lmax;
    #pragma unroll
    for (int o = 1; o < 32; o <<= 1) {
        float vv = __shfl_up_sync(0xffffffffu, rmax, o);
        if (lane >= o) rmax = fmaxf(rmax, vv);
    }
    float exclmax = __shfl_up_sync(0xffffffffu, rmax, 1);
    if (lane == 0) exclmax = -1e30f;
    float pm[8];
    float cm = exclmax;
    #pragma unroll
    for (int t = 0; t < 8; t++) {
        cm = fmaxf(cm, ev[t]);
        pm[t] = cm;
    }
    *(float4*)(slf + base)     = make_float4(sl[0], sl[1], sl[2], sl[3]);
    *(float4*)(slf + base + 4) = make_float4(sl[4], sl[5], sl[6], sl[7]);
    *(float4*)(ek + base)      = make_float4(ev[0], ev[1], ev[2], ev[3]);
    *(float4*)(ek + base + 4)  = make_float4(ev[4], ev[5], ev[6], ev[7]);
    *(float4*)(pmx + base)     = make_float4(pm[0], pm[1], pm[2], pm[3]);
    *(float4*)(pmx + base + 4) = make_float4(pm[4], pm[5], pm[6], pm[7]);
}

// ---------------- attention: proven 256-thread version (R7) ----------------
#define ATTN_SMEM (2 * SS * 64 * sizeof(float))
__global__ void __launch_bounds__(256, 1)
mlstm_attn_kernel(const float* __restrict__ q, const float* __restrict__ k,
                  const float* __restrict__ v,
                  const float* __restrict__ slf, const float* __restrict__ ek,
                  const float* __restrict__ pmx, float* __restrict__ out) {
    int bh = blockIdx.x;
    int b = bh >> 2, h = bh & 3;
    extern __shared__ float sm[];
    float* sk = sm;
    float* sv = sm + SS * 64;
    __shared__ float s_e[SS], s_px[SS], s_lf[SS];
    int tid = threadIdx.x;
    const float* kb = k + (size_t)b * SS * DIM + h * 64;
    const float* vb = v + (size_t)b * SS * DIM + h * 64;
    for (int i = tid; i < SS * 64; i += 256) {
        int s = i >> 6, d = i & 63;
        sk[i] = kb[(size_t)s * DIM + d];
        sv[i] = vb[(size_t)s * DIM + d];
    }
    for (int i = tid; i < SS; i += 256) {
        s_e[i]  = ek [(size_t)bh * SS + i];
        s_px[i] = pmx[(size_t)bh * SS + i];
        s_lf[i] = slf[(size_t)bh * SS + i];
    }
    __syncthreads();

    int w = tid >> 5, lane = tid & 31;
    int range = (w < 4) ? w : (11 - w);
    int qrow = range * 32 + lane;
    const float* qb = q + ((size_t)b * SS + qrow) * DIM + h * 64;
    float qreg[64], acc[64];
    #pragma unroll
    for (int d = 0; d < 64; d += 4) {
        float4 t = *(const float4*)(qb + d);
        qreg[d] = t.x; qreg[d+1] = t.y; qreg[d+2] = t.z; qreg[d+3] = t.w;
        acc[d] = 0.f; acc[d+1] = 0.f; acc[d+2] = 0.f; acc[d+3] = 0.f;
    }
    float sc = 0.f;
    float mpx = s_px[qrow];
    int kmax = range * 32 + 31;
    for (int kk = 0; kk <= kmax; kk++) {
        const float* kr = sk + kk * 64;
        float d0 = 0, d1 = 0, d2 = 0, d3 = 0;
        #pragma unroll
        for (int d = 0; d < 64; d += 4) {
            float4 kv = *(const float4*)(kr + d);
            d0 += qreg[d] * kv.x;   d1 += qreg[d+1] * kv.y;
            d2 += qreg[d+2] * kv.z; d3 += qreg[d+3] * kv.w;
        }
        float dot = (d0 + d1) + (d2 + d3);
        float coeff = dot * 0.125f * __expf(s_e[kk] - mpx);
        if (kk > qrow) coeff = 0.f;
        sc += coeff;
        const float* vr = sv + kk * 64;
        #pragma unroll
        for (int d = 0; d < 64; d += 4) {
            float4 vv = *(const float4*)(vr + d);
            acc[d]   += coeff * vv.x; acc[d+1] += coeff * vv.y;
            acc[d+2] += coeff * vv.z; acc[d+3] += coeff * vv.w;
        }
    }
    float maxd = s_lf[qrow] + mpx;
    float inv = 1.0f / (fmaxf(fabsf(sc), __expf(-maxd)) + 1e-6f);
    float* ob = out + ((size_t)b * SS + qrow) * DIM + h * 64;
    #pragma unroll
    for (int d = 0; d < 64; d += 4) {
        float4 ov;
        ov.x = acc[d] * inv;   ov.y = acc[d+1] * inv;
        ov.z = acc[d+2] * inv; ov.w = acc[d+3] * inv;
        *(float4*)(ob + d) = ov;
    }
}

// sLSTM block-diagonal gates — transposed (lane-contiguous) weights
__global__ void slstm_bd_kernel(const float* __restrict__ xc, const float* __restrict__ xn,
                                const float* __restrict__ wT,
                                float* __restrict__ gi, float* __restrict__ gf,
                                float* __restrict__ gz, float* __restrict__ go) {
    int idx = blockIdx.x * blockDim.x + threadIdx.x;
    int c = idx & 127;
    size_t bs = (size_t)(idx >> 7);
    int h = c >> 5, e = c & 31;
    const float* base = wT + h * 1024 + e;
    const float* xcb = xc + bs * DD + h * 32;
    const float* xnb = xn + bs * DD + h * 32;
    float a1 = 0, a2 = 0, a3 = 0, a4 = 0;
    #pragma unroll
    for (int d = 0; d < 32; d++) {
        float xv = xcb[d], nv = xnb[d];
        int o = d * 32;
        a1 += xv * base[o];
        a2 += xv * base[4096 + o];
        a3 += nv * base[8192 + o];
        a4 += nv * base[12288 + o];
    }
    gi[idx] = a1; gf[idx] = a2; gz[idx] = a3; go[idx] = a4;
}

#define SCAN_SMEM (4 * 32 * 128 * sizeof(float))
__global__ void __launch_bounds__(512, 1)
slstm_scan_kernel(const float* __restrict__ gi, const float* __restrict__ gf,
                  const float* __restrict__ gz, const float* __restrict__ go,
                  const float* __restrict__ rw, const float* __restrict__ bias,
                  float* __restrict__ y) {
    int b = blockIdx.x;
    int tid = threadIdx.x;
    extern __shared__ float srw[];
    __shared__ float hs[128], cs[128], ns[128], ms[128];
    __shared__ float sb[512], srec[512];
    for (int i = tid; i < 16384; i += 512) srw[i] = rw[i];
    sb[tid] = bias[tid];
    if (tid < 128) { hs[tid] = 0.f; cs[tid] = 0.f; ns[tid] = 0.f; ms[tid] = 0.f; }
    __syncthreads();
    int h = tid >> 7, j = tid & 127;
    const float* wp = srw + h * 4096 + j;
    const float* hb = hs + h * 32;
    for (int t = 0; t < SS; t++) {
        float r0 = 0, r1 = 0;
        #pragma unroll
        for (int d = 0; d < 32; d += 2) {
            r0 += hb[d]     * wp[d * 128];
            r1 += hb[d + 1] * wp[(d + 1) * 128];
        }
        srec[tid] = r0 + r1;
        __syncthreads();
        if (tid < 128) {
            size_t gidx = ((size_t)b * SS + t) * DD + tid;
            int hh = tid >> 5, d = tid & 31;
            int rb = hh * 128;
            float ix = gi[gidx] + srec[rb + d]      + sb[rb + d];
            float fx = gf[gidx] + srec[rb + 32 + d] + sb[rb + 32 + d];
            float zx = gz[gidx] + srec[rb + 64 + d] + sb[rb + 64 + d];
            float ox = go[gidx] + srec[rb + 96 + d] + sb[rb + 96 + d];
            float ls  = fminf(fx, 0.f) - log1pf(__expf(-fabsf(fx)));
            float lpm = ms[tid] + ls;
            float mn  = fmaxf(ix, lpm);
            float ig  = __expf(ix - mn);
            float fg  = __expf(lpm - mn);
            float cn  = fg * cs[tid] + ig * tanhf(zx);
            float nn  = fg * ns[tid] + ig;
            float hn  = cn / (nn * (1.0f + __expf(-ox)));
            cs[tid] = cn; ns[tid] = nn; ms[tid] = mn; hs[tid] = hn;
            y[gidx] = hn;
        }
        __syncthreads();
    }
}

// ---------------- tf32 tensor-core GEMM: 128x128 tile, 8 warps x (64x32) ----------------
template<int AOP>
__global__ void __launch_bounds__(256)
gemm_tf32_kernel(const float* __restrict__ A, const float* __restrict__ A2,
                 const float* __restrict__ A3, const float* __restrict__ Askip,
                 const float* __restrict__ W, float* __restrict__ C,
                 int N, int Kd, int accum) {
    __shared__ __align__(16) uint32_t sA[2][128][20];
    __shared__ __align__(16) uint32_t sB[2][128][20];
    const int bm = blockIdx.y * 128, bn = blockIdx.x * 128;
    const int tid = threadIdx.x;
    const int wid = tid >> 5, lane = tid & 31;
    const int wm = wid & 1, wn = wid >> 1;
    const int g = lane >> 2, t = lane & 3;
    const int arow = tid >> 1;
    const int acg = (tid & 1) << 3;
    float acc[4][4][4] = {};

    auto loadA4 = [&](int gr, int gk) -> float4 {
        float4 r;
        if (AOP == 0) {
            r = *(const float4*)(A + (size_t)gr * Kd + gk);
        } else if (AOP == 1) {
            float4 gg = *(const float4*)(A + (size_t)gr * 512 + gk);
            float4 u  = *(const float4*)(A + (size_t)gr * 512 + 256 + gk);
            r.x = 0.5f * gg.x * (1.0f + erff(gg.x * 0.70710678f)) * u.x;
            r.y = 0.5f * gg.y * (1.0f + erff(gg.y * 0.70710678f)) * u.y;
            r.z = 0.5f * gg.z * (1.0f + erff(gg.z * 0.70710678f)) * u.z;
            r.w = 0.5f * gg.w * (1.0f + erff(gg.w * 0.70710678f)) * u.w;
        } else {
            float4 hv = *(const float4*)(A  + (size_t)gr * 256 + gk);
            float4 xv = *(const float4*)(A2 + (size_t)gr * 256 + gk);
            float4 sk = *(const float4*)(Askip + gk);
            float4 zv = *(const float4*)(A3 + (size_t)gr * 512 + 256 + gk);
            r.x = (hv.x + sk.x * xv.x) * (zv.x / (1.0f + __expf(-zv.x)));
            r.y = (hv.y + sk.y * xv.y) * (zv.y / (1.0f + __expf(-zv.y)));
            r.z = (hv.z + sk.z * xv.z) * (zv.z / (1.0f + __expf(-zv.z)));
            r.w = (hv.w + sk.w * xv.w) * (zv.w / (1.0f + __expf(-zv.w)));
        }
        return r;
    };
    auto cvt4 = [&](float4 f) -> uint4 {
        return make_uint4(f2tf32(f.x), f2tf32(f.y), f2tf32(f.z), f2tf32(f.w));
    };
    auto compute = [&](int bf) {
        #pragma unroll
        for (int ks = 0; ks < 2; ks++) {
            int kb = ks * 8;
            uint32_t af[4][4], bfr[4][2];
            #pragma unroll
            for (int mi = 0; mi < 4; mi++) {
                int r0 = wm * 64 + mi * 16 + g;
                af[mi][0] = sA[bf][r0][kb + t];
                af[mi][1] = sA[bf][r0 + 8][kb + t];
                af[mi][2] = sA[bf][r0][kb + t + 4];
                af[mi][3] = sA[bf][r0 + 8][kb + t + 4];
            }
            #pragma unroll
            for (int ni = 0; ni < 4; ni++) {
                int c0 = wn * 32 + ni * 8 + g;
                bfr[ni][0] = sB[bf][c0][kb + t];
                bfr[ni][1] = sB[bf][c0][kb + t + 4];
            }
            #pragma unroll
            for (int mi = 0; mi < 4; mi++)
                #pragma unroll
                for (int ni = 0; ni < 4; ni++)
                    mma_tf32(acc[mi][ni], af[mi], bfr[ni]);
        }
    };

    {
        float4 alo = loadA4(bm + arow, acg);
        float4 ahi = loadA4(bm + arow, acg + 4);
        float4 wlo = *(const float4*)(W + (size_t)(bn + arow) * Kd + acg);
        float4 whi = *(const float4*)(W + (size_t)(bn + arow) * Kd + acg + 4);
        *(uint4*)&sA[0][arow][acg]     = cvt4(alo);
        *(uint4*)&sA[0][arow][acg + 4] = cvt4(ahi);
        *(uint4*)&sB[0][arow][acg]     = cvt4(wlo);
        *(uint4*)&sB[0][arow][acg + 4] = cvt4(whi);
    }
    __syncthreads();

    int buf = 0;
    for (int k0 = 16; k0 < Kd; k0 += 16) {
        float4 alo = loadA4(bm + arow, k0 + acg);
        float4 ahi = loadA4(bm + arow, k0 + acg + 4);
        float4 wlo = *(const float4*)(W + (size_t)(bn + arow) * Kd + k0 + acg);
        float4 whi = *(const float4*)(W + (size_t)(bn + arow) * Kd + k0 + acg + 4);
        compute(buf);
        int nb = buf ^ 1;
        *(uint4*)&sA[nb][arow][acg]     = cvt4(alo);
        *(uint4*)&sA[nb][arow][acg + 4] = cvt4(ahi);
        *(uint4*)&sB[nb][arow][acg]     = cvt4(wlo);
        *(uint4*)&sB[nb][arow][acg + 4] = cvt4(whi);
        __syncthreads();
        buf = nb;
    }
    compute(buf);

    #pragma unroll
    for (int mi = 0; mi < 4; mi++) {
        #pragma unroll
        for (int ni = 0; ni < 4; ni++) {
            int grow = bm + wm * 64 + mi * 16 + g;
            int gcol = bn + wn * 32 + ni * 8 + t * 2;
            float* p0 = C + (size_t)grow * N + gcol;
            float* p1 = C + (size_t)(grow + 8) * N + gcol;
            if (accum) {
                float2 x0 = *(float2*)p0, x1 = *(float2*)p1;
                x0.x += acc[mi][ni][0]; x0.y += acc[mi][ni][1];
                x1.x += acc[mi][ni][2]; x1.y += acc[mi][ni][3];
                *(float2*)p0 = x0; *(float2*)p1 = x1;
            } else {
                *(float2*)p0 = make_float2(acc[mi][ni][0], acc[mi][ni][1]);
                *(float2*)p1 = make_float2(acc[mi][ni][2], acc[mi][ni][3]);
            }
        }
    }
}

extern "C" void kernel_launch(void* const* d_in, const int* in_sizes, int n_in,
                              void* d_out, int out_size) {
    const int*   x          = (const int*)  d_in[0];
    const float* emb        = (const float*)d_in[1];
    const float* m_ln_w     = (const float*)d_in[2];
    const float* m_up_w     = (const float*)d_in[3];
    const float* m_conv_w   = (const float*)d_in[4];
    const float* m_conv_b   = (const float*)d_in[5];
    const float* m_q_w      = (const float*)d_in[6];
    const float* m_k_w      = (const float*)d_in[7];
    const float* m_v_w      = (const float*)d_in[8];
    const float* m_ig_w     = (const float*)d_in[9];
    const float* m_ig_b     = (const float*)d_in[10];
    const float* m_fg_w     = (const float*)d_in[11];
    const float* m_fg_b     = (const float*)d_in[12];
    const float* m_on_w     = (const float*)d_in[13];
    const float* m_skip     = (const float*)d_in[14];
    const float* m_down_w   = (const float*)d_in[15];
    const float* s_ln1_w    = (const float*)d_in[16];
    const float* s_conv_w   = (const float*)d_in[17];
    const float* s_conv_b   = (const float*)d_in[18];
    const float* s_ig_w     = (const float*)d_in[19];
    const float* s_fg_w     = (const float*)d_in[20];
    const float* s_zg_w     = (const float*)d_in[21];
    const float* s_og_w     = (const float*)d_in[22];
    const float* s_rec_w    = (const float*)d_in[23];
    const float* s_bias     = (const float*)d_in[24];
    const float* s_gn_w     = (const float*)d_in[25];
    const float* s_ln2_w    = (const float*)d_in[26];
    const float* s_ff_up_w  = (const float*)d_in[27];
    const float* s_ff_down_w= (const float*)d_in[28];
    const float* post_norm_w= (const float*)d_in[29];
    float* out = (float*)d_out;

    float *h_, *xn_, *big_, *xca_, *q_, *k_, *v_, *ht_;
    float *gi_, *gf_, *gz_, *go_, *y_, *ip_, *fp_, *slf_, *ek_, *pmx_, *wT_;
    cudaGetSymbolAddress((void**)&h_,   g_h);
    cudaGetSymbolAddress((void**)&xn_,  g_xn);
    cudaGetSymbolAddress((void**)&big_, g_big);
    cudaGetSymbolAddress((void**)&xca_, g_xca);
    cudaGetSymbolAddress((void**)&q_,   g_q);
    cudaGetSymbolAddress((void**)&k_,   g_k);
    cudaGetSymbolAddress((void**)&v_,   g_v);
    cudaGetSymbolAddress((void**)&ht_,  g_ht);
    cudaGetSymbolAddress((void**)&gi_,  g_gi);
    cudaGetSymbolAddress((void**)&gf_,  g_gf);
    cudaGetSymbolAddress((void**)&gz_,  g_gz);
    cudaGetSymbolAddress((void**)&go_,  g_go);
    cudaGetSymbolAddress((void**)&y_,   g_y);
    cudaGetSymbolAddress((void**)&ip_,  g_ip);
    cudaGetSymbolAddress((void**)&fp_,  g_fp);
    cudaGetSymbolAddress((void**)&slf_, g_slf);
    cudaGetSymbolAddress((void**)&ek_,  g_ek);
    cudaGetSymbolAddress((void**)&pmx_, g_pmx);
    cudaGetSymbolAddress((void**)&wT_,  g_wT);

    cudaFuncSetAttribute(mlstm_attn_kernel, cudaFuncAttributeMaxDynamicSharedMemorySize, (int)ATTN_SMEM);
    cudaFuncSetAttribute(slstm_scan_kernel, cudaFuncAttributeMaxDynamicSharedMemorySize, (int)SCAN_SMEM);

    // slots 1-3: embed_ln, up-gemm, conv — slot 4 = mlstm_qkv (ncu probe target)
    embed_ln_kernel<<<BS, 128>>>(x, emb, m_ln_w, h_, xn_);
    gemm_tf32_kernel<0><<<dim3(4, BS / 128), 256>>>(xn_, nullptr, nullptr, nullptr,
                                                    m_up_w, big_, 512, 128, 0);
    conv_silu_kernel<512, 256><<<BS * DIM / 256, 256>>>(big_, m_conv_w, m_conv_b, xca_);
    mlstm_qkv_kernel<<<BS * DIM / 256, 256>>>(xca_, big_, m_q_w, m_k_w, m_v_w, q_, k_, v_);
    mlstm_gates_mma<<<BS / 128, 256>>>(q_, k_, v_, m_ig_w, m_ig_b, m_fg_w, m_fg_b, ip_, fp_);
    mlstm_prefix_kernel<<<64, 256>>>(ip_, fp_, slf_, ek_, pmx_);
    mlstm_attn_kernel<<<BB * NHH, 256, ATTN_SMEM>>>(q_, k_, v_, slf_, ek_, pmx_, ht_);
    groupln_kernel<256, 64><<<BS * NHH * 32 / 256, 256>>>(ht_, m_on_w, nullptr, ht_);
    gemm_tf32_kernel<2><<<dim3(1, BS / 128), 256>>>(ht_, xca_, big_, m_skip,
                                                    m_down_w, h_, 128, 256, 1);

    transpose_w_kernel<<<64, 256>>>(s_ig_w, s_fg_w, s_zg_w, s_og_w, wT_, 0);
    transpose_w_kernel<<<64, 256>>>(s_ig_w, s_fg_w, s_zg_w, s_og_w, wT_, 16384);

    for (int i = 0; i < 2; i++) {
        ln128_kernel<<<BS, 128>>>(h_, s_ln1_w + i * DD, xn_);
        conv_silu_kernel<128, 128><<<BS * DD / 256, 256>>>(xn_, s_conv_w + i * DD * 4,
                                                           s_conv_b + i * DD, xca_);
        slstm_bd_kernel<<<BS * DD / 256, 256>>>(xca_, xn_, wT_ + i * 16384,
                                                gi_, gf_, gz_, go_);
        slstm_scan_kernel<<<BB, 512, SCAN_SMEM>>>(gi_, gf_, gz_, go_,
            s_rec_w + i * 16384, s_bias + i * 512, y_);
        groupln_kernel<128, 32><<<BS * NHH * 32 / 256, 256>>>(y_, s_gn_w + i * DD, h_, h_);
        ln128_kernel<<<BS, 128>>>(h_, s_ln2_w + i * DD, xn_);
        gemm_tf32_kernel<0><<<dim3(4, BS / 128), 256>>>(xn_, nullptr, nullptr, nullptr,
                                                        s_ff_up_w + i * 512 * 128, big_, 512, 128, 0);
        gemm_tf32_kernel<1><<<dim3(1, BS / 128), 256>>>(big_, nullptr, nullptr, nullptr,
                                                        s_ff_down_w + i * 128 * 256, h_, 128, 256, 1);
    }

    ln128_kernel<<<BS, 128>>>(h_, post_norm_w, out);
}

// round 12
// speedup vs baseline: 1.2365x; 1.1054x over previous
#include <cuda_runtime.h>
#include <cuda_bf16.h>
#include <math.h>
#include <stdint.h>

#define BB   128
#define SS   256
#define DD   128
#define DIM  256
#define NHH  4
#define BS   (BB*SS)

__device__ float g_h  [BS*DD];
__device__ float g_xn [BS*DD];
__device__ float g_big[BS*512];
__device__ float g_xca[BS*DIM];
__device__ float g_q  [BS*DIM];
__device__ float g_k  [BS*DIM];
__device__ float g_v  [BS*DIM];
__device__ float g_ht [BS*DIM];
__device__ float g_gi [BS*DD];
__device__ float g_gf [BS*DD];
__device__ float g_gz [BS*DD];
__device__ float g_go [BS*DD];
__device__ float g_y  [BS*DD];
__device__ float g_ip [BB*NHH*SS];
__device__ float g_fp [BB*NHH*SS];
__device__ float g_slf[BB*NHH*SS];
__device__ float g_ek [BB*NHH*SS];
__device__ float g_pmx[BB*NHH*SS];
__device__ float g_wT [2*4*4096];

// ---------------- tf32 helpers ----------------
__device__ __forceinline__ uint32_t f2tf32(float f) {
    uint32_t r;
    asm("cvt.rna.tf32.f32 %0, %1;" : "=r"(r) : "f"(f));
    return r;
}
__device__ __forceinline__ void mma_tf32(float* d, const uint32_t* a, const uint32_t* b) {
    asm volatile(
        "mma.sync.aligned.m16n8k8.row.col.f32.tf32.tf32.f32 "
        "{%0,%1,%2,%3}, {%4,%5,%6,%7}, {%8,%9}, {%0,%1,%2,%3};"
        : "+f"(d[0]), "+f"(d[1]), "+f"(d[2]), "+f"(d[3])
        : "r"(a[0]), "r"(a[1]), "r"(a[2]), "r"(a[3]), "r"(b[0]), "r"(b[1]));
}

// ---------------- fused embedding + LayerNorm ----------------
__global__ void embed_ln_kernel(const int* __restrict__ x, const float* __restrict__ emb,
                                const float* __restrict__ w,
                                float* __restrict__ h, float* __restrict__ xn) {
    int row = blockIdx.x;
    int tid = threadIdx.x;  // 128
    __shared__ float r1[4], r2[4];
    float v = emb[x[row] * DD + tid];
    h[(size_t)row * DD + tid] = v;
    float s = v;
    #pragma unroll
    for (int o = 16; o; o >>= 1) s += __shfl_xor_sync(0xffffffffu, s, o);
    if ((tid & 31) == 0) r1[tid >> 5] = s;
    __syncthreads();
    float mu = (r1[0] + r1[1] + r1[2] + r1[3]) * (1.0f / DD);
    float d = v - mu;
    float sq = d * d;
    #pragma unroll
    for (int o = 16; o; o >>= 1) sq += __shfl_xor_sync(0xffffffffu, sq, o);
    if ((tid & 31) == 0) r2[tid >> 5] = sq;
    __syncthreads();
    float var = (r2[0] + r2[1] + r2[2] + r2[3]) * (1.0f / DD);
    xn[(size_t)row * DD + tid] = d * rsqrtf(var + 1e-5f) * w[tid];
}

__global__ void ln128_kernel(const float* __restrict__ x, const float* __restrict__ w,
                             float* __restrict__ out) {
    int row = blockIdx.x;
    int tid = threadIdx.x;  // 128
    __shared__ float r1[4], r2[4];
    float v = x[(size_t)row * DD + tid];
    float s = v;
    #pragma unroll
    for (int o = 16; o; o >>= 1) s += __shfl_xor_sync(0xffffffffu, s, o);
    if ((tid & 31) == 0) r1[tid >> 5] = s;
    __syncthreads();
    float mu = (r1[0] + r1[1] + r1[2] + r1[3]) * (1.0f / DD);
    float d = v - mu;
    float sq = d * d;
    #pragma unroll
    for (int o = 16; o; o >>= 1) sq += __shfl_xor_sync(0xffffffffu, sq, o);
    if ((tid & 31) == 0) r2[tid >> 5] = sq;
    __syncthreads();
    float var = (r2[0] + r2[1] + r2[2] + r2[3]) * (1.0f / DD);
    out[(size_t)row * DD + tid] = d * rsqrtf(var + 1e-5f) * w[tid];
}

template<int Drow, int GS>
__global__ void groupln_kernel(const float* __restrict__ x, const float* __restrict__ w,
                               const float* __restrict__ addTo, float* __restrict__ out) {
    int gw = (blockIdx.x * blockDim.x + threadIdx.x) >> 5;
    int lane = threadIdx.x & 31;
    constexpr int GPR = Drow / GS;
    int row = gw / GPR, g = gw % GPR;
    size_t base = (size_t)row * Drow + g * GS;
    if (GS == 64) {
        float v0 = x[base + lane], v1 = x[base + 32 + lane];
        float s = v0 + v1;
        #pragma unroll
        for (int o = 16; o; o >>= 1) s += __shfl_xor_sync(0xffffffffu, s, o);
        float mu = s * (1.0f / 64.0f);
        float e0 = v0 - mu, e1 = v1 - mu;
        float sq = e0 * e0 + e1 * e1;
        #pragma unroll
        for (int o = 16; o; o >>= 1) sq += __shfl_xor_sync(0xffffffffu, sq, o);
        float r = rsqrtf(sq * (1.0f / 64.0f) + 1e-5f);
        float o0 = e0 * r * w[g * GS + lane];
        float o1 = e1 * r * w[g * GS + 32 + lane];
        if (addTo) { o0 += addTo[base + lane]; o1 += addTo[base + 32 + lane]; }
        out[base + lane] = o0;
        out[base + 32 + lane] = o1;
    } else {
        float v0 = x[base + lane];
        float s = v0;
        #pragma unroll
        for (int o = 16; o; o >>= 1) s += __shfl_xor_sync(0xffffffffu, s, o);
        float mu = s * (1.0f / 32.0f);
        float e0 = v0 - mu;
        float sq = e0 * e0;
        #pragma unroll
        for (int o = 16; o; o >>= 1) sq += __shfl_xor_sync(0xffffffffu, sq, o);
        float r = rsqrtf(sq * (1.0f / 32.0f) + 1e-5f);
        float o0 = e0 * r * w[g * GS + lane];
        if (addTo) o0 += addTo[base + lane];
        out[base + lane] = o0;
    }
}

template<int LDX, int C>
__global__ void conv_silu_kernel(const float* __restrict__ x,
                                 const float* __restrict__ w, const float* __restrict__ bias,
                                 float* __restrict__ out) {
    int idx = blockIdx.x * blockDim.x + threadIdx.x;
    int c = idx & (C - 1);
    int s = (idx / C) & (SS - 1);
    int b = idx / (C * SS);
    const float* xp = x + ((size_t)b * SS) * LDX + c;
    float acc = bias[c];
    #pragma unroll
    for (int j = 0; j < 4; j++) {
        int sj = s + j - 3;
        if (sj >= 0) acc += xp[(size_t)sj * LDX] * w[c * 4 + j];
    }
    out[idx] = acc / (1.0f + __expf(-acc));
}

__global__ void transpose_w_kernel(const float* __restrict__ ig, const float* __restrict__ fg,
                                   const float* __restrict__ zg, const float* __restrict__ og,
                                   float* __restrict__ wT, int off) {
    int idx = off + blockIdx.x * blockDim.x + threadIdx.x;
    int layer = idx >> 14;
    int arr = (idx >> 12) & 3;
    int r = idx & 4095;
    int h = r >> 10, e = (r >> 5) & 31, d = r & 31;
    const float* src = (arr == 0) ? ig : (arr == 1) ? fg : (arr == 2) ? zg : og;
    wT[layer * 16384 + arr * 4096 + h * 1024 + d * 32 + e] =
        src[layer * 4096 + h * 1024 + e * 32 + d];
}

// ---------------- mLSTM block-diagonal qkv ----------------
__global__ void __launch_bounds__(256)
mlstm_qkv_kernel(const float* __restrict__ xca, const float* __restrict__ big,
                 const float* __restrict__ qw, const float* __restrict__ kw,
                 const float* __restrict__ vw,
                 float* __restrict__ q, float* __restrict__ k, float* __restrict__ v) {
    int idx = blockIdx.x * blockDim.x + threadIdx.x;
    int c = idx & (DIM - 1);
    size_t bs = (size_t)(idx >> 8);
    int blk = c >> 3, e = c & 7;
    const float* xc = xca + bs * DIM + blk * 8;
    const float* xi = big + bs * 512 + blk * 8;
    const float* qp = qw + blk * 64 + e * 8;
    const float* kp = kw + blk * 64 + e * 8;
    const float* vp = vw + blk * 64 + e * 8;
    float4 x0 = *(const float4*)xc,       x1 = *(const float4*)(xc + 4);
    float4 i0 = *(const float4*)xi,       i1 = *(const float4*)(xi + 4);
    float4 q0 = *(const float4*)qp,       q1 = *(const float4*)(qp + 4);
    float4 k0 = *(const float4*)kp,       k1 = *(const float4*)(kp + 4);
    float4 v0 = *(const float4*)vp,       v1 = *(const float4*)(vp + 4);
    float aq = x0.x*q0.x + x0.y*q0.y + x0.z*q0.z + x0.w*q0.w
             + x1.x*q1.x + x1.y*q1.y + x1.z*q1.z + x1.w*q1.w;
    float ak = x0.x*k0.x + x0.y*k0.y + x0.z*k0.z + x0.w*k0.w
             + x1.x*k1.x + x1.y*k1.y + x1.z*k1.z + x1.w*k1.w;
    float av = i0.x*v0.x + i0.y*v0.y + i0.z*v0.z + i0.w*v0.w
             + i1.x*v1.x + i1.y*v1.y + i1.z*v1.z + i1.w*v1.w;
    q[idx] = aq; k[idx] = ak; v[idx] = av;
}

// ---------------- mLSTM gates via tf32 mma ----------------
__global__ void __launch_bounds__(256)
mlstm_gates_mma(const float* __restrict__ q, const float* __restrict__ k,
                const float* __restrict__ v,
                const float* __restrict__ igw, const float* __restrict__ igb,
                const float* __restrict__ fgw, const float* __restrict__ fgb,
                float* __restrict__ ip, float* __restrict__ fp) {
    __shared__ uint32_t sW[8][768];
    int tid = threadIdx.x;
    for (int i = tid; i < 8 * 768; i += 256) {
        int n = i / 768, kk = i - n * 768;
        float wv = (n < 4) ? igw[n * 768 + kk] : fgw[(n - 4) * 768 + kk];
        sW[n][kk] = f2tf32(wv);
    }
    __syncthreads();
    int w = tid >> 5, lane = tid & 31;
    int g = lane >> 2, t = lane & 3;
    int base = blockIdx.x * 128 + w * 16;
    float acc[4] = {0.f, 0.f, 0.f, 0.f};
    const float* arrs[3] = {q, k, v};
    #pragma unroll
    for (int seg = 0; seg < 3; seg++) {
        const float* r0 = arrs[seg] + (size_t)(base + g) * 256;
        const float* r1 = arrs[seg] + (size_t)(base + g + 8) * 256;
        const uint32_t* wrow = &sW[g][seg * 256];
        for (int ks = 0; ks < 32; ks++) {
            int k0 = ks * 8;
            uint32_t a[4], b[2];
            a[0] = f2tf32(r0[k0 + t]);
            a[1] = f2tf32(r1[k0 + t]);
            a[2] = f2tf32(r0[k0 + t + 4]);
            a[3] = f2tf32(r1[k0 + t + 4]);
            b[0] = wrow[k0 + t];
            b[1] = wrow[k0 + t + 4];
            mma_tf32(acc, a, b);
        }
    }
    int rows[2] = {base + g, base + g + 8};
    int ns[2] = {2 * t, 2 * t + 1};
    #pragma unroll
    for (int ri = 0; ri < 2; ri++) {
        #pragma unroll
        for (int ci = 0; ci < 2; ci++) {
            float val = acc[ri * 2 + ci];
            int row = rows[ri], n = ns[ci];
            int b_ = row >> 8, s = row & 255;
            if (n < 4) ip[(b_ * NHH + n) * SS + s] = val + igb[n];
            else       fp[(b_ * NHH + (n - 4)) * SS + s] = val + fgb[n - 4];
        }
    }
}

// ---------------- parallel gate prefix ----------------
__global__ void mlstm_prefix_kernel(const float* __restrict__ ip, const float* __restrict__ fp,
                                    float* __restrict__ slf, float* __restrict__ ek,
                                    float* __restrict__ pmx) {
    int warp = (blockIdx.x * blockDim.x + threadIdx.x) >> 5;
    int lane = threadIdx.x & 31;
    size_t base = (size_t)warp * SS + lane * 8;
    float fv[8], iv[8];
    {
        float4 a = *(const float4*)(fp + base);
        float4 b = *(const float4*)(fp + base + 4);
        fv[0]=a.x; fv[1]=a.y; fv[2]=a.z; fv[3]=a.w; fv[4]=b.x; fv[5]=b.y; fv[6]=b.z; fv[7]=b.w;
        float4 c = *(const float4*)(ip + base);
        float4 d = *(const float4*)(ip + base + 4);
        iv[0]=c.x; iv[1]=c.y; iv[2]=c.z; iv[3]=c.w; iv[4]=d.x; iv[5]=d.y; iv[6]=d.z; iv[7]=d.w;
    }
    float ls[8], lsum = 0.f;
    #pragma unroll
    for (int t = 0; t < 8; t++) {
        float f = fv[t];
        ls[t] = fminf(f, 0.f) - log1pf(expf(-fabsf(f)));
        lsum += ls[t];
    }
    float run = lsum;
    #pragma unroll
    for (int o = 1; o < 32; o <<= 1) {
        float vv = __shfl_up_sync(0xffffffffu, run, o);
        if (lane >= o) run += vv;
    }
    float c = run - lsum;
    float sl[8], ev[8], lmax = -1e30f;
    #pragma unroll
    for (int t = 0; t < 8; t++) {
        c += ls[t];
        sl[t] = c;
        ev[t] = iv[t] - c;
        lmax = fmaxf(lmax, ev[t]);
    }
    float rmax = lmax;
    #pragma unroll
    for (int o = 1; o < 32; o <<= 1) {
        float vv = __shfl_up_sync(0xffffffffu, rmax, o);
        if (lane >= o) rmax = fmaxf(rmax, vv);
    }
    float exclmax = __shfl_up_sync(0xffffffffu, rmax, 1);
    if (lane == 0) exclmax = -1e30f;
    float pm[8];
    float cm = exclmax;
    #pragma unroll
    for (int t = 0; t < 8; t++) {
        cm = fmaxf(cm, ev[t]);
        pm[t] = cm;
    }
    *(float4*)(slf + base)     = make_float4(sl[0], sl[1], sl[2], sl[3]);
    *(float4*)(slf + base + 4) = make_float4(sl[4], sl[5], sl[6], sl[7]);
    *(float4*)(ek + base)      = make_float4(ev[0], ev[1], ev[2], ev[3]);
    *(float4*)(ek + base + 4)  = make_float4(ev[4], ev[5], ev[6], ev[7]);
    *(float4*)(pmx + base)     = make_float4(pm[0], pm[1], pm[2], pm[3]);
    *(float4*)(pmx + base + 4) = make_float4(pm[4], pm[5], pm[6], pm[7]);
}

// ---------------- tensor-core attention ----------------
// One CTA per (b,h); 8 warps, warp handles 32 q-rows (range remapped for balance).
// smem: K tf32 [256][68], V^T tf32 [64][260], per-warp coeff [32][68], ce/px/lf.
// coeff = (QK^T/8) * exp(e_k) * exp(-pmx[q]), masked; AV via mma with coeff staged tf32.
#define ATTN_SMEM_U32 (17408 + 16640 + 8*32*68 + 768)
#define ATTN_SMEM_B   (ATTN_SMEM_U32 * 4)
__global__ void __launch_bounds__(256, 1)
mlstm_attn_tc(const float* __restrict__ q, const float* __restrict__ k,
              const float* __restrict__ v,
              const float* __restrict__ slf, const float* __restrict__ ek,
              const float* __restrict__ pmx, float* __restrict__ out) {
    extern __shared__ uint32_t su[];
    uint32_t* sK  = su;                    // [256][68]  (n=k-index, k=d)
    uint32_t* sVT = su + 17408;            // [64][260]  (n=d, k=kv-index)
    uint32_t* sC  = su + 17408 + 16640;    // [8][32][68]
    float* s_ce = (float*)(su + 17408 + 16640 + 8*32*68);
    float* s_px = s_ce + 256;
    float* s_lf = s_px + 256;

    int bh = blockIdx.x, b = bh >> 2, h = bh & 3;
    int tid = threadIdx.x, w = tid >> 5, lane = tid & 31;
    int g = lane >> 2, t = lane & 3;

    const float* kb = k + ((size_t)b * SS) * DIM + h * 64;
    const float* vb = v + ((size_t)b * SS) * DIM + h * 64;
    for (int e = tid; e < SS * 64; e += 256) {
        int kk = e >> 6, d = e & 63;
        sK [kk * 68 + d]  = f2tf32(kb[(size_t)kk * DIM + d]);
        sVT[d * 260 + kk] = f2tf32(vb[(size_t)kk * DIM + d]);
    }
    for (int i = tid; i < SS; i += 256) {
        s_ce[i] = __expf(fminf(ek[(size_t)bh * SS + i], 80.f));
        s_px[i] = pmx[(size_t)bh * SS + i];
        s_lf[i] = slf[(size_t)bh * SS + i];
    }

    int r = (w < 4) ? 2 * w : 15 - 2 * w;   // tile counts balanced per SMSP
    int rb = r * 32;
    // Q fragments (persistent): A[mi][dc] covers rows rb+mi*16..+16, dims dc*8..+8
    const float* qb = q + ((size_t)(b * SS + rb)) * DIM + h * 64;
    uint32_t qa[2][8][4];
    #pragma unroll
    for (int mi = 0; mi < 2; mi++)
        #pragma unroll
        for (int dc = 0; dc < 8; dc++) {
            qa[mi][dc][0] = f2tf32(qb[(size_t)(mi*16+g)   * DIM + dc*8 + t]);
            qa[mi][dc][1] = f2tf32(qb[(size_t)(mi*16+g+8) * DIM + dc*8 + t]);
            qa[mi][dc][2] = f2tf32(qb[(size_t)(mi*16+g)   * DIM + dc*8 + t + 4]);
            qa[mi][dc][3] = f2tf32(qb[(size_t)(mi*16+g+8) * DIM + dc*8 + t + 4]);
        }
    __syncthreads();

    float qf[2][2];
    #pragma unroll
    for (int mi = 0; mi < 2; mi++)
        #pragma unroll
        for (int ri = 0; ri < 2; ri++)
            qf[mi][ri] = __expf(fminf(-s_px[rb + mi*16 + g + 8*ri], 80.f));

    float Oacc[2][8][4] = {};
    float rs[2][2] = {};
    uint32_t* myC = sC + w * (32 * 68);
    int ntile = (r >> 1) + 1;

    for (int tt = 0; tt < ntile; tt++) {
        int kc = tt * 64;
        // --- QK^T ---
        float Sacc[2][8][4] = {};
        #pragma unroll
        for (int dc = 0; dc < 8; dc++) {
            uint32_t bf[8][2];
            #pragma unroll
            for (int ni = 0; ni < 8; ni++) {
                int krow = kc + ni * 8 + g;
                bf[ni][0] = sK[krow * 68 + dc * 8 + t];
                bf[ni][1] = sK[krow * 68 + dc * 8 + t + 4];
            }
            #pragma unroll
            for (int mi = 0; mi < 2; mi++)
                #pragma unroll
                for (int ni = 0; ni < 8; ni++)
                    mma_tf32(Sacc[mi][ni], qa[mi][dc], bf[ni]);
        }
        // --- coeff transform + stage + rowsum ---
        #pragma unroll
        for (int ni = 0; ni < 8; ni++) {
            int c0 = kc + ni * 8 + 2 * t;
            float ce0 = 0.125f * s_ce[c0], ce1 = 0.125f * s_ce[c0 + 1];
            #pragma unroll
            for (int mi = 0; mi < 2; mi++) {
                #pragma unroll
                for (int ri = 0; ri < 2; ri++) {
                    int lrow = mi * 16 + g + 8 * ri;
                    int qrow = rb + lrow;
                    float f = qf[mi][ri];
                    float v0 = Sacc[mi][ni][ri * 2]     * ce0 * f;
                    float v1 = Sacc[mi][ni][ri * 2 + 1] * ce1 * f;
                    if (c0 > qrow) v0 = 0.f;
                    if (c0 + 1 > qrow) v1 = 0.f;
                    rs[mi][ri] += v0 + v1;
                    myC[lrow * 68 + ni * 8 + 2 * t]     = f2tf32(v0);
                    myC[lrow * 68 + ni * 8 + 2 * t + 1] = f2tf32(v1);
                }
            }
        }
        __syncwarp();
        // --- AV ---
        #pragma unroll
        for (int kch = 0; kch < 8; kch++) {
            uint32_t af[2][4];
            #pragma unroll
            for (int mi = 0; mi < 2; mi++) {
                af[mi][0] = myC[(mi*16+g)   * 68 + kch*8 + t];
                af[mi][1] = myC[(mi*16+g+8) * 68 + kch*8 + t];
                af[mi][2] = myC[(mi*16+g)   * 68 + kch*8 + t + 4];
                af[mi][3] = myC[(mi*16+g+8) * 68 + kch*8 + t + 4];
            }
            uint32_t bf2[8][2];
            #pragma unroll
            for (int dn = 0; dn < 8; dn++) {
                int drow = dn * 8 + g;
                bf2[dn][0] = sVT[drow * 260 + kc + kch * 8 + t];
                bf2[dn][1] = sVT[drow * 260 + kc + kch * 8 + t + 4];
            }
            #pragma unroll
            for (int mi = 0; mi < 2; mi++)
                #pragma unroll
                for (int dn = 0; dn < 8; dn++)
                    mma_tf32(Oacc[mi][dn], af[mi], bf2[dn]);
        }
        __syncwarp();
    }

    // rowsum reduce across quad (t dimension)
    #pragma unroll
    for (int mi = 0; mi < 2; mi++)
        #pragma unroll
        for (int ri = 0; ri < 2; ri++) {
            float s = rs[mi][ri];
            s += __shfl_xor_sync(0xffffffffu, s, 1);
            s += __shfl_xor_sync(0xffffffffu, s, 2);
            rs[mi][ri] = s;
        }
    // normalize + write
    #pragma unroll
    for (int mi = 0; mi < 2; mi++) {
        #pragma unroll
        for (int ri = 0; ri < 2; ri++) {
            int qrow = rb + mi * 16 + g + 8 * ri;
            float maxd = s_lf[qrow] + s_px[qrow];
            float inv = 1.0f / (fmaxf(fabsf(rs[mi][ri]), __expf(fminf(-maxd, 80.f))) + 1e-6f);
            float* ob = out + ((size_t)(b * SS + qrow)) * DIM + h * 64;
            #pragma unroll
            for (int dn = 0; dn < 8; dn++) {
                float2 o;
                o.x = Oacc[mi][dn][ri * 2]     * inv;
                o.y = Oacc[mi][dn][ri * 2 + 1] * inv;
                *(float2*)(ob + dn * 8 + 2 * t) = o;
            }
        }
    }
}

// sLSTM block-diagonal gates — transposed weights
__global__ void slstm_bd_kernel(const float* __restrict__ xc, const float* __restrict__ xn,
                                const float* __restrict__ wT,
                                float* __restrict__ gi, float* __restrict__ gf,
                                float* __restrict__ gz, float* __restrict__ go) {
    int idx = blockIdx.x * blockDim.x + threadIdx.x;
    int c = idx & 127;
    size_t bs = (size_t)(idx >> 7);
    int h = c >> 5, e = c & 31;
    const float* base = wT + h * 1024 + e;
    const float* xcb = xc + bs * DD + h * 32;
    const float* xnb = xn + bs * DD + h * 32;
    float a1 = 0, a2 = 0, a3 = 0, a4 = 0;
    #pragma unroll
    for (int d = 0; d < 32; d++) {
        float xv = xcb[d], nv = xnb[d];
        int o = d * 32;
        a1 += xv * base[o];
        a2 += xv * base[4096 + o];
        a3 += nv * base[8192 + o];
        a4 += nv * base[12288 + o];
    }
    gi[idx] = a1; gf[idx] = a2; gz[idx] = a3; go[idx] = a4;
}

#define SCAN_SMEM (4 * 32 * 128 * sizeof(float))
__global__ void __launch_bounds__(512, 1)
slstm_scan_kernel(const float* __restrict__ gi, const float* __restrict__ gf,
                  const float* __restrict__ gz, const float* __restrict__ go,
                  const float* __restrict__ rw, const float* __restrict__ bias,
                  float* __restrict__ y) {
    int b = blockIdx.x;
    int tid = threadIdx.x;
    extern __shared__ float srw[];
    __shared__ float hs[128], cs[128], ns[128], ms[128];
    __shared__ float sb[512], srec[512];
    for (int i = tid; i < 16384; i += 512) srw[i] = rw[i];
    sb[tid] = bias[tid];
    if (tid < 128) { hs[tid] = 0.f; cs[tid] = 0.f; ns[tid] = 0.f; ms[tid] = 0.f; }
    __syncthreads();
    int h = tid >> 7, j = tid & 127;
    const float* wp = srw + h * 4096 + j;
    const float* hb = hs + h * 32;
    for (int t = 0; t < SS; t++) {
        float r0 = 0, r1 = 0;
        #pragma unroll
        for (int d = 0; d < 32; d += 2) {
            r0 += hb[d]     * wp[d * 128];
            r1 += hb[d + 1] * wp[(d + 1) * 128];
        }
        srec[tid] = r0 + r1;
        __syncthreads();
        if (tid < 128) {
            size_t gidx = ((size_t)b * SS + t) * DD + tid;
            int hh = tid >> 5, d = tid & 31;
            int rb = hh * 128;
            float ix = gi[gidx] + srec[rb + d]      + sb[rb + d];
            float fx = gf[gidx] + srec[rb + 32 + d] + sb[rb + 32 + d];
            float zx = gz[gidx] + srec[rb + 64 + d] + sb[rb + 64 + d];
            float ox = go[gidx] + srec[rb + 96 + d] + sb[rb + 96 + d];
            float ls  = fminf(fx, 0.f) - log1pf(__expf(-fabsf(fx)));
            float lpm = ms[tid] + ls;
            float mn  = fmaxf(ix, lpm);
            float ig  = __expf(ix - mn);
            float fg  = __expf(lpm - mn);
            float cn  = fg * cs[tid] + ig * tanhf(zx);
            float nn  = fg * ns[tid] + ig;
            float hn  = cn / (nn * (1.0f + __expf(-ox)));
            cs[tid] = cn; ns[tid] = nn; ms[tid] = mn; hs[tid] = hn;
            y[gidx] = hn;
        }
        __syncthreads();
    }
}

// ---------------- tf32 GEMM: 128x128 tile ----------------
template<int AOP>
__global__ void __launch_bounds__(256)
gemm_tf32_kernel(const float* __restrict__ A, const float* __restrict__ A2,
                 const float* __restrict__ A3, const float* __restrict__ Askip,
                 const float* __restrict__ W, float* __restrict__ C,
                 int N, int Kd, int accum) {
    __shared__ __align__(16) uint32_t sA[2][128][20];
    __shared__ __align__(16) uint32_t sB[2][128][20];
    const int bm = blockIdx.y * 128, bn = blockIdx.x * 128;
    const int tid = threadIdx.x;
    const int wid = tid >> 5, lane = tid & 31;
    const int wm = wid & 1, wn = wid >> 1;
    const int g = lane >> 2, t = lane & 3;
    const int arow = tid >> 1;
    const int acg = (tid & 1) << 3;
    float acc[4][4][4] = {};

    auto loadA4 = [&](int gr, int gk) -> float4 {
        float4 r;
        if (AOP == 0) {
            r = *(const float4*)(A + (size_t)gr * Kd + gk);
        } else if (AOP == 1) {
            float4 gg = *(const float4*)(A + (size_t)gr * 512 + gk);
            float4 u  = *(const float4*)(A + (size_t)gr * 512 + 256 + gk);
            r.x = 0.5f * gg.x * (1.0f + erff(gg.x * 0.70710678f)) * u.x;
            r.y = 0.5f * gg.y * (1.0f + erff(gg.y * 0.70710678f)) * u.y;
            r.z = 0.5f * gg.z * (1.0f + erff(gg.z * 0.70710678f)) * u.z;
            r.w = 0.5f * gg.w * (1.0f + erff(gg.w * 0.70710678f)) * u.w;
        } else {
            float4 hv = *(const float4*)(A  + (size_t)gr * 256 + gk);
            float4 xv = *(const float4*)(A2 + (size_t)gr * 256 + gk);
            float4 sk = *(const float4*)(Askip + gk);
            float4 zv = *(const float4*)(A3 + (size_t)gr * 512 + 256 + gk);
            r.x = (hv.x + sk.x * xv.x) * (zv.x / (1.0f + __expf(-zv.x)));
            r.y = (hv.y + sk.y * xv.y) * (zv.y / (1.0f + __expf(-zv.y)));
            r.z = (hv.z + sk.z * xv.z) * (zv.z / (1.0f + __expf(-zv.z)));
            r.w = (hv.w + sk.w * xv.w) * (zv.w / (1.0f + __expf(-zv.w)));
        }
        return r;
    };
    auto cvt4 = [&](float4 f) -> uint4 {
        return make_uint4(f2tf32(f.x), f2tf32(f.y), f2tf32(f.z), f2tf32(f.w));
    };
    auto compute = [&](int bf) {
        #pragma unroll
        for (int ks = 0; ks < 2; ks++) {
            int kb = ks * 8;
            uint32_t af[4][4], bfr[4][2];
            #pragma unroll
            for (int mi = 0; mi < 4; mi++) {
                int r0 = wm * 64 + mi * 16 + g;
                af[mi][0] = sA[bf][r0][kb + t];
                af[mi][1] = sA[bf][r0 + 8][kb + t];
                af[mi][2] = sA[bf][r0][kb + t + 4];
                af[mi][3] = sA[bf][r0 + 8][kb + t + 4];
            }
            #pragma unroll
            for (int ni = 0; ni < 4; ni++) {
                int c0 = wn * 32 + ni * 8 + g;
                bfr[ni][0] = sB[bf][c0][kb + t];
                bfr[ni][1] = sB[bf][c0][kb + t + 4];
            }
            #pragma unroll
            for (int mi = 0; mi < 4; mi++)
                #pragma unroll
                for (int ni = 0; ni < 4; ni++)
                    mma_tf32(acc[mi][ni], af[mi], bfr[ni]);
        }
    };

    {
        float4 alo = loadA4(bm + arow, acg);
        float4 ahi = loadA4(bm + arow, acg + 4);
        float4 wlo = *(const float4*)(W + (size_t)(bn + arow) * Kd + acg);
        float4 whi = *(const float4*)(W + (size_t)(bn + arow) * Kd + acg + 4);
        *(uint4*)&sA[0][arow][acg]     = cvt4(alo);
        *(uint4*)&sA[0][arow][acg + 4] = cvt4(ahi);
        *(uint4*)&sB[0][arow][acg]     = cvt4(wlo);
        *(uint4*)&sB[0][arow][acg + 4] = cvt4(whi);
    }
    __syncthreads();

    int buf = 0;
    for (int k0 = 16; k0 < Kd; k0 += 16) {
        float4 alo = loadA4(bm + arow, k0 + acg);
        float4 ahi = loadA4(bm + arow, k0 + acg + 4);
        float4 wlo = *(const float4*)(W + (size_t)(bn + arow) * Kd + k0 + acg);
        float4 whi = *(const float4*)(W + (size_t)(bn + arow) * Kd + k0 + acg + 4);
        compute(buf);
        int nb = buf ^ 1;
        *(uint4*)&sA[nb][arow][acg]     = cvt4(alo);
        *(uint4*)&sA[nb][arow][acg + 4] = cvt4(ahi);
        *(uint4*)&sB[nb][arow][acg]     = cvt4(wlo);
        *(uint4*)&sB[nb][arow][acg + 4] = cvt4(whi);
        __syncthreads();
        buf = nb;
    }
    compute(buf);

    #pragma unroll
    for (int mi = 0; mi < 4; mi++) {
        #pragma unroll
        for (int ni = 0; ni < 4; ni++) {
            int grow = bm + wm * 64 + mi * 16 + g;
            int gcol = bn + wn * 32 + ni * 8 + t * 2;
            float* p0 = C + (size_t)grow * N + gcol;
            float* p1 = C + (size_t)(grow + 8) * N + gcol;
            if (accum) {
                float2 x0 = *(float2*)p0, x1 = *(float2*)p1;
                x0.x += acc[mi][ni][0]; x0.y += acc[mi][ni][1];
                x1.x += acc[mi][ni][2]; x1.y += acc[mi][ni][3];
                *(float2*)p0 = x0; *(float2*)p1 = x1;
            } else {
                *(float2*)p0 = make_float2(acc[mi][ni][0], acc[mi][ni][1]);
                *(float2*)p1 = make_float2(acc[mi][ni][2], acc[mi][ni][3]);
            }
        }
    }
}

extern "C" void kernel_launch(void* const* d_in, const int* in_sizes, int n_in,
                              void* d_out, int out_size) {
    const int*   x          = (const int*)  d_in[0];
    const float* emb        = (const float*)d_in[1];
    const float* m_ln_w     = (const float*)d_in[2];
    const float* m_up_w     = (const float*)d_in[3];
    const float* m_conv_w   = (const float*)d_in[4];
    const float* m_conv_b   = (const float*)d_in[5];
    const float* m_q_w      = (const float*)d_in[6];
    const float* m_k_w      = (const float*)d_in[7];
    const float* m_v_w      = (const float*)d_in[8];
    const float* m_ig_w     = (const float*)d_in[9];
    const float* m_ig_b     = (const float*)d_in[10];
    const float* m_fg_w     = (const float*)d_in[11];
    const float* m_fg_b     = (const float*)d_in[12];
    const float* m_on_w     = (const float*)d_in[13];
    const float* m_skip     = (const float*)d_in[14];
    const float* m_down_w   = (const float*)d_in[15];
    const float* s_ln1_w    = (const float*)d_in[16];
    const float* s_conv_w   = (const float*)d_in[17];
    const float* s_conv_b   = (const float*)d_in[18];
    const float* s_ig_w     = (const float*)d_in[19];
    const float* s_fg_w     = (const float*)d_in[20];
    const float* s_zg_w     = (const float*)d_in[21];
    const float* s_og_w     = (const float*)d_in[22];
    const float* s_rec_w    = (const float*)d_in[23];
    const float* s_bias     = (const float*)d_in[24];
    const float* s_gn_w     = (const float*)d_in[25];
    const float* s_ln2_w    = (const float*)d_in[26];
    const float* s_ff_up_w  = (const float*)d_in[27];
    const float* s_ff_down_w= (const float*)d_in[28];
    const float* post_norm_w= (const float*)d_in[29];
    float* out = (float*)d_out;

    float *h_, *xn_, *big_, *xca_, *q_, *k_, *v_, *ht_;
    float *gi_, *gf_, *gz_, *go_, *y_, *ip_, *fp_, *slf_, *ek_, *pmx_, *wT_;
    cudaGetSymbolAddress((void**)&h_,   g_h);
    cudaGetSymbolAddress((void**)&xn_,  g_xn);
    cudaGetSymbolAddress((void**)&big_, g_big);
    cudaGetSymbolAddress((void**)&xca_, g_xca);
    cudaGetSymbolAddress((void**)&q_,   g_q);
    cudaGetSymbolAddress((void**)&k_,   g_k);
    cudaGetSymbolAddress((void**)&v_,   g_v);
    cudaGetSymbolAddress((void**)&ht_,  g_ht);
    cudaGetSymbolAddress((void**)&gi_,  g_gi);
    cudaGetSymbolAddress((void**)&gf_,  g_gf);
    cudaGetSymbolAddress((void**)&gz_,  g_gz);
    cudaGetSymbolAddress((void**)&go_,  g_go);
    cudaGetSymbolAddress((void**)&y_,   g_y);
    cudaGetSymbolAddress((void**)&ip_,  g_ip);
    cudaGetSymbolAddress((void**)&fp_,  g_fp);
    cudaGetSymbolAddress((void**)&slf_, g_slf);
    cudaGetSymbolAddress((void**)&ek_,  g_ek);
    cudaGetSymbolAddress((void**)&pmx_, g_pmx);
    cudaGetSymbolAddress((void**)&wT_,  g_wT);

    cudaFuncSetAttribute(mlstm_attn_tc, cudaFuncAttributeMaxDynamicSharedMemorySize, ATTN_SMEM_B);
    cudaFuncSetAttribute(slstm_scan_kernel, cudaFuncAttributeMaxDynamicSharedMemorySize, (int)SCAN_SMEM);

    embed_ln_kernel<<<BS, 128>>>(x, emb, m_ln_w, h_, xn_);
    gemm_tf32_kernel<0><<<dim3(4, BS / 128), 256>>>(xn_, nullptr, nullptr, nullptr,
                                                    m_up_w, big_, 512, 128, 0);
    conv_silu_kernel<512, 256><<<BS * DIM / 256, 256>>>(big_, m_conv_w, m_conv_b, xca_);
    mlstm_qkv_kernel<<<BS * DIM / 256, 256>>>(xca_, big_, m_q_w, m_k_w, m_v_w, q_, k_, v_);
    mlstm_gates_mma<<<BS / 128, 256>>>(q_, k_, v_, m_ig_w, m_ig_b, m_fg_w, m_fg_b, ip_, fp_);
    mlstm_prefix_kernel<<<64, 256>>>(ip_, fp_, slf_, ek_, pmx_);
    mlstm_attn_tc<<<BB * NHH, 256, ATTN_SMEM_B>>>(q_, k_, v_, slf_, ek_, pmx_, ht_);
    groupln_kernel<256, 64><<<BS * NHH * 32 / 256, 256>>>(ht_, m_on_w, nullptr, ht_);
    gemm_tf32_kernel<2><<<dim3(1, BS / 128), 256>>>(ht_, xca_, big_, m_skip,
                                                    m_down_w, h_, 128, 256, 1);

    transpose_w_kernel<<<64, 256>>>(s_ig_w, s_fg_w, s_zg_w, s_og_w, wT_, 0);
    transpose_w_kernel<<<64, 256>>>(s_ig_w, s_fg_w, s_zg_w, s_og_w, wT_, 16384);

    for (int i = 0; i < 2; i++) {
        ln128_kernel<<<BS, 128>>>(h_, s_ln1_w + i * DD, xn_);
        conv_silu_kernel<128, 128><<<BS * DD / 256, 256>>>(xn_, s_conv_w + i * DD * 4,
                                                           s_conv_b + i * DD, xca_);
        slstm_bd_kernel<<<BS * DD / 256, 256>>>(xca_, xn_, wT_ + i * 16384,
                                                gi_, gf_, gz_, go_);
        slstm_scan_kernel<<<BB, 512, SCAN_SMEM>>>(gi_, gf_, gz_, go_,
            s_rec_w + i * 16384, s_bias + i * 512, y_);
        groupln_kernel<128, 32><<<BS * NHH * 32 / 256, 256>>>(y_, s_gn_w + i * DD, h_, h_);
        ln128_kernel<<<BS, 128>>>(h_, s_ln2_w + i * DD, xn_);
        gemm_tf32_kernel<0><<<dim3(4, BS / 128), 256>>>(xn_, nullptr, nullptr, nullptr,
                                                        s_ff_up_w + i * 512 * 128, big_, 512, 128, 0);
        gemm_tf32_kernel<1><<<dim3(1, BS / 128), 256>>>(big_, nullptr, nullptr, nullptr,
                                                        s_ff_down_w + i * 128 * 256, h_, 128, 256, 1);
    }

    ln128_kernel<<<BS, 128>>>(h_, post_norm_w, out);
}

// round 13
// speedup vs baseline: 1.2982x; 1.0499x over previous
#include <cuda_runtime.h>
#include <cuda_bf16.h>
#include <math.h>
#include <stdint.h>

#define BB   128
#define SS   256
#define DD   128
#define DIM  256
#define NHH  4
#define BS   (BB*SS)

__device__ float g_h  [BS*DD];
__device__ float g_xn [BS*DD];
__device__ float g_big[BS*512];
__device__ float g_xca[BS*DIM];
__device__ float g_q  [BS*DIM];
__device__ float g_k  [BS*DIM];
__device__ float g_v  [BS*DIM];
__device__ float g_ht [BS*DIM];
__device__ float g_gi [BS*DD];
__device__ float g_gf [BS*DD];
__device__ float g_gz [BS*DD];
__device__ float g_go [BS*DD];
__device__ float g_y  [BS*DD];
__device__ float g_ip [BB*NHH*SS];
__device__ float g_fp [BB*NHH*SS];
__device__ float g_slf[BB*NHH*SS];
__device__ float g_ek [BB*NHH*SS];
__device__ float g_pmx[BB*NHH*SS];
__device__ float g_wT [2*4*4096];

// ---------------- tf32 helpers ----------------
__device__ __forceinline__ uint32_t f2tf32(float f) {
    uint32_t r;
    asm("cvt.rna.tf32.f32 %0, %1;" : "=r"(r) : "f"(f));
    return r;
}
__device__ __forceinline__ void mma_tf32(float* d, const uint32_t* a, const uint32_t* b) {
    asm volatile(
        "mma.sync.aligned.m16n8k8.row.col.f32.tf32.tf32.f32 "
        "{%0,%1,%2,%3}, {%4,%5,%6,%7}, {%8,%9}, {%0,%1,%2,%3};"
        : "+f"(d[0]), "+f"(d[1]), "+f"(d[2]), "+f"(d[3])
        : "r"(a[0]), "r"(a[1]), "r"(a[2]), "r"(a[3]), "r"(b[0]), "r"(b[1]));
}

// ---------------- fused embedding + LayerNorm ----------------
__global__ void embed_ln_kernel(const int* __restrict__ x, const float* __restrict__ emb,
                                const float* __restrict__ w,
                                float* __restrict__ h, float* __restrict__ xn) {
    int row = blockIdx.x;
    int tid = threadIdx.x;  // 128
    __shared__ float r1[4], r2[4];
    float v = emb[x[row] * DD + tid];
    h[(size_t)row * DD + tid] = v;
    float s = v;
    #pragma unroll
    for (int o = 16; o; o >>= 1) s += __shfl_xor_sync(0xffffffffu, s, o);
    if ((tid & 31) == 0) r1[tid >> 5] = s;
    __syncthreads();
    float mu = (r1[0] + r1[1] + r1[2] + r1[3]) * (1.0f / DD);
    float d = v - mu;
    float sq = d * d;
    #pragma unroll
    for (int o = 16; o; o >>= 1) sq += __shfl_xor_sync(0xffffffffu, sq, o);
    if ((tid & 31) == 0) r2[tid >> 5] = sq;
    __syncthreads();
    float var = (r2[0] + r2[1] + r2[2] + r2[3]) * (1.0f / DD);
    xn[(size_t)row * DD + tid] = d * rsqrtf(var + 1e-5f) * w[tid];
}

__global__ void ln128_kernel(const float* __restrict__ x, const float* __restrict__ w,
                             float* __restrict__ out) {
    int row = blockIdx.x;
    int tid = threadIdx.x;  // 128
    __shared__ float r1[4], r2[4];
    float v = x[(size_t)row * DD + tid];
    float s = v;
    #pragma unroll
    for (int o = 16; o; o >>= 1) s += __shfl_xor_sync(0xffffffffu, s, o);
    if ((tid & 31) == 0) r1[tid >> 5] = s;
    __syncthreads();
    float mu = (r1[0] + r1[1] + r1[2] + r1[3]) * (1.0f / DD);
    float d = v - mu;
    float sq = d * d;
    #pragma unroll
    for (int o = 16; o; o >>= 1) sq += __shfl_xor_sync(0xffffffffu, sq, o);
    if ((tid & 31) == 0) r2[tid >> 5] = sq;
    __syncthreads();
    float var = (r2[0] + r2[1] + r2[2] + r2[3]) * (1.0f / DD);
    out[(size_t)row * DD + tid] = d * rsqrtf(var + 1e-5f) * w[tid];
}

// fused: groupln(y, gs=32)*gnw + h -> h ; then LN(h)*ln2w -> xn. One block per row.
__global__ void slstm_post_kernel(const float* __restrict__ y, const float* __restrict__ gnw,
                                  const float* __restrict__ ln2w,
                                  float* __restrict__ h, float* __restrict__ xn) {
    int row = blockIdx.x;
    int tid = threadIdx.x;  // 128; warp = head (group of 32)
    __shared__ float r1[4], r2[4];
    float yv = y[(size_t)row * DD + tid];
    // group LN over this warp's 32 lanes
    float s = yv;
    #pragma unroll
    for (int o = 16; o; o >>= 1) s += __shfl_xor_sync(0xffffffffu, s, o);
    float mu = s * (1.0f / 32.0f);
    float e = yv - mu;
    float sq = e * e;
    #pragma unroll
    for (int o = 16; o; o >>= 1) sq += __shfl_xor_sync(0xffffffffu, sq, o);
    float rr = rsqrtf(sq * (1.0f / 32.0f) + 1e-5f);
    float hv = e * rr * gnw[tid] + h[(size_t)row * DD + tid];
    h[(size_t)row * DD + tid] = hv;
    // full-row LN
    float s2 = hv;
    #pragma unroll
    for (int o = 16; o; o >>= 1) s2 += __shfl_xor_sync(0xffffffffu, s2, o);
    if ((tid & 31) == 0) r1[tid >> 5] = s2;
    __syncthreads();
    float mu2 = (r1[0] + r1[1] + r1[2] + r1[3]) * (1.0f / DD);
    float d2 = hv - mu2;
    float q2 = d2 * d2;
    #pragma unroll
    for (int o = 16; o; o >>= 1) q2 += __shfl_xor_sync(0xffffffffu, q2, o);
    if ((tid & 31) == 0) r2[tid >> 5] = q2;
    __syncthreads();
    float var2 = (r2[0] + r2[1] + r2[2] + r2[3]) * (1.0f / DD);
    xn[(size_t)row * DD + tid] = d2 * rsqrtf(var2 + 1e-5f) * ln2w[tid];
}

template<int LDX, int C>
__global__ void conv_silu_kernel(const float* __restrict__ x,
                                 const float* __restrict__ w, const float* __restrict__ bias,
                                 float* __restrict__ out) {
    int idx = blockIdx.x * blockDim.x + threadIdx.x;
    int c = idx & (C - 1);
    int s = (idx / C) & (SS - 1);
    int b = idx / (C * SS);
    const float* xp = x + ((size_t)b * SS) * LDX + c;
    float acc = bias[c];
    #pragma unroll
    for (int j = 0; j < 4; j++) {
        int sj = s + j - 3;
        if (sj >= 0) acc += xp[(size_t)sj * LDX] * w[c * 4 + j];
    }
    out[idx] = acc / (1.0f + __expf(-acc));
}

__global__ void transpose_w_kernel(const float* __restrict__ ig, const float* __restrict__ fg,
                                   const float* __restrict__ zg, const float* __restrict__ og,
                                   float* __restrict__ wT, int off) {
    int idx = off + blockIdx.x * blockDim.x + threadIdx.x;
    int layer = idx >> 14;
    int arr = (idx >> 12) & 3;
    int r = idx & 4095;
    int h = r >> 10, e = (r >> 5) & 31, d = r & 31;
    const float* src = (arr == 0) ? ig : (arr == 1) ? fg : (arr == 2) ? zg : og;
    wT[layer * 16384 + arr * 4096 + h * 1024 + d * 32 + e] =
        src[layer * 4096 + h * 1024 + e * 32 + d];
}

// ---------------- mLSTM qkv: weights in regs, 8 rows per thread ----------------
__global__ void __launch_bounds__(256)
mlstm_qkv_kernel(const float* __restrict__ xca, const float* __restrict__ big,
                 const float* __restrict__ qw, const float* __restrict__ kw,
                 const float* __restrict__ vw,
                 float* __restrict__ q, float* __restrict__ k, float* __restrict__ v) {
    int tid = threadIdx.x;           // c = blk*8+e
    int blk = tid >> 3, e = tid & 7;
    size_t bs0 = (size_t)blockIdx.x * 8;
    const float* qp = qw + blk * 64 + e * 8;
    const float* kp = kw + blk * 64 + e * 8;
    const float* vp = vw + blk * 64 + e * 8;
    float4 q0 = *(const float4*)qp, q1 = *(const float4*)(qp + 4);
    float4 k0 = *(const float4*)kp, k1 = *(const float4*)(kp + 4);
    float4 v0 = *(const float4*)vp, v1 = *(const float4*)(vp + 4);
    #pragma unroll
    for (int i = 0; i < 8; i++) {
        size_t bs = bs0 + i;
        const float* xc = xca + bs * DIM + blk * 8;
        const float* xi = big + bs * 512 + blk * 8;
        float4 x0 = *(const float4*)xc, x1 = *(const float4*)(xc + 4);
        float4 i0 = *(const float4*)xi, i1 = *(const float4*)(xi + 4);
        float aq = x0.x*q0.x + x0.y*q0.y + x0.z*q0.z + x0.w*q0.w
                 + x1.x*q1.x + x1.y*q1.y + x1.z*q1.z + x1.w*q1.w;
        float ak = x0.x*k0.x + x0.y*k0.y + x0.z*k0.z + x0.w*k0.w
                 + x1.x*k1.x + x1.y*k1.y + x1.z*k1.z + x1.w*k1.w;
        float av = i0.x*v0.x + i0.y*v0.y + i0.z*v0.z + i0.w*v0.w
                 + i1.x*v1.x + i1.y*v1.y + i1.z*v1.z + i1.w*v1.w;
        q[bs * DIM + tid] = aq;
        k[bs * DIM + tid] = ak;
        v[bs * DIM + tid] = av;
    }
}

// ---------------- mLSTM gates via tf32 mma ----------------
__global__ void __launch_bounds__(256)
mlstm_gates_mma(const float* __restrict__ q, const float* __restrict__ k,
                const float* __restrict__ v,
                const float* __restrict__ igw, const float* __restrict__ igb,
                const float* __restrict__ fgw, const float* __restrict__ fgb,
                float* __restrict__ ip, float* __restrict__ fp) {
    __shared__ uint32_t sW[8][768];
    int tid = threadIdx.x;
    for (int i = tid; i < 8 * 768; i += 256) {
        int n = i / 768, kk = i - n * 768;
        float wv = (n < 4) ? igw[n * 768 + kk] : fgw[(n - 4) * 768 + kk];
        sW[n][kk] = f2tf32(wv);
    }
    __syncthreads();
    int w = tid >> 5, lane = tid & 31;
    int g = lane >> 2, t = lane & 3;
    int base = blockIdx.x * 128 + w * 16;
    float acc[4] = {0.f, 0.f, 0.f, 0.f};
    const float* arrs[3] = {q, k, v};
    #pragma unroll
    for (int seg = 0; seg < 3; seg++) {
        const float* r0 = arrs[seg] + (size_t)(base + g) * 256;
        const float* r1 = arrs[seg] + (size_t)(base + g + 8) * 256;
        const uint32_t* wrow = &sW[g][seg * 256];
        for (int ks = 0; ks < 32; ks++) {
            int k0 = ks * 8;
            uint32_t a[4], b[2];
            a[0] = f2tf32(r0[k0 + t]);
            a[1] = f2tf32(r1[k0 + t]);
            a[2] = f2tf32(r0[k0 + t + 4]);
            a[3] = f2tf32(r1[k0 + t + 4]);
            b[0] = wrow[k0 + t];
            b[1] = wrow[k0 + t + 4];
            mma_tf32(acc, a, b);
        }
    }
    int rows[2] = {base + g, base + g + 8};
    int ns[2] = {2 * t, 2 * t + 1};
    #pragma unroll
    for (int ri = 0; ri < 2; ri++) {
        #pragma unroll
        for (int ci = 0; ci < 2; ci++) {
            float val = acc[ri * 2 + ci];
            int row = rows[ri], n = ns[ci];
            int b_ = row >> 8, s = row & 255;
            if (n < 4) ip[(b_ * NHH + n) * SS + s] = val + igb[n];
            else       fp[(b_ * NHH + (n - 4)) * SS + s] = val + fgb[n - 4];
        }
    }
}

// ---------------- parallel gate prefix ----------------
__global__ void mlstm_prefix_kernel(const float* __restrict__ ip, const float* __restrict__ fp,
                                    float* __restrict__ slf, float* __restrict__ ek,
                                    float* __restrict__ pmx) {
    int warp = (blockIdx.x * blockDim.x + threadIdx.x) >> 5;
    int lane = threadIdx.x & 31;
    size_t base = (size_t)warp * SS + lane * 8;
    float fv[8], iv[8];
    {
        float4 a = *(const float4*)(fp + base);
        float4 b = *(const float4*)(fp + base + 4);
        fv[0]=a.x; fv[1]=a.y; fv[2]=a.z; fv[3]=a.w; fv[4]=b.x; fv[5]=b.y; fv[6]=b.z; fv[7]=b.w;
        float4 c = *(const float4*)(ip + base);
        float4 d = *(const float4*)(ip + base + 4);
        iv[0]=c.x; iv[1]=c.y; iv[2]=c.z; iv[3]=c.w; iv[4]=d.x; iv[5]=d.y; iv[6]=d.z; iv[7]=d.w;
    }
    float ls[8], lsum = 0.f;
    #pragma unroll
    for (int t = 0; t < 8; t++) {
        float f = fv[t];
        ls[t] = fminf(f, 0.f) - log1pf(expf(-fabsf(f)));
        lsum += ls[t];
    }
    float run = lsum;
    #pragma unroll
    for (int o = 1; o < 32; o <<= 1) {
        float vv = __shfl_up_sync(0xffffffffu, run, o);
        if (lane >= o) run += vv;
    }
    float c = run - lsum;
    float sl[8], ev[8], lmax = -1e30f;
    #pragma unroll
    for (int t = 0; t < 8; t++) {
        c += ls[t];
        sl[t] = c;
        ev[t] = iv[t] - c;
        lmax = fmaxf(lmax, ev[t]);
    }
    float rmax = lmax;
    #pragma unroll
    for (int o = 1; o < 32; o <<= 1) {
        float vv = __shfl_up_sync(0xffffffffu, rmax, o);
        if (lane >= o) rmax = fmaxf(rmax, vv);
    }
    float exclmax = __shfl_up_sync(0xffffffffu, rmax, 1);
    if (lane == 0) exclmax = -1e30f;
    float pm[8];
    float cm = exclmax;
    #pragma unroll
    for (int t = 0; t < 8; t++) {
        cm = fmaxf(cm, ev[t]);
        pm[t] = cm;
    }
    *(float4*)(slf + base)     = make_float4(sl[0], sl[1], sl[2], sl[3]);
    *(float4*)(slf + base + 4) = make_float4(sl[4], sl[5], sl[6], sl[7]);
    *(float4*)(ek + base)      = make_float4(ev[0], ev[1], ev[2], ev[3]);
    *(float4*)(ek + base + 4)  = make_float4(ev[4], ev[5], ev[6], ev[7]);
    *(float4*)(pmx + base)     = make_float4(pm[0], pm[1], pm[2], pm[3]);
    *(float4*)(pmx + base + 4) = make_float4(pm[4], pm[5], pm[6], pm[7]);
}

// ---------------- tensor-core attention + fused head group-LN epilogue ----------------
#define ATTN_SMEM_U32 (17408 + 16640 + 8*32*68 + 768)
#define ATTN_SMEM_B   (ATTN_SMEM_U32 * 4)
__global__ void __launch_bounds__(256, 1)
mlstm_attn_tc(const float* __restrict__ q, const float* __restrict__ k,
              const float* __restrict__ v,
              const float* __restrict__ slf, const float* __restrict__ ek,
              const float* __restrict__ pmx, const float* __restrict__ onw,
              float* __restrict__ out) {
    extern __shared__ uint32_t su[];
    uint32_t* sK  = su;                    // [256][68]
    uint32_t* sVT = su + 17408;            // [64][260]
    uint32_t* sC  = su + 17408 + 16640;    // [8][32][68]
    float* s_ce = (float*)(su + 17408 + 16640 + 8*32*68);
    float* s_px = s_ce + 256;
    float* s_lf = s_px + 256;

    int bh = blockIdx.x, b = bh >> 2, h = bh & 3;
    int tid = threadIdx.x, w = tid >> 5, lane = tid & 31;
    int g = lane >> 2, t = lane & 3;

    const float* kb = k + ((size_t)b * SS) * DIM + h * 64;
    const float* vb = v + ((size_t)b * SS) * DIM + h * 64;
    for (int e = tid; e < SS * 64; e += 256) {
        int kk = e >> 6, d = e & 63;
        sK [kk * 68 + d]  = f2tf32(kb[(size_t)kk * DIM + d]);
        sVT[d * 260 + kk] = f2tf32(vb[(size_t)kk * DIM + d]);
    }
    for (int i = tid; i < SS; i += 256) {
        s_ce[i] = __expf(fminf(ek[(size_t)bh * SS + i], 80.f));
        s_px[i] = pmx[(size_t)bh * SS + i];
        s_lf[i] = slf[(size_t)bh * SS + i];
    }

    int r = (w < 4) ? 2 * w : 15 - 2 * w;
    int rb = r * 32;
    const float* qb = q + ((size_t)(b * SS + rb)) * DIM + h * 64;
    uint32_t qa[2][8][4];
    #pragma unroll
    for (int mi = 0; mi < 2; mi++)
        #pragma unroll
        for (int dc = 0; dc < 8; dc++) {
            qa[mi][dc][0] = f2tf32(qb[(size_t)(mi*16+g)   * DIM + dc*8 + t]);
            qa[mi][dc][1] = f2tf32(qb[(size_t)(mi*16+g+8) * DIM + dc*8 + t]);
            qa[mi][dc][2] = f2tf32(qb[(size_t)(mi*16+g)   * DIM + dc*8 + t + 4]);
            qa[mi][dc][3] = f2tf32(qb[(size_t)(mi*16+g+8) * DIM + dc*8 + t + 4]);
        }
    __syncthreads();

    float qf[2][2];
    #pragma unroll
    for (int mi = 0; mi < 2; mi++)
        #pragma unroll
        for (int ri = 0; ri < 2; ri++)
            qf[mi][ri] = __expf(fminf(-s_px[rb + mi*16 + g + 8*ri], 80.f));

    float Oacc[2][8][4] = {};
    float rs[2][2] = {};
    uint32_t* myC = sC + w * (32 * 68);
    int ntile = (r >> 1) + 1;

    for (int tt = 0; tt < ntile; tt++) {
        int kc = tt * 64;
        float Sacc[2][8][4] = {};
        #pragma unroll
        for (int dc = 0; dc < 8; dc++) {
            uint32_t bf[8][2];
            #pragma unroll
            for (int ni = 0; ni < 8; ni++) {
                int krow = kc + ni * 8 + g;
                bf[ni][0] = sK[krow * 68 + dc * 8 + t];
                bf[ni][1] = sK[krow * 68 + dc * 8 + t + 4];
            }
            #pragma unroll
            for (int mi = 0; mi < 2; mi++)
                #pragma unroll
                for (int ni = 0; ni < 8; ni++)
                    mma_tf32(Sacc[mi][ni], qa[mi][dc], bf[ni]);
        }
        #pragma unroll
        for (int ni = 0; ni < 8; ni++) {
            int c0 = kc + ni * 8 + 2 * t;
            float ce0 = 0.125f * s_ce[c0], ce1 = 0.125f * s_ce[c0 + 1];
            #pragma unroll
            for (int mi = 0; mi < 2; mi++) {
                #pragma unroll
                for (int ri = 0; ri < 2; ri++) {
                    int lrow = mi * 16 + g + 8 * ri;
                    int qrow = rb + lrow;
                    float f = qf[mi][ri];
                    float v0 = Sacc[mi][ni][ri * 2]     * ce0 * f;
                    float v1 = Sacc[mi][ni][ri * 2 + 1] * ce1 * f;
                    if (c0 > qrow) v0 = 0.f;
                    if (c0 + 1 > qrow) v1 = 0.f;
                    rs[mi][ri] += v0 + v1;
                    myC[lrow * 68 + ni * 8 + 2 * t]     = f2tf32(v0);
                    myC[lrow * 68 + ni * 8 + 2 * t + 1] = f2tf32(v1);
                }
            }
        }
        __syncwarp();
        #pragma unroll
        for (int kch = 0; kch < 8; kch++) {
            uint32_t af[2][4];
            #pragma unroll
            for (int mi = 0; mi < 2; mi++) {
                af[mi][0] = myC[(mi*16+g)   * 68 + kch*8 + t];
                af[mi][1] = myC[(mi*16+g+8) * 68 + kch*8 + t];
                af[mi][2] = myC[(mi*16+g)   * 68 + kch*8 + t + 4];
                af[mi][3] = myC[(mi*16+g+8) * 68 + kch*8 + t + 4];
            }
            uint32_t bf2[8][2];
            #pragma unroll
            for (int dn = 0; dn < 8; dn++) {
                int drow = dn * 8 + g;
                bf2[dn][0] = sVT[drow * 260 + kc + kch * 8 + t];
                bf2[dn][1] = sVT[drow * 260 + kc + kch * 8 + t + 4];
            }
            #pragma unroll
            for (int mi = 0; mi < 2; mi++)
                #pragma unroll
                for (int dn = 0; dn < 8; dn++)
                    mma_tf32(Oacc[mi][dn], af[mi], bf2[dn]);
        }
        __syncwarp();
    }

    #pragma unroll
    for (int mi = 0; mi < 2; mi++)
        #pragma unroll
        for (int ri = 0; ri < 2; ri++) {
            float s = rs[mi][ri];
            s += __shfl_xor_sync(0xffffffffu, s, 1);
            s += __shfl_xor_sync(0xffffffffu, s, 2);
            rs[mi][ri] = s;
        }
    // head LN weights (same cols for every row this thread touches)
    float wv[8][2];
    #pragma unroll
    for (int dn = 0; dn < 8; dn++) {
        wv[dn][0] = onw[h * 64 + dn * 8 + 2 * t];
        wv[dn][1] = onw[h * 64 + dn * 8 + 2 * t + 1];
    }
    // normalize (mLSTM) + fused per-head group-LN + write
    #pragma unroll
    for (int mi = 0; mi < 2; mi++) {
        #pragma unroll
        for (int ri = 0; ri < 2; ri++) {
            int qrow = rb + mi * 16 + g + 8 * ri;
            float maxd = s_lf[qrow] + s_px[qrow];
            float inv = 1.0f / (fmaxf(fabsf(rs[mi][ri]), __expf(fminf(-maxd, 80.f))) + 1e-6f);
            float vals[8][2];
            float s = 0.f;
            #pragma unroll
            for (int dn = 0; dn < 8; dn++) {
                vals[dn][0] = Oacc[mi][dn][ri * 2]     * inv;
                vals[dn][1] = Oacc[mi][dn][ri * 2 + 1] * inv;
                s += vals[dn][0] + vals[dn][1];
            }
            s += __shfl_xor_sync(0xffffffffu, s, 1);
            s += __shfl_xor_sync(0xffffffffu, s, 2);
            float mu = s * (1.0f / 64.0f);
            float sq = 0.f;
            #pragma unroll
            for (int dn = 0; dn < 8; dn++) {
                float d0 = vals[dn][0] - mu, d1 = vals[dn][1] - mu;
                sq += d0 * d0 + d1 * d1;
            }
            sq += __shfl_xor_sync(0xffffffffu, sq, 1);
            sq += __shfl_xor_sync(0xffffffffu, sq, 2);
            float rr = rsqrtf(sq * (1.0f / 64.0f) + 1e-5f);
            float* ob = out + ((size_t)(b * SS + qrow)) * DIM + h * 64;
            #pragma unroll
            for (int dn = 0; dn < 8; dn++) {
                float2 o;
                o.x = (vals[dn][0] - mu) * rr * wv[dn][0];
                o.y = (vals[dn][1] - mu) * rr * wv[dn][1];
                *(float2*)(ob + dn * 8 + 2 * t) = o;
            }
        }
    }
}

// sLSTM block-diagonal gates — transposed weights
__global__ void slstm_bd_kernel(const float* __restrict__ xc, const float* __restrict__ xn,
                                const float* __restrict__ wT,
                                float* __restrict__ gi, float* __restrict__ gf,
                                float* __restrict__ gz, float* __restrict__ go) {
    int idx = blockIdx.x * blockDim.x + threadIdx.x;
    int c = idx & 127;
    size_t bs = (size_t)(idx >> 7);
    int h = c >> 5, e = c & 31;
    const float* base = wT + h * 1024 + e;
    const float* xcb = xc + bs * DD + h * 32;
    const float* xnb = xn + bs * DD + h * 32;
    float a1 = 0, a2 = 0, a3 = 0, a4 = 0;
    #pragma unroll
    for (int d = 0; d < 32; d++) {
        float xv = xcb[d], nv = xnb[d];
        int o = d * 32;
        a1 += xv * base[o];
        a2 += xv * base[4096 + o];
        a3 += nv * base[8192 + o];
        a4 += nv * base[12288 + o];
    }
    gi[idx] = a1; gf[idx] = a2; gz[idx] = a3; go[idx] = a4;
}

#define SCAN_SMEM (4 * 32 * 128 * sizeof(float))
__global__ void __launch_bounds__(512, 1)
slstm_scan_kernel(const float* __restrict__ gi, const float* __restrict__ gf,
                  const float* __restrict__ gz, const float* __restrict__ go,
                  const float* __restrict__ rw, const float* __restrict__ bias,
                  float* __restrict__ y) {
    int b = blockIdx.x;
    int tid = threadIdx.x;
    extern __shared__ float srw[];
    __shared__ float hs[128], cs[128], ns[128], ms[128];
    __shared__ float sb[512], srec[512];
    for (int i = tid; i < 16384; i += 512) srw[i] = rw[i];
    sb[tid] = bias[tid];
    if (tid < 128) { hs[tid] = 0.f; cs[tid] = 0.f; ns[tid] = 0.f; ms[tid] = 0.f; }
    __syncthreads();
    int h = tid >> 7, j = tid & 127;
    const float* wp = srw + h * 4096 + j;
    const float* hb = hs + h * 32;
    for (int t = 0; t < SS; t++) {
        float r0 = 0, r1 = 0;
        #pragma unroll
        for (int d = 0; d < 32; d += 2) {
            r0 += hb[d]     * wp[d * 128];
            r1 += hb[d + 1] * wp[(d + 1) * 128];
        }
        srec[tid] = r0 + r1;
        __syncthreads();
        if (tid < 128) {
            size_t gidx = ((size_t)b * SS + t) * DD + tid;
            int hh = tid >> 5, d = tid & 31;
            int rb = hh * 128;
            float ix = gi[gidx] + srec[rb + d]      + sb[rb + d];
            float fx = gf[gidx] + srec[rb + 32 + d] + sb[rb + 32 + d];
            float zx = gz[gidx] + srec[rb + 64 + d] + sb[rb + 64 + d];
            float ox = go[gidx] + srec[rb + 96 + d] + sb[rb + 96 + d];
            float ls  = fminf(fx, 0.f) - log1pf(__expf(-fabsf(fx)));
            float lpm = ms[tid] + ls;
            float mn  = fmaxf(ix, lpm);
            float ig  = __expf(ix - mn);
            float fg  = __expf(lpm - mn);
            float cn  = fg * cs[tid] + ig * tanhf(zx);
            float nn  = fg * ns[tid] + ig;
            float hn  = cn / (nn * (1.0f + __expf(-ox)));
            cs[tid] = cn; ns[tid] = nn; ms[tid] = mn; hs[tid] = hn;
            y[gidx] = hn;
        }
        __syncthreads();
    }
}

// ---------------- tf32 GEMM: 128x128 tile ----------------
template<int AOP>
__global__ void __launch_bounds__(256)
gemm_tf32_kernel(const float* __restrict__ A, const float* __restrict__ A2,
                 const float* __restrict__ A3, const float* __restrict__ Askip,
                 const float* __restrict__ W, float* __restrict__ C,
                 int N, int Kd, int accum) {
    __shared__ __align__(16) uint32_t sA[2][128][20];
    __shared__ __align__(16) uint32_t sB[2][128][20];
    const int bm = blockIdx.y * 128, bn = blockIdx.x * 128;
    const int tid = threadIdx.x;
    const int wid = tid >> 5, lane = tid & 31;
    const int wm = wid & 1, wn = wid >> 1;
    const int g = lane >> 2, t = lane & 3;
    const int arow = tid >> 1;
    const int acg = (tid & 1) << 3;
    float acc[4][4][4] = {};

    auto loadA4 = [&](int gr, int gk) -> float4 {
        float4 r;
        if (AOP == 0) {
            r = *(const float4*)(A + (size_t)gr * Kd + gk);
        } else if (AOP == 1) {
            float4 gg = *(const float4*)(A + (size_t)gr * 512 + gk);
            float4 u  = *(const float4*)(A + (size_t)gr * 512 + 256 + gk);
            r.x = 0.5f * gg.x * (1.0f + erff(gg.x * 0.70710678f)) * u.x;
            r.y = 0.5f * gg.y * (1.0f + erff(gg.y * 0.70710678f)) * u.y;
            r.z = 0.5f * gg.z * (1.0f + erff(gg.z * 0.70710678f)) * u.z;
            r.w = 0.5f * gg.w * (1.0f + erff(gg.w * 0.70710678f)) * u.w;
        } else {
            float4 hv = *(const float4*)(A  + (size_t)gr * 256 + gk);
            float4 xv = *(const float4*)(A2 + (size_t)gr * 256 + gk);
            float4 sk = *(const float4*)(Askip + gk);
            float4 zv = *(const float4*)(A3 + (size_t)gr * 512 + 256 + gk);
            r.x = (hv.x + sk.x * xv.x) * (zv.x / (1.0f + __expf(-zv.x)));
            r.y = (hv.y + sk.y * xv.y) * (zv.y / (1.0f + __expf(-zv.y)));
            r.z = (hv.z + sk.z * xv.z) * (zv.z / (1.0f + __expf(-zv.z)));
            r.w = (hv.w + sk.w * xv.w) * (zv.w / (1.0f + __expf(-zv.w)));
        }
        return r;
    };
    auto cvt4 = [&](float4 f) -> uint4 {
        return make_uint4(f2tf32(f.x), f2tf32(f.y), f2tf32(f.z), f2tf32(f.w));
    };
    auto compute = [&](int bf) {
        #pragma unroll
        for (int ks = 0; ks < 2; ks++) {
            int kb = ks * 8;
            uint32_t af[4][4], bfr[4][2];
            #pragma unroll
            for (int mi = 0; mi < 4; mi++) {
                int r0 = wm * 64 + mi * 16 + g;
                af[mi][0] = sA[bf][r0][kb + t];
                af[mi][1] = sA[bf][r0 + 8][kb + t];
                af[mi][2] = sA[bf][r0][kb + t + 4];
                af[mi][3] = sA[bf][r0 + 8][kb + t + 4];
            }
            #pragma unroll
            for (int ni = 0; ni < 4; ni++) {
                int c0 = wn * 32 + ni * 8 + g;
                bfr[ni][0] = sB[bf][c0][kb + t];
                bfr[ni][1] = sB[bf][c0][kb + t + 4];
            }
            #pragma unroll
            for (int mi = 0; mi < 4; mi++)
                #pragma unroll
                for (int ni = 0; ni < 4; ni++)
                    mma_tf32(acc[mi][ni], af[mi], bfr[ni]);
        }
    };

    {
        float4 alo = loadA4(bm + arow, acg);
        float4 ahi = loadA4(bm + arow, acg + 4);
        float4 wlo = *(const float4*)(W + (size_t)(bn + arow) * Kd + acg);
        float4 whi = *(const float4*)(W + (size_t)(bn + arow) * Kd + acg + 4);
        *(uint4*)&sA[0][arow][acg]     = cvt4(alo);
        *(uint4*)&sA[0][arow][acg + 4] = cvt4(ahi);
        *(uint4*)&sB[0][arow][acg]     = cvt4(wlo);
        *(uint4*)&sB[0][arow][acg + 4] = cvt4(whi);
    }
    __syncthreads();

    int buf = 0;
    for (int k0 = 16; k0 < Kd; k0 += 16) {
        float4 alo = loadA4(bm + arow, k0 + acg);
        float4 ahi = loadA4(bm + arow, k0 + acg + 4);
        float4 wlo = *(const float4*)(W + (size_t)(bn + arow) * Kd + k0 + acg);
        float4 whi = *(const float4*)(W + (size_t)(bn + arow) * Kd + k0 + acg + 4);
        compute(buf);
        int nb = buf ^ 1;
        *(uint4*)&sA[nb][arow][acg]     = cvt4(alo);
        *(uint4*)&sA[nb][arow][acg + 4] = cvt4(ahi);
        *(uint4*)&sB[nb][arow][acg]     = cvt4(wlo);
        *(uint4*)&sB[nb][arow][acg + 4] = cvt4(whi);
        __syncthreads();
        buf = nb;
    }
    compute(buf);

    #pragma unroll
    for (int mi = 0; mi < 4; mi++) {
        #pragma unroll
        for (int ni = 0; ni < 4; ni++) {
            int grow = bm + wm * 64 + mi * 16 + g;
            int gcol = bn + wn * 32 + ni * 8 + t * 2;
            float* p0 = C + (size_t)grow * N + gcol;
            float* p1 = C + (size_t)(grow + 8) * N + gcol;
            if (accum) {
                float2 x0 = *(float2*)p0, x1 = *(float2*)p1;
                x0.x += acc[mi][ni][0]; x0.y += acc[mi][ni][1];
                x1.x += acc[mi][ni][2]; x1.y += acc[mi][ni][3];
                *(float2*)p0 = x0; *(float2*)p1 = x1;
            } else {
                *(float2*)p0 = make_float2(acc[mi][ni][0], acc[mi][ni][1]);
                *(float2*)p1 = make_float2(acc[mi][ni][2], acc[mi][ni][3]);
            }
        }
    }
}

extern "C" void kernel_launch(void* const* d_in, const int* in_sizes, int n_in,
                              void* d_out, int out_size) {
    const int*   x          = (const int*)  d_in[0];
    const float* emb        = (const float*)d_in[1];
    const float* m_ln_w     = (const float*)d_in[2];
    const float* m_up_w     = (const float*)d_in[3];
    const float* m_conv_w   = (const float*)d_in[4];
    const float* m_conv_b   = (const float*)d_in[5];
    const float* m_q_w      = (const float*)d_in[6];
    const float* m_k_w      = (const float*)d_in[7];
    const float* m_v_w      = (const float*)d_in[8];
    const float* m_ig_w     = (const float*)d_in[9];
    const float* m_ig_b     = (const float*)d_in[10];
    const float* m_fg_w     = (const float*)d_in[11];
    const float* m_fg_b     = (const float*)d_in[12];
    const float* m_on_w     = (const float*)d_in[13];
    const float* m_skip     = (const float*)d_in[14];
    const float* m_down_w   = (const float*)d_in[15];
    const float* s_ln1_w    = (const float*)d_in[16];
    const float* s_conv_w   = (const float*)d_in[17];
    const float* s_conv_b   = (const float*)d_in[18];
    const float* s_ig_w     = (const float*)d_in[19];
    const float* s_fg_w     = (const float*)d_in[20];
    const float* s_zg_w     = (const float*)d_in[21];
    const float* s_og_w     = (const float*)d_in[22];
    const float* s_rec_w    = (const float*)d_in[23];
    const float* s_bias     = (const float*)d_in[24];
    const float* s_gn_w     = (const float*)d_in[25];
    const float* s_ln2_w    = (const float*)d_in[26];
    const float* s_ff_up_w  = (const float*)d_in[27];
    const float* s_ff_down_w= (const float*)d_in[28];
    const float* post_norm_w= (const float*)d_in[29];
    float* out = (float*)d_out;

    float *h_, *xn_, *big_, *xca_, *q_, *k_, *v_, *ht_;
    float *gi_, *gf_, *gz_, *go_, *y_, *ip_, *fp_, *slf_, *ek_, *pmx_, *wT_;
    cudaGetSymbolAddress((void**)&h_,   g_h);
    cudaGetSymbolAddress((void**)&xn_,  g_xn);
    cudaGetSymbolAddress((void**)&big_, g_big);
    cudaGetSymbolAddress((void**)&xca_, g_xca);
    cudaGetSymbolAddress((void**)&q_,   g_q);
    cudaGetSymbolAddress((void**)&k_,   g_k);
    cudaGetSymbolAddress((void**)&v_,   g_v);
    cudaGetSymbolAddress((void**)&ht_,  g_ht);
    cudaGetSymbolAddress((void**)&gi_,  g_gi);
    cudaGetSymbolAddress((void**)&gf_,  g_gf);
    cudaGetSymbolAddress((void**)&gz_,  g_gz);
    cudaGetSymbolAddress((void**)&go_,  g_go);
    cudaGetSymbolAddress((void**)&y_,   g_y);
    cudaGetSymbolAddress((void**)&ip_,  g_ip);
    cudaGetSymbolAddress((void**)&fp_,  g_fp);
    cudaGetSymbolAddress((void**)&slf_, g_slf);
    cudaGetSymbolAddress((void**)&ek_,  g_ek);
    cudaGetSymbolAddress((void**)&pmx_, g_pmx);
    cudaGetSymbolAddress((void**)&wT_,  g_wT);

    cudaFuncSetAttribute(mlstm_attn_tc, cudaFuncAttributeMaxDynamicSharedMemorySize, ATTN_SMEM_B);
    cudaFuncSetAttribute(slstm_scan_kernel, cudaFuncAttributeMaxDynamicSharedMemorySize, (int)SCAN_SMEM);

    embed_ln_kernel<<<BS, 128>>>(x, emb, m_ln_w, h_, xn_);
    gemm_tf32_kernel<0><<<dim3(4, BS / 128), 256>>>(xn_, nullptr, nullptr, nullptr,
                                                    m_up_w, big_, 512, 128, 0);
    conv_silu_kernel<512, 256><<<BS * DIM / 256, 256>>>(big_, m_conv_w, m_conv_b, xca_);
    mlstm_qkv_kernel<<<BS / 8, 256>>>(xca_, big_, m_q_w, m_k_w, m_v_w, q_, k_, v_);
    mlstm_gates_mma<<<BS / 128, 256>>>(q_, k_, v_, m_ig_w, m_ig_b, m_fg_w, m_fg_b, ip_, fp_);
    mlstm_prefix_kernel<<<64, 256>>>(ip_, fp_, slf_, ek_, pmx_);
    mlstm_attn_tc<<<BB * NHH, 256, ATTN_SMEM_B>>>(q_, k_, v_, slf_, ek_, pmx_, m_on_w, ht_);
    gemm_tf32_kernel<2><<<dim3(1, BS / 128), 256>>>(ht_, xca_, big_, m_skip,
                                                    m_down_w, h_, 128, 256, 1);

    transpose_w_kernel<<<64, 256>>>(s_ig_w, s_fg_w, s_zg_w, s_og_w, wT_, 0);
    transpose_w_kernel<<<64, 256>>>(s_ig_w, s_fg_w, s_zg_w, s_og_w, wT_, 16384);

    for (int i = 0; i < 2; i++) {
        ln128_kernel<<<BS, 128>>>(h_, s_ln1_w + i * DD, xn_);
        conv_silu_kernel<128, 128><<<BS * DD / 256, 256>>>(xn_, s_conv_w + i * DD * 4,
                                                           s_conv_b + i * DD, xca_);
        slstm_bd_kernel<<<BS * DD / 256, 256>>>(xca_, xn_, wT_ + i * 16384,
                                                gi_, gf_, gz_, go_);
        slstm_scan_kernel<<<BB, 512, SCAN_SMEM>>>(gi_, gf_, gz_, go_,
            s_rec_w + i * 16384, s_bias + i * 512, y_);
        slstm_post_kernel<<<BS, 128>>>(y_, s_gn_w + i * DD, s_ln2_w + i * DD, h_, xn_);
        gemm_tf32_kernel<0><<<dim3(4, BS / 128), 256>>>(xn_, nullptr, nullptr, nullptr,
                                                        s_ff_up_w + i * 512 * 128, big_, 512, 128, 0);
        gemm_tf32_kernel<1><<<dim3(1, BS / 128), 256>>>(big_, nullptr, nullptr, nullptr,
                                                        s_ff_down_w + i * 128 * 256, h_, 128, 256, 1);
    }

    ln128_kernel<<<BS, 128>>>(h_, post_norm_w, out);
}

// round 14
// speedup vs baseline: 1.3340x; 1.0276x over previous
#include <cuda_runtime.h>
#include <cuda_bf16.h>
#include <math.h>
#include <stdint.h>

#define BB   128
#define SS   256
#define DD   128
#define DIM  256
#define NHH  4
#define BS   (BB*SS)

__device__ float g_h  [BS*DD];
__device__ float g_xn [BS*DD];
__device__ float g_big[BS*512];
__device__ float g_xca[BS*DIM];
__device__ float g_q  [BS*DIM];
__device__ float g_k  [BS*DIM];
__device__ float g_v  [BS*DIM];
__device__ float g_ht [BS*DIM];
__device__ float g_gi [BS*DD];
__device__ float g_gf [BS*DD];
__device__ float g_gz [BS*DD];
__device__ float g_go [BS*DD];
__device__ float g_y  [BS*DD];
__device__ float g_ip [BB*NHH*SS];
__device__ float g_fp [BB*NHH*SS];
__device__ float g_slf[BB*NHH*SS];
__device__ float g_ek [BB*NHH*SS];
__device__ float g_pmx[BB*NHH*SS];
__device__ float g_wT [2*4*4096];

// ---------------- precision helpers ----------------
__device__ __forceinline__ uint32_t f2tf32(float f) {
    uint32_t r;
    asm("cvt.rna.tf32.f32 %0, %1;" : "=r"(r) : "f"(f));
    return r;
}
__device__ __forceinline__ void mma_tf32(float* d, const uint32_t* a, const uint32_t* b) {
    asm volatile(
        "mma.sync.aligned.m16n8k8.row.col.f32.tf32.tf32.f32 "
        "{%0,%1,%2,%3}, {%4,%5,%6,%7}, {%8,%9}, {%0,%1,%2,%3};"
        : "+f"(d[0]), "+f"(d[1]), "+f"(d[2]), "+f"(d[3])
        : "r"(a[0]), "r"(a[1]), "r"(a[2]), "r"(a[3]), "r"(b[0]), "r"(b[1]));
}
// pack two floats -> bf16x2 word (lo = first arg, hi = second)
__device__ __forceinline__ uint32_t pkbf2(float lo, float hi) {
    uint32_t r;
    asm("cvt.rn.bf16x2.f32 %0, %1, %2;" : "=r"(r) : "f"(hi), "f"(lo));
    return r;
}
__device__ __forceinline__ void mma_bf16(float* d, const uint32_t* a, const uint32_t* b) {
    asm volatile(
        "mma.sync.aligned.m16n8k16.row.col.f32.bf16.bf16.f32 "
        "{%0,%1,%2,%3}, {%4,%5,%6,%7}, {%8,%9}, {%0,%1,%2,%3};"
        : "+f"(d[0]), "+f"(d[1]), "+f"(d[2]), "+f"(d[3])
        : "r"(a[0]), "r"(a[1]), "r"(a[2]), "r"(a[3]), "r"(b[0]), "r"(b[1]));
}

// ---------------- fused embedding + LayerNorm ----------------
__global__ void embed_ln_kernel(const int* __restrict__ x, const float* __restrict__ emb,
                                const float* __restrict__ w,
                                float* __restrict__ h, float* __restrict__ xn) {
    int row = blockIdx.x;
    int tid = threadIdx.x;  // 128
    __shared__ float r1[4], r2[4];
    float v = emb[x[row] * DD + tid];
    h[(size_t)row * DD + tid] = v;
    float s = v;
    #pragma unroll
    for (int o = 16; o; o >>= 1) s += __shfl_xor_sync(0xffffffffu, s, o);
    if ((tid & 31) == 0) r1[tid >> 5] = s;
    __syncthreads();
    float mu = (r1[0] + r1[1] + r1[2] + r1[3]) * (1.0f / DD);
    float d = v - mu;
    float sq = d * d;
    #pragma unroll
    for (int o = 16; o; o >>= 1) sq += __shfl_xor_sync(0xffffffffu, sq, o);
    if ((tid & 31) == 0) r2[tid >> 5] = sq;
    __syncthreads();
    float var = (r2[0] + r2[1] + r2[2] + r2[3]) * (1.0f / DD);
    xn[(size_t)row * DD + tid] = d * rsqrtf(var + 1e-5f) * w[tid];
}

__global__ void ln128_kernel(const float* __restrict__ x, const float* __restrict__ w,
                             float* __restrict__ out) {
    int row = blockIdx.x;
    int tid = threadIdx.x;  // 128
    __shared__ float r1[4], r2[4];
    float v = x[(size_t)row * DD + tid];
    float s = v;
    #pragma unroll
    for (int o = 16; o; o >>= 1) s += __shfl_xor_sync(0xffffffffu, s, o);
    if ((tid & 31) == 0) r1[tid >> 5] = s;
    __syncthreads();
    float mu = (r1[0] + r1[1] + r1[2] + r1[3]) * (1.0f / DD);
    float d = v - mu;
    float sq = d * d;
    #pragma unroll
    for (int o = 16; o; o >>= 1) sq += __shfl_xor_sync(0xffffffffu, sq, o);
    if ((tid & 31) == 0) r2[tid >> 5] = sq;
    __syncthreads();
    float var = (r2[0] + r2[1] + r2[2] + r2[3]) * (1.0f / DD);
    out[(size_t)row * DD + tid] = d * rsqrtf(var + 1e-5f) * w[tid];
}

// fused: groupln(y, gs=32)*gnw + h -> h ; then LN(h)*ln2w -> xn
__global__ void slstm_post_kernel(const float* __restrict__ y, const float* __restrict__ gnw,
                                  const float* __restrict__ ln2w,
                                  float* __restrict__ h, float* __restrict__ xn) {
    int row = blockIdx.x;
    int tid = threadIdx.x;  // 128
    __shared__ float r1[4], r2[4];
    float yv = y[(size_t)row * DD + tid];
    float s = yv;
    #pragma unroll
    for (int o = 16; o; o >>= 1) s += __shfl_xor_sync(0xffffffffu, s, o);
    float mu = s * (1.0f / 32.0f);
    float e = yv - mu;
    float sq = e * e;
    #pragma unroll
    for (int o = 16; o; o >>= 1) sq += __shfl_xor_sync(0xffffffffu, sq, o);
    float rr = rsqrtf(sq * (1.0f / 32.0f) + 1e-5f);
    float hv = e * rr * gnw[tid] + h[(size_t)row * DD + tid];
    h[(size_t)row * DD + tid] = hv;
    float s2 = hv;
    #pragma unroll
    for (int o = 16; o; o >>= 1) s2 += __shfl_xor_sync(0xffffffffu, s2, o);
    if ((tid & 31) == 0) r1[tid >> 5] = s2;
    __syncthreads();
    float mu2 = (r1[0] + r1[1] + r1[2] + r1[3]) * (1.0f / DD);
    float d2 = hv - mu2;
    float q2 = d2 * d2;
    #pragma unroll
    for (int o = 16; o; o >>= 1) q2 += __shfl_xor_sync(0xffffffffu, q2, o);
    if ((tid & 31) == 0) r2[tid >> 5] = q2;
    __syncthreads();
    float var2 = (r2[0] + r2[1] + r2[2] + r2[3]) * (1.0f / DD);
    xn[(size_t)row * DD + tid] = d2 * rsqrtf(var2 + 1e-5f) * ln2w[tid];
}

template<int LDX, int C>
__global__ void conv_silu_kernel(const float* __restrict__ x,
                                 const float* __restrict__ w, const float* __restrict__ bias,
                                 float* __restrict__ out) {
    int idx = blockIdx.x * blockDim.x + threadIdx.x;
    int c = idx & (C - 1);
    int s = (idx / C) & (SS - 1);
    int b = idx / (C * SS);
    const float* xp = x + ((size_t)b * SS) * LDX + c;
    float acc = bias[c];
    #pragma unroll
    for (int j = 0; j < 4; j++) {
        int sj = s + j - 3;
        if (sj >= 0) acc += xp[(size_t)sj * LDX] * w[c * 4 + j];
    }
    out[idx] = acc / (1.0f + __expf(-acc));
}

__global__ void transpose_w_kernel(const float* __restrict__ ig, const float* __restrict__ fg,
                                   const float* __restrict__ zg, const float* __restrict__ og,
                                   float* __restrict__ wT, int off) {
    int idx = off + blockIdx.x * blockDim.x + threadIdx.x;
    int layer = idx >> 14;
    int arr = (idx >> 12) & 3;
    int r = idx & 4095;
    int h = r >> 10, e = (r >> 5) & 31, d = r & 31;
    const float* src = (arr == 0) ? ig : (arr == 1) ? fg : (arr == 2) ? zg : og;
    wT[layer * 16384 + arr * 4096 + h * 1024 + d * 32 + e] =
        src[layer * 4096 + h * 1024 + e * 32 + d];
}

// ---------------- mLSTM qkv: weights in regs, 8 rows per thread ----------------
__global__ void __launch_bounds__(256)
mlstm_qkv_kernel(const float* __restrict__ xca, const float* __restrict__ big,
                 const float* __restrict__ qw, const float* __restrict__ kw,
                 const float* __restrict__ vw,
                 float* __restrict__ q, float* __restrict__ k, float* __restrict__ v) {
    int tid = threadIdx.x;
    int blk = tid >> 3, e = tid & 7;
    size_t bs0 = (size_t)blockIdx.x * 8;
    const float* qp = qw + blk * 64 + e * 8;
    const float* kp = kw + blk * 64 + e * 8;
    const float* vp = vw + blk * 64 + e * 8;
    float4 q0 = *(const float4*)qp, q1 = *(const float4*)(qp + 4);
    float4 k0 = *(const float4*)kp, k1 = *(const float4*)(kp + 4);
    float4 v0 = *(const float4*)vp, v1 = *(const float4*)(vp + 4);
    #pragma unroll
    for (int i = 0; i < 8; i++) {
        size_t bs = bs0 + i;
        const float* xc = xca + bs * DIM + blk * 8;
        const float* xi = big + bs * 512 + blk * 8;
        float4 x0 = *(const float4*)xc, x1 = *(const float4*)(xc + 4);
        float4 i0 = *(const float4*)xi, i1 = *(const float4*)(xi + 4);
        float aq = x0.x*q0.x + x0.y*q0.y + x0.z*q0.z + x0.w*q0.w
                 + x1.x*q1.x + x1.y*q1.y + x1.z*q1.z + x1.w*q1.w;
        float ak = x0.x*k0.x + x0.y*k0.y + x0.z*k0.z + x0.w*k0.w
                 + x1.x*k1.x + x1.y*k1.y + x1.z*k1.z + x1.w*k1.w;
        float av = i0.x*v0.x + i0.y*v0.y + i0.z*v0.z + i0.w*v0.w
                 + i1.x*v1.x + i1.y*v1.y + i1.z*v1.z + i1.w*v1.w;
        q[bs * DIM + tid] = aq;
        k[bs * DIM + tid] = ak;
        v[bs * DIM + tid] = av;
    }
}

// ---------------- mLSTM gates via tf32 mma ----------------
__global__ void __launch_bounds__(256)
mlstm_gates_mma(const float* __restrict__ q, const float* __restrict__ k,
                const float* __restrict__ v,
                const float* __restrict__ igw, const float* __restrict__ igb,
                const float* __restrict__ fgw, const float* __restrict__ fgb,
                float* __restrict__ ip, float* __restrict__ fp) {
    __shared__ uint32_t sW[8][768];
    int tid = threadIdx.x;
    for (int i = tid; i < 8 * 768; i += 256) {
        int n = i / 768, kk = i - n * 768;
        float wv = (n < 4) ? igw[n * 768 + kk] : fgw[(n - 4) * 768 + kk];
        sW[n][kk] = f2tf32(wv);
    }
    __syncthreads();
    int w = tid >> 5, lane = tid & 31;
    int g = lane >> 2, t = lane & 3;
    int base = blockIdx.x * 128 + w * 16;
    float acc[4] = {0.f, 0.f, 0.f, 0.f};
    const float* arrs[3] = {q, k, v};
    #pragma unroll
    for (int seg = 0; seg < 3; seg++) {
        const float* r0 = arrs[seg] + (size_t)(base + g) * 256;
        const float* r1 = arrs[seg] + (size_t)(base + g + 8) * 256;
        const uint32_t* wrow = &sW[g][seg * 256];
        for (int ks = 0; ks < 32; ks++) {
            int k0 = ks * 8;
            uint32_t a[4], b[2];
            a[0] = f2tf32(r0[k0 + t]);
            a[1] = f2tf32(r1[k0 + t]);
            a[2] = f2tf32(r0[k0 + t + 4]);
            a[3] = f2tf32(r1[k0 + t + 4]);
            b[0] = wrow[k0 + t];
            b[1] = wrow[k0 + t + 4];
            mma_tf32(acc, a, b);
        }
    }
    int rows[2] = {base + g, base + g + 8};
    int ns[2] = {2 * t, 2 * t + 1};
    #pragma unroll
    for (int ri = 0; ri < 2; ri++) {
        #pragma unroll
        for (int ci = 0; ci < 2; ci++) {
            float val = acc[ri * 2 + ci];
            int row = rows[ri], n = ns[ci];
            int b_ = row >> 8, s = row & 255;
            if (n < 4) ip[(b_ * NHH + n) * SS + s] = val + igb[n];
            else       fp[(b_ * NHH + (n - 4)) * SS + s] = val + fgb[n - 4];
        }
    }
}

// ---------------- parallel gate prefix ----------------
__global__ void mlstm_prefix_kernel(const float* __restrict__ ip, const float* __restrict__ fp,
                                    float* __restrict__ slf, float* __restrict__ ek,
                                    float* __restrict__ pmx) {
    int warp = (blockIdx.x * blockDim.x + threadIdx.x) >> 5;
    int lane = threadIdx.x & 31;
    size_t base = (size_t)warp * SS + lane * 8;
    float fv[8], iv[8];
    {
        float4 a = *(const float4*)(fp + base);
        float4 b = *(const float4*)(fp + base + 4);
        fv[0]=a.x; fv[1]=a.y; fv[2]=a.z; fv[3]=a.w; fv[4]=b.x; fv[5]=b.y; fv[6]=b.z; fv[7]=b.w;
        float4 c = *(const float4*)(ip + base);
        float4 d = *(const float4*)(ip + base + 4);
        iv[0]=c.x; iv[1]=c.y; iv[2]=c.z; iv[3]=c.w; iv[4]=d.x; iv[5]=d.y; iv[6]=d.z; iv[7]=d.w;
    }
    float ls[8], lsum = 0.f;
    #pragma unroll
    for (int t = 0; t < 8; t++) {
        float f = fv[t];
        ls[t] = fminf(f, 0.f) - log1pf(expf(-fabsf(f)));
        lsum += ls[t];
    }
    float run = lsum;
    #pragma unroll
    for (int o = 1; o < 32; o <<= 1) {
        float vv = __shfl_up_sync(0xffffffffu, run, o);
        if (lane >= o) run += vv;
    }
    float c = run - lsum;
    float sl[8], ev[8], lmax = -1e30f;
    #pragma unroll
    for (int t = 0; t < 8; t++) {
        c += ls[t];
        sl[t] = c;
        ev[t] = iv[t] - c;
        lmax = fmaxf(lmax, ev[t]);
    }
    float rmax = lmax;
    #pragma unroll
    for (int o = 1; o < 32; o <<= 1) {
        float vv = __shfl_up_sync(0xffffffffu, rmax, o);
        if (lane >= o) rmax = fmaxf(rmax, vv);
    }
    float exclmax = __shfl_up_sync(0xffffffffu, rmax, 1);
    if (lane == 0) exclmax = -1e30f;
    float pm[8];
    float cm = exclmax;
    #pragma unroll
    for (int t = 0; t < 8; t++) {
        cm = fmaxf(cm, ev[t]);
        pm[t] = cm;
    }
    *(float4*)(slf + base)     = make_float4(sl[0], sl[1], sl[2], sl[3]);
    *(float4*)(slf + base + 4) = make_float4(sl[4], sl[5], sl[6], sl[7]);
    *(float4*)(ek + base)      = make_float4(ev[0], ev[1], ev[2], ev[3]);
    *(float4*)(ek + base + 4)  = make_float4(ev[4], ev[5], ev[6], ev[7]);
    *(float4*)(pmx + base)     = make_float4(pm[0], pm[1], pm[2], pm[3]);
    *(float4*)(pmx + base + 4) = make_float4(pm[4], pm[5], pm[6], pm[7]);
}

// ---------------- tensor-core attention + fused head group-LN epilogue ----------------
#define ATTN_SMEM_U32 (17408 + 16640 + 8*32*68 + 768)
#define ATTN_SMEM_B   (ATTN_SMEM_U32 * 4)
__global__ void __launch_bounds__(256, 1)
mlstm_attn_tc(const float* __restrict__ q, const float* __restrict__ k,
              const float* __restrict__ v,
              const float* __restrict__ slf, const float* __restrict__ ek,
              const float* __restrict__ pmx, const float* __restrict__ onw,
              float* __restrict__ out) {
    extern __shared__ uint32_t su[];
    uint32_t* sK  = su;                    // [256][68]
    uint32_t* sVT = su + 17408;            // [64][260]
    uint32_t* sC  = su + 17408 + 16640;    // [8][32][68]
    float* s_ce = (float*)(su + 17408 + 16640 + 8*32*68);
    float* s_px = s_ce + 256;
    float* s_lf = s_px + 256;

    int bh = blockIdx.x, b = bh >> 2, h = bh & 3;
    int tid = threadIdx.x, w = tid >> 5, lane = tid & 31;
    int g = lane >> 2, t = lane & 3;

    const float* kb = k + ((size_t)b * SS) * DIM + h * 64;
    const float* vb = v + ((size_t)b * SS) * DIM + h * 64;
    for (int e = tid; e < SS * 64; e += 256) {
        int kk = e >> 6, d = e & 63;
        sK [kk * 68 + d]  = f2tf32(kb[(size_t)kk * DIM + d]);
        sVT[d * 260 + kk] = f2tf32(vb[(size_t)kk * DIM + d]);
    }
    for (int i = tid; i < SS; i += 256) {
        s_ce[i] = __expf(fminf(ek[(size_t)bh * SS + i], 80.f));
        s_px[i] = pmx[(size_t)bh * SS + i];
        s_lf[i] = slf[(size_t)bh * SS + i];
    }

    int r = (w < 4) ? 2 * w : 15 - 2 * w;
    int rb = r * 32;
    const float* qb = q + ((size_t)(b * SS + rb)) * DIM + h * 64;
    uint32_t qa[2][8][4];
    #pragma unroll
    for (int mi = 0; mi < 2; mi++)
        #pragma unroll
        for (int dc = 0; dc < 8; dc++) {
            qa[mi][dc][0] = f2tf32(qb[(size_t)(mi*16+g)   * DIM + dc*8 + t]);
            qa[mi][dc][1] = f2tf32(qb[(size_t)(mi*16+g+8) * DIM + dc*8 + t]);
            qa[mi][dc][2] = f2tf32(qb[(size_t)(mi*16+g)   * DIM + dc*8 + t + 4]);
            qa[mi][dc][3] = f2tf32(qb[(size_t)(mi*16+g+8) * DIM + dc*8 + t + 4]);
        }
    __syncthreads();

    float qf[2][2];
    #pragma unroll
    for (int mi = 0; mi < 2; mi++)
        #pragma unroll
        for (int ri = 0; ri < 2; ri++)
            qf[mi][ri] = __expf(fminf(-s_px[rb + mi*16 + g + 8*ri], 80.f));

    float Oacc[2][8][4] = {};
    float rs[2][2] = {};
    uint32_t* myC = sC + w * (32 * 68);
    int ntile = (r >> 1) + 1;

    for (int tt = 0; tt < ntile; tt++) {
        int kc = tt * 64;
        float Sacc[2][8][4] = {};
        #pragma unroll
        for (int dc = 0; dc < 8; dc++) {
            uint32_t bf[8][2];
            #pragma unroll
            for (int ni = 0; ni < 8; ni++) {
                int krow = kc + ni * 8 + g;
                bf[ni][0] = sK[krow * 68 + dc * 8 + t];
                bf[ni][1] = sK[krow * 68 + dc * 8 + t + 4];
            }
            #pragma unroll
            for (int mi = 0; mi < 2; mi++)
                #pragma unroll
                for (int ni = 0; ni < 8; ni++)
                    mma_tf32(Sacc[mi][ni], qa[mi][dc], bf[ni]);
        }
        #pragma unroll
        for (int ni = 0; ni < 8; ni++) {
            int c0 = kc + ni * 8 + 2 * t;
            float ce0 = 0.125f * s_ce[c0], ce1 = 0.125f * s_ce[c0 + 1];
            #pragma unroll
            for (int mi = 0; mi < 2; mi++) {
                #pragma unroll
                for (int ri = 0; ri < 2; ri++) {
                    int lrow = mi * 16 + g + 8 * ri;
                    int qrow = rb + lrow;
                    float f = qf[mi][ri];
                    float v0 = Sacc[mi][ni][ri * 2]     * ce0 * f;
                    float v1 = Sacc[mi][ni][ri * 2 + 1] * ce1 * f;
                    if (c0 > qrow) v0 = 0.f;
                    if (c0 + 1 > qrow) v1 = 0.f;
                    rs[mi][ri] += v0 + v1;
                    myC[lrow * 68 + ni * 8 + 2 * t]     = f2tf32(v0);
                    myC[lrow * 68 + ni * 8 + 2 * t + 1] = f2tf32(v1);
                }
            }
        }
        __syncwarp();
        #pragma unroll
        for (int kch = 0; kch < 8; kch++) {
            uint32_t af[2][4];
            #pragma unroll
            for (int mi = 0; mi < 2; mi++) {
                af[mi][0] = myC[(mi*16+g)   * 68 + kch*8 + t];
                af[mi][1] = myC[(mi*16+g+8) * 68 + kch*8 + t];
                af[mi][2] = myC[(mi*16+g)   * 68 + kch*8 + t + 4];
                af[mi][3] = myC[(mi*16+g+8) * 68 + kch*8 + t + 4];
            }
            uint32_t bf2[8][2];
            #pragma unroll
            for (int dn = 0; dn < 8; dn++) {
                int drow = dn * 8 + g;
                bf2[dn][0] = sVT[drow * 260 + kc + kch * 8 + t];
                bf2[dn][1] = sVT[drow * 260 + kc + kch * 8 + t + 4];
            }
            #pragma unroll
            for (int mi = 0; mi < 2; mi++)
                #pragma unroll
                for (int dn = 0; dn < 8; dn++)
                    mma_tf32(Oacc[mi][dn], af[mi], bf2[dn]);
        }
        __syncwarp();
    }

    #pragma unroll
    for (int mi = 0; mi < 2; mi++)
        #pragma unroll
        for (int ri = 0; ri < 2; ri++) {
            float s = rs[mi][ri];
            s += __shfl_xor_sync(0xffffffffu, s, 1);
            s += __shfl_xor_sync(0xffffffffu, s, 2);
            rs[mi][ri] = s;
        }
    float wv[8][2];
    #pragma unroll
    for (int dn = 0; dn < 8; dn++) {
        wv[dn][0] = onw[h * 64 + dn * 8 + 2 * t];
        wv[dn][1] = onw[h * 64 + dn * 8 + 2 * t + 1];
    }
    #pragma unroll
    for (int mi = 0; mi < 2; mi++) {
        #pragma unroll
        for (int ri = 0; ri < 2; ri++) {
            int qrow = rb + mi * 16 + g + 8 * ri;
            float maxd = s_lf[qrow] + s_px[qrow];
            float inv = 1.0f / (fmaxf(fabsf(rs[mi][ri]), __expf(fminf(-maxd, 80.f))) + 1e-6f);
            float vals[8][2];
            float s = 0.f;
            #pragma unroll
            for (int dn = 0; dn < 8; dn++) {
                vals[dn][0] = Oacc[mi][dn][ri * 2]     * inv;
                vals[dn][1] = Oacc[mi][dn][ri * 2 + 1] * inv;
                s += vals[dn][0] + vals[dn][1];
            }
            s += __shfl_xor_sync(0xffffffffu, s, 1);
            s += __shfl_xor_sync(0xffffffffu, s, 2);
            float mu = s * (1.0f / 64.0f);
            float sq = 0.f;
            #pragma unroll
            for (int dn = 0; dn < 8; dn++) {
                float d0 = vals[dn][0] - mu, d1 = vals[dn][1] - mu;
                sq += d0 * d0 + d1 * d1;
            }
            sq += __shfl_xor_sync(0xffffffffu, sq, 1);
            sq += __shfl_xor_sync(0xffffffffu, sq, 2);
            float rr = rsqrtf(sq * (1.0f / 64.0f) + 1e-5f);
            float* ob = out + ((size_t)(b * SS + qrow)) * DIM + h * 64;
            #pragma unroll
            for (int dn = 0; dn < 8; dn++) {
                float2 o;
                o.x = (vals[dn][0] - mu) * rr * wv[dn][0];
                o.y = (vals[dn][1] - mu) * rr * wv[dn][1];
                *(float2*)(ob + dn * 8 + 2 * t) = o;
            }
        }
    }
}

// sLSTM block-diagonal gates
__global__ void slstm_bd_kernel(const float* __restrict__ xc, const float* __restrict__ xn,
                                const float* __restrict__ wT,
                                float* __restrict__ gi, float* __restrict__ gf,
                                float* __restrict__ gz, float* __restrict__ go) {
    int idx = blockIdx.x * blockDim.x + threadIdx.x;
    int c = idx & 127;
    size_t bs = (size_t)(idx >> 7);
    int h = c >> 5, e = c & 31;
    const float* base = wT + h * 1024 + e;
    const float* xcb = xc + bs * DD + h * 32;
    const float* xnb = xn + bs * DD + h * 32;
    float a1 = 0, a2 = 0, a3 = 0, a4 = 0;
    #pragma unroll
    for (int d = 0; d < 32; d++) {
        float xv = xcb[d], nv = xnb[d];
        int o = d * 32;
        a1 += xv * base[o];
        a2 += xv * base[4096 + o];
        a3 += nv * base[8192 + o];
        a4 += nv * base[12288 + o];
    }
    gi[idx] = a1; gf[idx] = a2; gz[idx] = a3; go[idx] = a4;
}

#define SCAN_SMEM (4 * 32 * 128 * sizeof(float))
__global__ void __launch_bounds__(512, 1)
slstm_scan_kernel(const float* __restrict__ gi, const float* __restrict__ gf,
                  const float* __restrict__ gz, const float* __restrict__ go,
                  const float* __restrict__ rw, const float* __restrict__ bias,
                  float* __restrict__ y) {
    int b = blockIdx.x;
    int tid = threadIdx.x;
    extern __shared__ float srw[];
    __shared__ float hs[128], cs[128], ns[128], ms[128];
    __shared__ float sb[512], srec[512];
    for (int i = tid; i < 16384; i += 512) srw[i] = rw[i];
    sb[tid] = bias[tid];
    if (tid < 128) { hs[tid] = 0.f; cs[tid] = 0.f; ns[tid] = 0.f; ms[tid] = 0.f; }
    __syncthreads();
    int h = tid >> 7, j = tid & 127;
    const float* wp = srw + h * 4096 + j;
    const float* hb = hs + h * 32;
    for (int t = 0; t < SS; t++) {
        float r0 = 0, r1 = 0;
        #pragma unroll
        for (int d = 0; d < 32; d += 2) {
            r0 += hb[d]     * wp[d * 128];
            r1 += hb[d + 1] * wp[(d + 1) * 128];
        }
        srec[tid] = r0 + r1;
        __syncthreads();
        if (tid < 128) {
            size_t gidx = ((size_t)b * SS + t) * DD + tid;
            int hh = tid >> 5, d = tid & 31;
            int rb = hh * 128;
            float ix = gi[gidx] + srec[rb + d]      + sb[rb + d];
            float fx = gf[gidx] + srec[rb + 32 + d] + sb[rb + 32 + d];
            float zx = gz[gidx] + srec[rb + 64 + d] + sb[rb + 64 + d];
            float ox = go[gidx] + srec[rb + 96 + d] + sb[rb + 96 + d];
            float ls  = fminf(fx, 0.f) - log1pf(__expf(-fabsf(fx)));
            float lpm = ms[tid] + ls;
            float mn  = fmaxf(ix, lpm);
            float ig  = __expf(ix - mn);
            float fg  = __expf(lpm - mn);
            float cn  = fg * cs[tid] + ig * tanhf(zx);
            float nn  = fg * ns[tid] + ig;
            float hn  = cn / (nn * (1.0f + __expf(-ox)));
            cs[tid] = cn; ns[tid] = nn; ms[tid] = mn; hs[tid] = hn;
            y[gidx] = hn;
        }
        __syncthreads();
    }
}

// ---------------- bf16 GEMM: 128x128 tile, m16n8k16, chunk=32k ----------------
template<int AOP>
__global__ void __launch_bounds__(256)
gemm_bf16_kernel(const float* __restrict__ A, const float* __restrict__ A2,
                 const float* __restrict__ A3, const float* __restrict__ Askip,
                 const float* __restrict__ W, float* __restrict__ C,
                 int N, int Kd, int accum) {
    __shared__ __align__(16) uint32_t sA[2][128][20];   // 16 bf16x2 words (=32 k) + pad
    __shared__ __align__(16) uint32_t sB[2][128][20];
    const int bm = blockIdx.y * 128, bn = blockIdx.x * 128;
    const int tid = threadIdx.x;
    const int wid = tid >> 5, lane = tid & 31;
    const int wm = wid & 1, wn = wid >> 1;
    const int g = lane >> 2, t = lane & 3;
    const int arow = tid >> 1;
    const int half = tid & 1;        // stages k-halves [0,16) or [16,32) of the chunk
    float acc[4][4][4] = {};

    auto loadA4 = [&](int gr, int gk) -> float4 {
        float4 r;
        if (AOP == 0) {
            r = *(const float4*)(A + (size_t)gr * Kd + gk);
        } else if (AOP == 1) {
            float4 gg = *(const float4*)(A + (size_t)gr * 512 + gk);
            float4 u  = *(const float4*)(A + (size_t)gr * 512 + 256 + gk);
            r.x = 0.5f * gg.x * (1.0f + erff(gg.x * 0.70710678f)) * u.x;
            r.y = 0.5f * gg.y * (1.0f + erff(gg.y * 0.70710678f)) * u.y;
            r.z = 0.5f * gg.z * (1.0f + erff(gg.z * 0.70710678f)) * u.z;
            r.w = 0.5f * gg.w * (1.0f + erff(gg.w * 0.70710678f)) * u.w;
        } else {
            float4 hv = *(const float4*)(A  + (size_t)gr * 256 + gk);
            float4 xv = *(const float4*)(A2 + (size_t)gr * 256 + gk);
            float4 sk = *(const float4*)(Askip + gk);
            float4 zv = *(const float4*)(A3 + (size_t)gr * 512 + 256 + gk);
            r.x = (hv.x + sk.x * xv.x) * (zv.x / (1.0f + __expf(-zv.x)));
            r.y = (hv.y + sk.y * xv.y) * (zv.y / (1.0f + __expf(-zv.y)));
            r.z = (hv.z + sk.z * xv.z) * (zv.z / (1.0f + __expf(-zv.z)));
            r.w = (hv.w + sk.w * xv.w) * (zv.w / (1.0f + __expf(-zv.w)));
        }
        return r;
    };

    // stage one 32-k chunk: this thread covers k = chunk*32 + half*16 + [0,16)
    auto stage = [&](int bf, int chunk) {
        int gk = chunk * 32 + half * 16;
        int wb = half * 8;
        float4 a0 = loadA4(bm + arow, gk);
        float4 a1 = loadA4(bm + arow, gk + 4);
        float4 a2 = loadA4(bm + arow, gk + 8);
        float4 a3 = loadA4(bm + arow, gk + 12);
        sA[bf][arow][wb+0] = pkbf2(a0.x, a0.y); sA[bf][arow][wb+1] = pkbf2(a0.z, a0.w);
        sA[bf][arow][wb+2] = pkbf2(a1.x, a1.y); sA[bf][arow][wb+3] = pkbf2(a1.z, a1.w);
        sA[bf][arow][wb+4] = pkbf2(a2.x, a2.y); sA[bf][arow][wb+5] = pkbf2(a2.z, a2.w);
        sA[bf][arow][wb+6] = pkbf2(a3.x, a3.y); sA[bf][arow][wb+7] = pkbf2(a3.z, a3.w);
        const float* wr = W + (size_t)(bn + arow) * Kd + gk;
        float4 b0 = *(const float4*)wr;
        float4 b1 = *(const float4*)(wr + 4);
        float4 b2 = *(const float4*)(wr + 8);
        float4 b3 = *(const float4*)(wr + 12);
        sB[bf][arow][wb+0] = pkbf2(b0.x, b0.y); sB[bf][arow][wb+1] = pkbf2(b0.z, b0.w);
        sB[bf][arow][wb+2] = pkbf2(b1.x, b1.y); sB[bf][arow][wb+3] = pkbf2(b1.z, b1.w);
        sB[bf][arow][wb+4] = pkbf2(b2.x, b2.y); sB[bf][arow][wb+5] = pkbf2(b2.z, b2.w);
        sB[bf][arow][wb+6] = pkbf2(b3.x, b3.y); sB[bf][arow][wb+7] = pkbf2(b3.z, b3.w);
    };

    auto compute = [&](int bf) {
        #pragma unroll
        for (int ks = 0; ks < 2; ks++) {       // each kstep = 16 k = 8 words
            int kb = ks * 8;
            uint32_t af[4][4], bfr[4][2];
            #pragma unroll
            for (int mi = 0; mi < 4; mi++) {
                int r0 = wm * 64 + mi * 16 + g;
                af[mi][0] = sA[bf][r0][kb + t];
                af[mi][1] = sA[bf][r0 + 8][kb + t];
                af[mi][2] = sA[bf][r0][kb + t + 4];
                af[mi][3] = sA[bf][r0 + 8][kb + t + 4];
            }
            #pragma unroll
            for (int ni = 0; ni < 4; ni++) {
                int c0 = wn * 32 + ni * 8 + g;
                bfr[ni][0] = sB[bf][c0][kb + t];
                bfr[ni][1] = sB[bf][c0][kb + t + 4];
            }
            #pragma unroll
            for (int mi = 0; mi < 4; mi++)
                #pragma unroll
                for (int ni = 0; ni < 4; ni++)
                    mma_bf16(acc[mi][ni], af[mi], bfr[ni]);
        }
    };

    stage(0, 0);
    __syncthreads();
    int buf = 0;
    int nchunks = Kd >> 5;
    for (int ch = 1; ch < nchunks; ch++) {
        int nb = buf ^ 1;
        stage(nb, ch);          // gmem loads overlap compute via scoreboarding
        compute(buf);
        __syncthreads();
        buf = nb;
    }
    compute(buf);

    #pragma unroll
    for (int mi = 0; mi < 4; mi++) {
        #pragma unroll
        for (int ni = 0; ni < 4; ni++) {
            int grow = bm + wm * 64 + mi * 16 + g;
            int gcol = bn + wn * 32 + ni * 8 + t * 2;
            float* p0 = C + (size_t)grow * N + gcol;
            float* p1 = C + (size_t)(grow + 8) * N + gcol;
            if (accum) {
                float2 x0 = *(float2*)p0, x1 = *(float2*)p1;
                x0.x += acc[mi][ni][0]; x0.y += acc[mi][ni][1];
                x1.x += acc[mi][ni][2]; x1.y += acc[mi][ni][3];
                *(float2*)p0 = x0; *(float2*)p1 = x1;
            } else {
                *(float2*)p0 = make_float2(acc[mi][ni][0], acc[mi][ni][1]);
                *(float2*)p1 = make_float2(acc[mi][ni][2], acc[mi][ni][3]);
            }
        }
    }
}

extern "C" void kernel_launch(void* const* d_in, const int* in_sizes, int n_in,
                              void* d_out, int out_size) {
    const int*   x          = (const int*)  d_in[0];
    const float* emb        = (const float*)d_in[1];
    const float* m_ln_w     = (const float*)d_in[2];
    const float* m_up_w     = (const float*)d_in[3];
    const float* m_conv_w   = (const float*)d_in[4];
    const float* m_conv_b   = (const float*)d_in[5];
    const float* m_q_w      = (const float*)d_in[6];
    const float* m_k_w      = (const float*)d_in[7];
    const float* m_v_w      = (const float*)d_in[8];
    const float* m_ig_w     = (const float*)d_in[9];
    const float* m_ig_b     = (const float*)d_in[10];
    const float* m_fg_w     = (const float*)d_in[11];
    const float* m_fg_b     = (const float*)d_in[12];
    const float* m_on_w     = (const float*)d_in[13];
    const float* m_skip     = (const float*)d_in[14];
    const float* m_down_w   = (const float*)d_in[15];
    const float* s_ln1_w    = (const float*)d_in[16];
    const float* s_conv_w   = (const float*)d_in[17];
    const float* s_conv_b   = (const float*)d_in[18];
    const float* s_ig_w     = (const float*)d_in[19];
    const float* s_fg_w     = (const float*)d_in[20];
    const float* s_zg_w     = (const float*)d_in[21];
    const float* s_og_w     = (const float*)d_in[22];
    const float* s_rec_w    = (const float*)d_in[23];
    const float* s_bias     = (const float*)d_in[24];
    const float* s_gn_w     = (const float*)d_in[25];
    const float* s_ln2_w    = (const float*)d_in[26];
    const float* s_ff_up_w  = (const float*)d_in[27];
    const float* s_ff_down_w= (const float*)d_in[28];
    const float* post_norm_w= (const float*)d_in[29];
    float* out = (float*)d_out;

    float *h_, *xn_, *big_, *xca_, *q_, *k_, *v_, *ht_;
    float *gi_, *gf_, *gz_, *go_, *y_, *ip_, *fp_, *slf_, *ek_, *pmx_, *wT_;
    cudaGetSymbolAddress((void**)&h_,   g_h);
    cudaGetSymbolAddress((void**)&xn_,  g_xn);
    cudaGetSymbolAddress((void**)&big_, g_big);
    cudaGetSymbolAddress((void**)&xca_, g_xca);
    cudaGetSymbolAddress((void**)&q_,   g_q);
    cudaGetSymbolAddress((void**)&k_,   g_k);
    cudaGetSymbolAddress((void**)&v_,   g_v);
    cudaGetSymbolAddress((void**)&ht_,  g_ht);
    cudaGetSymbolAddress((void**)&gi_,  g_gi);
    cudaGetSymbolAddress((void**)&gf_,  g_gf);
    cudaGetSymbolAddress((void**)&gz_,  g_gz);
    cudaGetSymbolAddress((void**)&go_,  g_go);
    cudaGetSymbolAddress((void**)&y_,   g_y);
    cudaGetSymbolAddress((void**)&ip_,  g_ip);
    cudaGetSymbolAddress((void**)&fp_,  g_fp);
    cudaGetSymbolAddress((void**)&slf_, g_slf);
    cudaGetSymbolAddress((void**)&ek_,  g_ek);
    cudaGetSymbolAddress((void**)&pmx_, g_pmx);
    cudaGetSymbolAddress((void**)&wT_,  g_wT);

    cudaFuncSetAttribute(mlstm_attn_tc, cudaFuncAttributeMaxDynamicSharedMemorySize, ATTN_SMEM_B);
    cudaFuncSetAttribute(slstm_scan_kernel, cudaFuncAttributeMaxDynamicSharedMemorySize, (int)SCAN_SMEM);

    // slots 1-3: embed_ln + transposes — slot 4 = bf16 up-GEMM (ncu probe)
    embed_ln_kernel<<<BS, 128>>>(x, emb, m_ln_w, h_, xn_);
    transpose_w_kernel<<<64, 256>>>(s_ig_w, s_fg_w, s_zg_w, s_og_w, wT_, 0);
    transpose_w_kernel<<<64, 256>>>(s_ig_w, s_fg_w, s_zg_w, s_og_w, wT_, 16384);
    gemm_bf16_kernel<0><<<dim3(4, BS / 128), 256>>>(xn_, nullptr, nullptr, nullptr,
                                                    m_up_w, big_, 512, 128, 0);
    conv_silu_kernel<512, 256><<<BS * DIM / 256, 256>>>(big_, m_conv_w, m_conv_b, xca_);
    mlstm_qkv_kernel<<<BS / 8, 256>>>(xca_, big_, m_q_w, m_k_w, m_v_w, q_, k_, v_);
    mlstm_gates_mma<<<BS / 128, 256>>>(q_, k_, v_, m_ig_w, m_ig_b, m_fg_w, m_fg_b, ip_, fp_);
    mlstm_prefix_kernel<<<64, 256>>>(ip_, fp_, slf_, ek_, pmx_);
    mlstm_attn_tc<<<BB * NHH, 256, ATTN_SMEM_B>>>(q_, k_, v_, slf_, ek_, pmx_, m_on_w, ht_);
    gemm_bf16_kernel<2><<<dim3(1, BS / 128), 256>>>(ht_, xca_, big_, m_skip,
                                                    m_down_w, h_, 128, 256, 1);

    for (int i = 0; i < 2; i++) {
        ln128_kernel<<<BS, 128>>>(h_, s_ln1_w + i * DD, xn_);
        conv_silu_kernel<128, 128><<<BS * DD / 256, 256>>>(xn_, s_conv_w + i * DD * 4,
                                                           s_conv_b + i * DD, xca_);
        slstm_bd_kernel<<<BS * DD / 256, 256>>>(xca_, xn_, wT_ + i * 16384,
                                                gi_, gf_, gz_, go_);
        slstm_scan_kernel<<<BB, 512, SCAN_SMEM>>>(gi_, gf_, gz_, go_,
            s_rec_w + i * 16384, s_bias + i * 512, y_);
        slstm_post_kernel<<<BS, 128>>>(y_, s_gn_w + i * DD, s_ln2_w + i * DD, h_, xn_);
        gemm_bf16_kernel<0><<<dim3(4, BS / 128), 256>>>(xn_, nullptr, nullptr, nullptr,
                                                        s_ff_up_w + i * 512 * 128, big_, 512, 128, 0);
        gemm_bf16_kernel<1><<<dim3(1, BS / 128), 256>>>(big_, nullptr, nullptr, nullptr,
                                                        s_ff_down_w + i * 128 * 256, h_, 128, 256, 1);
    }

    ln128_kernel<<<BS, 128>>>(h_, post_norm_w, out);
}

// round 15
// speedup vs baseline: 1.5531x; 1.1643x over previous
#include <cuda_runtime.h>
#include <cuda_bf16.h>
#include <math.h>
#include <stdint.h>

#define BB   128
#define SS   256
#define DD   128
#define DIM  256
#define NHH  4
#define BS   (BB*SS)

__device__ float g_h  [BS*DD];
__device__ float g_xn [BS*DD];
__device__ float g_big[BS*512];
__device__ float g_xca[BS*DIM];
__device__ float g_q  [BS*DIM];
__device__ float g_k  [BS*DIM];
__device__ float g_v  [BS*DIM];
__device__ float g_ht [BS*DIM];
__device__ float g_gi [BS*DD];
__device__ float g_gf [BS*DD];
__device__ float g_gz [BS*DD];
__device__ float g_go [BS*DD];
__device__ float g_y  [BS*DD];
__device__ float g_ip [BB*NHH*SS];
__device__ float g_fp [BB*NHH*SS];
__device__ float g_slf[BB*NHH*SS];
__device__ float g_ek [BB*NHH*SS];
__device__ float g_pmx[BB*NHH*SS];
__device__ float g_wT [2*4*4096];

// ---------------- precision helpers ----------------
__device__ __forceinline__ uint32_t f2tf32(float f) {
    uint32_t r;
    asm("cvt.rna.tf32.f32 %0, %1;" : "=r"(r) : "f"(f));
    return r;
}
__device__ __forceinline__ void mma_tf32(float* d, const uint32_t* a, const uint32_t* b) {
    asm volatile(
        "mma.sync.aligned.m16n8k8.row.col.f32.tf32.tf32.f32 "
        "{%0,%1,%2,%3}, {%4,%5,%6,%7}, {%8,%9}, {%0,%1,%2,%3};"
        : "+f"(d[0]), "+f"(d[1]), "+f"(d[2]), "+f"(d[3])
        : "r"(a[0]), "r"(a[1]), "r"(a[2]), "r"(a[3]), "r"(b[0]), "r"(b[1]));
}
__device__ __forceinline__ uint32_t pkbf2(float lo, float hi) {
    uint32_t r;
    asm("cvt.rn.bf16x2.f32 %0, %1, %2;" : "=r"(r) : "f"(hi), "f"(lo));
    return r;
}
__device__ __forceinline__ void mma_bf16(float* d, const uint32_t* a, const uint32_t* b) {
    asm volatile(
        "mma.sync.aligned.m16n8k16.row.col.f32.bf16.bf16.f32 "
        "{%0,%1,%2,%3}, {%4,%5,%6,%7}, {%8,%9}, {%0,%1,%2,%3};"
        : "+f"(d[0]), "+f"(d[1]), "+f"(d[2]), "+f"(d[3])
        : "r"(a[0]), "r"(a[1]), "r"(a[2]), "r"(a[3]), "r"(b[0]), "r"(b[1]));
}

// ---------------- fused embedding + LayerNorm ----------------
__global__ void embed_ln_kernel(const int* __restrict__ x, const float* __restrict__ emb,
                                const float* __restrict__ w,
                                float* __restrict__ h, float* __restrict__ xn) {
    int row = blockIdx.x;
    int tid = threadIdx.x;  // 128
    __shared__ float r1[4], r2[4];
    float v = emb[x[row] * DD + tid];
    h[(size_t)row * DD + tid] = v;
    float s = v;
    #pragma unroll
    for (int o = 16; o; o >>= 1) s += __shfl_xor_sync(0xffffffffu, s, o);
    if ((tid & 31) == 0) r1[tid >> 5] = s;
    __syncthreads();
    float mu = (r1[0] + r1[1] + r1[2] + r1[3]) * (1.0f / DD);
    float d = v - mu;
    float sq = d * d;
    #pragma unroll
    for (int o = 16; o; o >>= 1) sq += __shfl_xor_sync(0xffffffffu, sq, o);
    if ((tid & 31) == 0) r2[tid >> 5] = sq;
    __syncthreads();
    float var = (r2[0] + r2[1] + r2[2] + r2[3]) * (1.0f / DD);
    xn[(size_t)row * DD + tid] = d * rsqrtf(var + 1e-5f) * w[tid];
}

__global__ void ln128_kernel(const float* __restrict__ x, const float* __restrict__ w,
                             float* __restrict__ out) {
    int row = blockIdx.x;
    int tid = threadIdx.x;  // 128
    __shared__ float r1[4], r2[4];
    float v = x[(size_t)row * DD + tid];
    float s = v;
    #pragma unroll
    for (int o = 16; o; o >>= 1) s += __shfl_xor_sync(0xffffffffu, s, o);
    if ((tid & 31) == 0) r1[tid >> 5] = s;
    __syncthreads();
    float mu = (r1[0] + r1[1] + r1[2] + r1[3]) * (1.0f / DD);
    float d = v - mu;
    float sq = d * d;
    #pragma unroll
    for (int o = 16; o; o >>= 1) sq += __shfl_xor_sync(0xffffffffu, sq, o);
    if ((tid & 31) == 0) r2[tid >> 5] = sq;
    __syncthreads();
    float var = (r2[0] + r2[1] + r2[2] + r2[3]) * (1.0f / DD);
    out[(size_t)row * DD + tid] = d * rsqrtf(var + 1e-5f) * w[tid];
}

// fused: groupln(y, gs=32)*gnw + h -> h ; then LN(h)*ln2w -> xn
__global__ void slstm_post_kernel(const float* __restrict__ y, const float* __restrict__ gnw,
                                  const float* __restrict__ ln2w,
                                  float* __restrict__ h, float* __restrict__ xn) {
    int row = blockIdx.x;
    int tid = threadIdx.x;  // 128
    __shared__ float r1[4], r2[4];
    float yv = y[(size_t)row * DD + tid];
    float s = yv;
    #pragma unroll
    for (int o = 16; o; o >>= 1) s += __shfl_xor_sync(0xffffffffu, s, o);
    float mu = s * (1.0f / 32.0f);
    float e = yv - mu;
    float sq = e * e;
    #pragma unroll
    for (int o = 16; o; o >>= 1) sq += __shfl_xor_sync(0xffffffffu, sq, o);
    float rr = rsqrtf(sq * (1.0f / 32.0f) + 1e-5f);
    float hv = e * rr * gnw[tid] + h[(size_t)row * DD + tid];
    h[(size_t)row * DD + tid] = hv;
    float s2 = hv;
    #pragma unroll
    for (int o = 16; o; o >>= 1) s2 += __shfl_xor_sync(0xffffffffu, s2, o);
    if ((tid & 31) == 0) r1[tid >> 5] = s2;
    __syncthreads();
    float mu2 = (r1[0] + r1[1] + r1[2] + r1[3]) * (1.0f / DD);
    float d2 = hv - mu2;
    float q2 = d2 * d2;
    #pragma unroll
    for (int o = 16; o; o >>= 1) q2 += __shfl_xor_sync(0xffffffffu, q2, o);
    if ((tid & 31) == 0) r2[tid >> 5] = q2;
    __syncthreads();
    float var2 = (r2[0] + r2[1] + r2[2] + r2[3]) * (1.0f / DD);
    xn[(size_t)row * DD + tid] = d2 * rsqrtf(var2 + 1e-5f) * ln2w[tid];
}

// float4 conv: one thread = 4 consecutive channels
template<int LDX, int C>
__global__ void conv_silu4_kernel(const float* __restrict__ x,
                                  const float* __restrict__ w, const float* __restrict__ bias,
                                  float* __restrict__ out) {
    int idx = blockIdx.x * blockDim.x + threadIdx.x;     // BS*C/4
    constexpr int NC = C / 4;
    int c4 = (idx & (NC - 1)) * 4;
    int s = (idx / NC) & (SS - 1);
    int b = idx / (NC * SS);
    const float* xp = x + ((size_t)b * SS) * LDX + c4;
    float4 acc = *(const float4*)(bias + c4);
    #pragma unroll
    for (int j = 0; j < 4; j++) {
        int sj = s + j - 3;
        if (sj >= 0) {
            float4 xv = *(const float4*)(xp + (size_t)sj * LDX);
            acc.x += xv.x * w[(c4 + 0) * 4 + j];
            acc.y += xv.y * w[(c4 + 1) * 4 + j];
            acc.z += xv.z * w[(c4 + 2) * 4 + j];
            acc.w += xv.w * w[(c4 + 3) * 4 + j];
        }
    }
    float4 o;
    o.x = acc.x / (1.0f + __expf(-acc.x));
    o.y = acc.y / (1.0f + __expf(-acc.y));
    o.z = acc.z / (1.0f + __expf(-acc.z));
    o.w = acc.w / (1.0f + __expf(-acc.w));
    *(float4*)(out + ((size_t)b * SS + s) * C + c4) = o;
}

__global__ void transpose_w_kernel(const float* __restrict__ ig, const float* __restrict__ fg,
                                   const float* __restrict__ zg, const float* __restrict__ og,
                                   float* __restrict__ wT, int off) {
    int idx = off + blockIdx.x * blockDim.x + threadIdx.x;
    int layer = idx >> 14;
    int arr = (idx >> 12) & 3;
    int r = idx & 4095;
    int h = r >> 10, e = (r >> 5) & 31, d = r & 31;
    const float* src = (arr == 0) ? ig : (arr == 1) ? fg : (arr == 2) ? zg : og;
    wT[layer * 16384 + arr * 4096 + h * 1024 + d * 32 + e] =
        src[layer * 4096 + h * 1024 + e * 32 + d];
}

// ---------------- mLSTM qkv: weights in regs, 8 rows per thread ----------------
__global__ void __launch_bounds__(256)
mlstm_qkv_kernel(const float* __restrict__ xca, const float* __restrict__ big,
                 const float* __restrict__ qw, const float* __restrict__ kw,
                 const float* __restrict__ vw,
                 float* __restrict__ q, float* __restrict__ k, float* __restrict__ v) {
    int tid = threadIdx.x;
    int blk = tid >> 3, e = tid & 7;
    size_t bs0 = (size_t)blockIdx.x * 8;
    const float* qp = qw + blk * 64 + e * 8;
    const float* kp = kw + blk * 64 + e * 8;
    const float* vp = vw + blk * 64 + e * 8;
    float4 q0 = *(const float4*)qp, q1 = *(const float4*)(qp + 4);
    float4 k0 = *(const float4*)kp, k1 = *(const float4*)(kp + 4);
    float4 v0 = *(const float4*)vp, v1 = *(const float4*)(vp + 4);
    #pragma unroll
    for (int i = 0; i < 8; i++) {
        size_t bs = bs0 + i;
        const float* xc = xca + bs * DIM + blk * 8;
        const float* xi = big + bs * 512 + blk * 8;
        float4 x0 = *(const float4*)xc, x1 = *(const float4*)(xc + 4);
        float4 i0 = *(const float4*)xi, i1 = *(const float4*)(xi + 4);
        float aq = x0.x*q0.x + x0.y*q0.y + x0.z*q0.z + x0.w*q0.w
                 + x1.x*q1.x + x1.y*q1.y + x1.z*q1.z + x1.w*q1.w;
        float ak = x0.x*k0.x + x0.y*k0.y + x0.z*k0.z + x0.w*k0.w
                 + x1.x*k1.x + x1.y*k1.y + x1.z*k1.z + x1.w*k1.w;
        float av = i0.x*v0.x + i0.y*v0.y + i0.z*v0.z + i0.w*v0.w
                 + i1.x*v1.x + i1.y*v1.y + i1.z*v1.z + i1.w*v1.w;
        q[bs * DIM + tid] = aq;
        k[bs * DIM + tid] = ak;
        v[bs * DIM + tid] = av;
    }
}

// ---------------- mLSTM gates via tf32 mma ----------------
__global__ void __launch_bounds__(256)
mlstm_gates_mma(const float* __restrict__ q, const float* __restrict__ k,
                const float* __restrict__ v,
                const float* __restrict__ igw, const float* __restrict__ igb,
                const float* __restrict__ fgw, const float* __restrict__ fgb,
                float* __restrict__ ip, float* __restrict__ fp) {
    __shared__ uint32_t sW[8][768];
    int tid = threadIdx.x;
    for (int i = tid; i < 8 * 768; i += 256) {
        int n = i / 768, kk = i - n * 768;
        float wv = (n < 4) ? igw[n * 768 + kk] : fgw[(n - 4) * 768 + kk];
        sW[n][kk] = f2tf32(wv);
    }
    __syncthreads();
    int w = tid >> 5, lane = tid & 31;
    int g = lane >> 2, t = lane & 3;
    int base = blockIdx.x * 128 + w * 16;
    float acc[4] = {0.f, 0.f, 0.f, 0.f};
    const float* arrs[3] = {q, k, v};
    #pragma unroll
    for (int seg = 0; seg < 3; seg++) {
        const float* r0 = arrs[seg] + (size_t)(base + g) * 256;
        const float* r1 = arrs[seg] + (size_t)(base + g + 8) * 256;
        const uint32_t* wrow = &sW[g][seg * 256];
        for (int ks = 0; ks < 32; ks++) {
            int k0 = ks * 8;
            uint32_t a[4], b[2];
            a[0] = f2tf32(r0[k0 + t]);
            a[1] = f2tf32(r1[k0 + t]);
            a[2] = f2tf32(r0[k0 + t + 4]);
            a[3] = f2tf32(r1[k0 + t + 4]);
            b[0] = wrow[k0 + t];
            b[1] = wrow[k0 + t + 4];
            mma_tf32(acc, a, b);
        }
    }
    int rows[2] = {base + g, base + g + 8};
    int ns[2] = {2 * t, 2 * t + 1};
    #pragma unroll
    for (int ri = 0; ri < 2; ri++) {
        #pragma unroll
        for (int ci = 0; ci < 2; ci++) {
            float val = acc[ri * 2 + ci];
            int row = rows[ri], n = ns[ci];
            int b_ = row >> 8, s = row & 255;
            if (n < 4) ip[(b_ * NHH + n) * SS + s] = val + igb[n];
            else       fp[(b_ * NHH + (n - 4)) * SS + s] = val + fgb[n - 4];
        }
    }
}

// ---------------- parallel gate prefix ----------------
__global__ void mlstm_prefix_kernel(const float* __restrict__ ip, const float* __restrict__ fp,
                                    float* __restrict__ slf, float* __restrict__ ek,
                                    float* __restrict__ pmx) {
    int warp = (blockIdx.x * blockDim.x + threadIdx.x) >> 5;
    int lane = threadIdx.x & 31;
    size_t base = (size_t)warp * SS + lane * 8;
    float fv[8], iv[8];
    {
        float4 a = *(const float4*)(fp + base);
        float4 b = *(const float4*)(fp + base + 4);
        fv[0]=a.x; fv[1]=a.y; fv[2]=a.z; fv[3]=a.w; fv[4]=b.x; fv[5]=b.y; fv[6]=b.z; fv[7]=b.w;
        float4 c = *(const float4*)(ip + base);
        float4 d = *(const float4*)(ip + base + 4);
        iv[0]=c.x; iv[1]=c.y; iv[2]=c.z; iv[3]=c.w; iv[4]=d.x; iv[5]=d.y; iv[6]=d.z; iv[7]=d.w;
    }
    float ls[8], lsum = 0.f;
    #pragma unroll
    for (int t = 0; t < 8; t++) {
        float f = fv[t];
        ls[t] = fminf(f, 0.f) - log1pf(expf(-fabsf(f)));
        lsum += ls[t];
    }
    float run = lsum;
    #pragma unroll
    for (int o = 1; o < 32; o <<= 1) {
        float vv = __shfl_up_sync(0xffffffffu, run, o);
        if (lane >= o) run += vv;
    }
    float c = run - lsum;
    float sl[8], ev[8], lmax = -1e30f;
    #pragma unroll
    for (int t = 0; t < 8; t++) {
        c += ls[t];
        sl[t] = c;
        ev[t] = iv[t] - c;
        lmax = fmaxf(lmax, ev[t]);
    }
    float rmax = lmax;
    #pragma unroll
    for (int o = 1; o < 32; o <<= 1) {
        float vv = __shfl_up_sync(0xffffffffu, rmax, o);
        if (lane >= o) rmax = fmaxf(rmax, vv);
    }
    float exclmax = __shfl_up_sync(0xffffffffu, rmax, 1);
    if (lane == 0) exclmax = -1e30f;
    float pm[8];
    float cm = exclmax;
    #pragma unroll
    for (int t = 0; t < 8; t++) {
        cm = fmaxf(cm, ev[t]);
        pm[t] = cm;
    }
    *(float4*)(slf + base)     = make_float4(sl[0], sl[1], sl[2], sl[3]);
    *(float4*)(slf + base + 4) = make_float4(sl[4], sl[5], sl[6], sl[7]);
    *(float4*)(ek + base)      = make_float4(ev[0], ev[1], ev[2], ev[3]);
    *(float4*)(ek + base + 4)  = make_float4(ev[4], ev[5], ev[6], ev[7]);
    *(float4*)(pmx + base)     = make_float4(pm[0], pm[1], pm[2], pm[3]);
    *(float4*)(pmx + base + 4) = make_float4(pm[4], pm[5], pm[6], pm[7]);
}

// ---------------- tensor-core attention + fused head group-LN epilogue ----------------
#define ATTN_SMEM_U32 (17408 + 16640 + 8*32*68 + 768)
#define ATTN_SMEM_B   (ATTN_SMEM_U32 * 4)
__global__ void __launch_bounds__(256, 1)
mlstm_attn_tc(const float* __restrict__ q, const float* __restrict__ k,
              const float* __restrict__ v,
              const float* __restrict__ slf, const float* __restrict__ ek,
              const float* __restrict__ pmx, const float* __restrict__ onw,
              float* __restrict__ out) {
    extern __shared__ uint32_t su[];
    uint32_t* sK  = su;                    // [256][68]
    uint32_t* sVT = su + 17408;            // [64][260]
    uint32_t* sC  = su + 17408 + 16640;    // [8][32][68]
    float* s_ce = (float*)(su + 17408 + 16640 + 8*32*68);
    float* s_px = s_ce + 256;
    float* s_lf = s_px + 256;

    int bh = blockIdx.x, b = bh >> 2, h = bh & 3;
    int tid = threadIdx.x, w = tid >> 5, lane = tid & 31;
    int g = lane >> 2, t = lane & 3;

    const float* kb = k + ((size_t)b * SS) * DIM + h * 64;
    const float* vb = v + ((size_t)b * SS) * DIM + h * 64;
    for (int e = tid; e < SS * 64; e += 256) {
        int kk = e >> 6, d = e & 63;
        sK [kk * 68 + d]  = f2tf32(kb[(size_t)kk * DIM + d]);
        sVT[d * 260 + kk] = f2tf32(vb[(size_t)kk * DIM + d]);
    }
    for (int i = tid; i < SS; i += 256) {
        s_ce[i] = __expf(fminf(ek[(size_t)bh * SS + i], 80.f));
        s_px[i] = pmx[(size_t)bh * SS + i];
        s_lf[i] = slf[(size_t)bh * SS + i];
    }

    int r = (w < 4) ? 2 * w : 15 - 2 * w;
    int rb = r * 32;
    const float* qb = q + ((size_t)(b * SS + rb)) * DIM + h * 64;
    uint32_t qa[2][8][4];
    #pragma unroll
    for (int mi = 0; mi < 2; mi++)
        #pragma unroll
        for (int dc = 0; dc < 8; dc++) {
            qa[mi][dc][0] = f2tf32(qb[(size_t)(mi*16+g)   * DIM + dc*8 + t]);
            qa[mi][dc][1] = f2tf32(qb[(size_t)(mi*16+g+8) * DIM + dc*8 + t]);
            qa[mi][dc][2] = f2tf32(qb[(size_t)(mi*16+g)   * DIM + dc*8 + t + 4]);
            qa[mi][dc][3] = f2tf32(qb[(size_t)(mi*16+g+8) * DIM + dc*8 + t + 4]);
        }
    __syncthreads();

    float qf[2][2];
    #pragma unroll
    for (int mi = 0; mi < 2; mi++)
        #pragma unroll
        for (int ri = 0; ri < 2; ri++)
            qf[mi][ri] = __expf(fminf(-s_px[rb + mi*16 + g + 8*ri], 80.f));

    float Oacc[2][8][4] = {};
    float rs[2][2] = {};
    uint32_t* myC = sC + w * (32 * 68);
    int ntile = (r >> 1) + 1;

    for (int tt = 0; tt < ntile; tt++) {
        int kc = tt * 64;
        float Sacc[2][8][4] = {};
        #pragma unroll
        for (int dc = 0; dc < 8; dc++) {
            uint32_t bf[8][2];
            #pragma unroll
            for (int ni = 0; ni < 8; ni++) {
                int krow = kc + ni * 8 + g;
                bf[ni][0] = sK[krow * 68 + dc * 8 + t];
                bf[ni][1] = sK[krow * 68 + dc * 8 + t + 4];
            }
            #pragma unroll
            for (int mi = 0; mi < 2; mi++)
                #pragma unroll
                for (int ni = 0; ni < 8; ni++)
                    mma_tf32(Sacc[mi][ni], qa[mi][dc], bf[ni]);
        }
        #pragma unroll
        for (int ni = 0; ni < 8; ni++) {
            int c0 = kc + ni * 8 + 2 * t;
            float ce0 = 0.125f * s_ce[c0], ce1 = 0.125f * s_ce[c0 + 1];
            #pragma unroll
            for (int mi = 0; mi < 2; mi++) {
                #pragma unroll
                for (int ri = 0; ri < 2; ri++) {
                    int lrow = mi * 16 + g + 8 * ri;
                    int qrow = rb + lrow;
                    float f = qf[mi][ri];
                    float v0 = Sacc[mi][ni][ri * 2]     * ce0 * f;
                    float v1 = Sacc[mi][ni][ri * 2 + 1] * ce1 * f;
                    if (c0 > qrow) v0 = 0.f;
                    if (c0 + 1 > qrow) v1 = 0.f;
                    rs[mi][ri] += v0 + v1;
                    myC[lrow * 68 + ni * 8 + 2 * t]     = f2tf32(v0);
                    myC[lrow * 68 + ni * 8 + 2 * t + 1] = f2tf32(v1);
                }
            }
        }
        __syncwarp();
        #pragma unroll
        for (int kch = 0; kch < 8; kch++) {
            uint32_t af[2][4];
            #pragma unroll
            for (int mi = 0; mi < 2; mi++) {
                af[mi][0] = myC[(mi*16+g)   * 68 + kch*8 + t];
                af[mi][1] = myC[(mi*16+g+8) * 68 + kch*8 + t];
                af[mi][2] = myC[(mi*16+g)   * 68 + kch*8 + t + 4];
                af[mi][3] = myC[(mi*16+g+8) * 68 + kch*8 + t + 4];
            }
            uint32_t bf2[8][2];
            #pragma unroll
            for (int dn = 0; dn < 8; dn++) {
                int drow = dn * 8 + g;
                bf2[dn][0] = sVT[drow * 260 + kc + kch * 8 + t];
                bf2[dn][1] = sVT[drow * 260 + kc + kch * 8 + t + 4];
            }
            #pragma unroll
            for (int mi = 0; mi < 2; mi++)
                #pragma unroll
                for (int dn = 0; dn < 8; dn++)
                    mma_tf32(Oacc[mi][dn], af[mi], bf2[dn]);
        }
        __syncwarp();
    }

    #pragma unroll
    for (int mi = 0; mi < 2; mi++)
        #pragma unroll
        for (int ri = 0; ri < 2; ri++) {
            float s = rs[mi][ri];
            s += __shfl_xor_sync(0xffffffffu, s, 1);
            s += __shfl_xor_sync(0xffffffffu, s, 2);
            rs[mi][ri] = s;
        }
    float wv[8][2];
    #pragma unroll
    for (int dn = 0; dn < 8; dn++) {
        wv[dn][0] = onw[h * 64 + dn * 8 + 2 * t];
        wv[dn][1] = onw[h * 64 + dn * 8 + 2 * t + 1];
    }
    #pragma unroll
    for (int mi = 0; mi < 2; mi++) {
        #pragma unroll
        for (int ri = 0; ri < 2; ri++) {
            int qrow = rb + mi * 16 + g + 8 * ri;
            float maxd = s_lf[qrow] + s_px[qrow];
            float inv = 1.0f / (fmaxf(fabsf(rs[mi][ri]), __expf(fminf(-maxd, 80.f))) + 1e-6f);
            float vals[8][2];
            float s = 0.f;
            #pragma unroll
            for (int dn = 0; dn < 8; dn++) {
                vals[dn][0] = Oacc[mi][dn][ri * 2]     * inv;
                vals[dn][1] = Oacc[mi][dn][ri * 2 + 1] * inv;
                s += vals[dn][0] + vals[dn][1];
            }
            s += __shfl_xor_sync(0xffffffffu, s, 1);
            s += __shfl_xor_sync(0xffffffffu, s, 2);
            float mu = s * (1.0f / 64.0f);
            float sq = 0.f;
            #pragma unroll
            for (int dn = 0; dn < 8; dn++) {
                float d0 = vals[dn][0] - mu, d1 = vals[dn][1] - mu;
                sq += d0 * d0 + d1 * d1;
            }
            sq += __shfl_xor_sync(0xffffffffu, sq, 1);
            sq += __shfl_xor_sync(0xffffffffu, sq, 2);
            float rr = rsqrtf(sq * (1.0f / 64.0f) + 1e-5f);
            float* ob = out + ((size_t)(b * SS + qrow)) * DIM + h * 64;
            #pragma unroll
            for (int dn = 0; dn < 8; dn++) {
                float2 o;
                o.x = (vals[dn][0] - mu) * rr * wv[dn][0];
                o.y = (vals[dn][1] - mu) * rr * wv[dn][1];
                *(float2*)(ob + dn * 8 + 2 * t) = o;
            }
        }
    }
}

// sLSTM block-diagonal gates
__global__ void slstm_bd_kernel(const float* __restrict__ xc, const float* __restrict__ xn,
                                const float* __restrict__ wT,
                                float* __restrict__ gi, float* __restrict__ gf,
                                float* __restrict__ gz, float* __restrict__ go) {
    int idx = blockIdx.x * blockDim.x + threadIdx.x;
    int c = idx & 127;
    size_t bs = (size_t)(idx >> 7);
    int h = c >> 5, e = c & 31;
    const float* base = wT + h * 1024 + e;
    const float* xcb = xc + bs * DD + h * 32;
    const float* xnb = xn + bs * DD + h * 32;
    float a1 = 0, a2 = 0, a3 = 0, a4 = 0;
    #pragma unroll
    for (int d = 0; d < 32; d++) {
        float xv = xcb[d], nv = xnb[d];
        int o = d * 32;
        a1 += xv * base[o];
        a2 += xv * base[4096 + o];
        a3 += nv * base[8192 + o];
        a4 += nv * base[12288 + o];
    }
    gi[idx] = a1; gf[idx] = a2; gz[idx] = a3; go[idx] = a4;
}

// ---------------- register-resident warp-per-head sLSTM scan ----------------
// CTA = one batch, 128 threads; warp = head, lane = channel. Recurrent weights
// in registers, h broadcast via shfl; no smem, no barriers; next-step gates prefetched.
__global__ void __launch_bounds__(128, 1)
slstm_scan_warp(const float* __restrict__ gi, const float* __restrict__ gf,
                const float* __restrict__ gz, const float* __restrict__ go,
                const float* __restrict__ rw, const float* __restrict__ bias,
                float* __restrict__ y) {
    int b = blockIdx.x;
    int lane = threadIdx.x & 31, hh = threadIdx.x >> 5;
    float wi[32], wf[32], wz[32], wo[32];
    const float* wb = rw + hh * 4096 + lane;
    #pragma unroll
    for (int d = 0; d < 32; d++) {
        wi[d] = wb[d * 128];
        wf[d] = wb[d * 128 + 32];
        wz[d] = wb[d * 128 + 64];
        wo[d] = wb[d * 128 + 96];
    }
    float bi = bias[hh * 128 + lane];
    float bfv = bias[hh * 128 + 32 + lane];
    float bz = bias[hh * 128 + 64 + lane];
    float bo = bias[hh * 128 + 96 + lane];
    float hs = 0.f, cs = 0.f, ns = 0.f, ms = 0.f;
    size_t base = (size_t)b * SS * DD + hh * 32 + lane;
    float ngi = gi[base], ngf = gf[base], ngz = gz[base], ngo = go[base];
    for (int t = 0; t < SS; t++) {
        float ixt = ngi, fxt = ngf, zxt = ngz, oxt = ngo;
        if (t + 1 < SS) {
            size_t nb = base + (size_t)(t + 1) * DD;
            ngi = gi[nb]; ngf = gf[nb]; ngz = gz[nb]; ngo = go[nb];
        }
        float ri0 = 0, ri1 = 0, rf0 = 0, rf1 = 0, rz0 = 0, rz1 = 0, ro0 = 0, ro1 = 0;
        #pragma unroll
        for (int d = 0; d < 32; d += 2) {
            float h0 = __shfl_sync(0xffffffffu, hs, d);
            float h1 = __shfl_sync(0xffffffffu, hs, d + 1);
            ri0 += h0 * wi[d]; ri1 += h1 * wi[d + 1];
            rf0 += h0 * wf[d]; rf1 += h1 * wf[d + 1];
            rz0 += h0 * wz[d]; rz1 += h1 * wz[d + 1];
            ro0 += h0 * wo[d]; ro1 += h1 * wo[d + 1];
        }
        float ix = ixt + (ri0 + ri1) + bi;
        float fx = fxt + (rf0 + rf1) + bfv;
        float zx = zxt + (rz0 + rz1) + bz;
        float ox = oxt + (ro0 + ro1) + bo;
        float ls  = fminf(fx, 0.f) - log1pf(__expf(-fabsf(fx)));
        float lpm = ms + ls;
        float mn  = fmaxf(ix, lpm);
        float ig  = __expf(ix - mn);
        float fg  = __expf(lpm - mn);
        float cn  = fg * cs + ig * tanhf(zx);
        float nn  = fg * ns + ig;
        float hn  = cn / (nn * (1.0f + __expf(-ox)));
        cs = cn; ns = nn; ms = mn; hs = hn;
        y[base + (size_t)t * DD] = hn;
    }
}

// ---------------- bf16 GEMM: 128x128 tile, m16n8k16, chunk=32k ----------------
template<int AOP>
__global__ void __launch_bounds__(256)
gemm_bf16_kernel(const float* __restrict__ A, const float* __restrict__ A2,
                 const float* __restrict__ A3, const float* __restrict__ Askip,
                 const float* __restrict__ W, float* __restrict__ C,
                 int N, int Kd, int accum) {
    __shared__ __align__(16) uint32_t sA[2][128][20];
    __shared__ __align__(16) uint32_t sB[2][128][20];
    const int bm = blockIdx.y * 128, bn = blockIdx.x * 128;
    const int tid = threadIdx.x;
    const int wid = tid >> 5, lane = tid & 31;
    const int wm = wid & 1, wn = wid >> 1;
    const int g = lane >> 2, t = lane & 3;
    const int arow = tid >> 1;
    const int half = tid & 1;
    float acc[4][4][4] = {};

    auto loadA4 = [&](int gr, int gk) -> float4 {
        float4 r;
        if (AOP == 0) {
            r = *(const float4*)(A + (size_t)gr * Kd + gk);
        } else if (AOP == 1) {
            float4 gg = *(const float4*)(A + (size_t)gr * 512 + gk);
            float4 u  = *(const float4*)(A + (size_t)gr * 512 + 256 + gk);
            r.x = 0.5f * gg.x * (1.0f + erff(gg.x * 0.70710678f)) * u.x;
            r.y = 0.5f * gg.y * (1.0f + erff(gg.y * 0.70710678f)) * u.y;
            r.z = 0.5f * gg.z * (1.0f + erff(gg.z * 0.70710678f)) * u.z;
            r.w = 0.5f * gg.w * (1.0f + erff(gg.w * 0.70710678f)) * u.w;
        } else {
            float4 hv = *(const float4*)(A  + (size_t)gr * 256 + gk);
            float4 xv = *(const float4*)(A2 + (size_t)gr * 256 + gk);
            float4 sk = *(const float4*)(Askip + gk);
            float4 zv = *(const float4*)(A3 + (size_t)gr * 512 + 256 + gk);
            r.x = (hv.x + sk.x * xv.x) * (zv.x / (1.0f + __expf(-zv.x)));
            r.y = (hv.y + sk.y * xv.y) * (zv.y / (1.0f + __expf(-zv.y)));
            r.z = (hv.z + sk.z * xv.z) * (zv.z / (1.0f + __expf(-zv.z)));
            r.w = (hv.w + sk.w * xv.w) * (zv.w / (1.0f + __expf(-zv.w)));
        }
        return r;
    };

    auto stage = [&](int bf, int chunk) {
        int gk = chunk * 32 + half * 16;
        int wb = half * 8;
        float4 a0 = loadA4(bm + arow, gk);
        float4 a1 = loadA4(bm + arow, gk + 4);
        float4 a2 = loadA4(bm + arow, gk + 8);
        float4 a3 = loadA4(bm + arow, gk + 12);
        sA[bf][arow][wb+0] = pkbf2(a0.x, a0.y); sA[bf][arow][wb+1] = pkbf2(a0.z, a0.w);
        sA[bf][arow][wb+2] = pkbf2(a1.x, a1.y); sA[bf][arow][wb+3] = pkbf2(a1.z, a1.w);
        sA[bf][arow][wb+4] = pkbf2(a2.x, a2.y); sA[bf][arow][wb+5] = pkbf2(a2.z, a2.w);
        sA[bf][arow][wb+6] = pkbf2(a3.x, a3.y); sA[bf][arow][wb+7] = pkbf2(a3.z, a3.w);
        const float* wr = W + (size_t)(bn + arow) * Kd + gk;
        float4 b0 = *(const float4*)wr;
        float4 b1 = *(const float4*)(wr + 4);
        float4 b2 = *(const float4*)(wr + 8);
        float4 b3 = *(const float4*)(wr + 12);
        sB[bf][arow][wb+0] = pkbf2(b0.x, b0.y); sB[bf][arow][wb+1] = pkbf2(b0.z, b0.w);
        sB[bf][arow][wb+2] = pkbf2(b1.x, b1.y); sB[bf][arow][wb+3] = pkbf2(b1.z, b1.w);
        sB[bf][arow][wb+4] = pkbf2(b2.x, b2.y); sB[bf][arow][wb+5] = pkbf2(b2.z, b2.w);
        sB[bf][arow][wb+6] = pkbf2(b3.x, b3.y); sB[bf][arow][wb+7] = pkbf2(b3.z, b3.w);
    };

    auto compute = [&](int bf) {
        #pragma unroll
        for (int ks = 0; ks < 2; ks++) {
            int kb = ks * 8;
            uint32_t af[4][4], bfr[4][2];
            #pragma unroll
            for (int mi = 0; mi < 4; mi++) {
                int r0 = wm * 64 + mi * 16 + g;
                af[mi][0] = sA[bf][r0][kb + t];
                af[mi][1] = sA[bf][r0 + 8][kb + t];
                af[mi][2] = sA[bf][r0][kb + t + 4];
                af[mi][3] = sA[bf][r0 + 8][kb + t + 4];
            }
            #pragma unroll
            for (int ni = 0; ni < 4; ni++) {
                int c0 = wn * 32 + ni * 8 + g;
                bfr[ni][0] = sB[bf][c0][kb + t];
                bfr[ni][1] = sB[bf][c0][kb + t + 4];
            }
            #pragma unroll
            for (int mi = 0; mi < 4; mi++)
                #pragma unroll
                for (int ni = 0; ni < 4; ni++)
                    mma_bf16(acc[mi][ni], af[mi], bfr[ni]);
        }
    };

    stage(0, 0);
    __syncthreads();
    int buf = 0;
    int nchunks = Kd >> 5;
    for (int ch = 1; ch < nchunks; ch++) {
        int nb = buf ^ 1;
        stage(nb, ch);
        compute(buf);
        __syncthreads();
        buf = nb;
    }
    compute(buf);

    #pragma unroll
    for (int mi = 0; mi < 4; mi++) {
        #pragma unroll
        for (int ni = 0; ni < 4; ni++) {
            int grow = bm + wm * 64 + mi * 16 + g;
            int gcol = bn + wn * 32 + ni * 8 + t * 2;
            float* p0 = C + (size_t)grow * N + gcol;
            float* p1 = C + (size_t)(grow + 8) * N + gcol;
            if (accum) {
                float2 x0 = *(float2*)p0, x1 = *(float2*)p1;
                x0.x += acc[mi][ni][0]; x0.y += acc[mi][ni][1];
                x1.x += acc[mi][ni][2]; x1.y += acc[mi][ni][3];
                *(float2*)p0 = x0; *(float2*)p1 = x1;
            } else {
                *(float2*)p0 = make_float2(acc[mi][ni][0], acc[mi][ni][1]);
                *(float2*)p1 = make_float2(acc[mi][ni][2], acc[mi][ni][3]);
            }
        }
    }
}

extern "C" void kernel_launch(void* const* d_in, const int* in_sizes, int n_in,
                              void* d_out, int out_size) {
    const int*   x          = (const int*)  d_in[0];
    const float* emb        = (const float*)d_in[1];
    const float* m_ln_w     = (const float*)d_in[2];
    const float* m_up_w     = (const float*)d_in[3];
    const float* m_conv_w   = (const float*)d_in[4];
    const float* m_conv_b   = (const float*)d_in[5];
    const float* m_q_w      = (const float*)d_in[6];
    const float* m_k_w      = (const float*)d_in[7];
    const float* m_v_w      = (const float*)d_in[8];
    const float* m_ig_w     = (const float*)d_in[9];
    const float* m_ig_b     = (const float*)d_in[10];
    const float* m_fg_w     = (const float*)d_in[11];
    const float* m_fg_b     = (const float*)d_in[12];
    const float* m_on_w     = (const float*)d_in[13];
    const float* m_skip     = (const float*)d_in[14];
    const float* m_down_w   = (const float*)d_in[15];
    const float* s_ln1_w    = (const float*)d_in[16];
    const float* s_conv_w   = (const float*)d_in[17];
    const float* s_conv_b   = (const float*)d_in[18];
    const float* s_ig_w     = (const float*)d_in[19];
    const float* s_fg_w     = (const float*)d_in[20];
    const float* s_zg_w     = (const float*)d_in[21];
    const float* s_og_w     = (const float*)d_in[22];
    const float* s_rec_w    = (const float*)d_in[23];
    const float* s_bias     = (const float*)d_in[24];
    const float* s_gn_w     = (const float*)d_in[25];
    const float* s_ln2_w    = (const float*)d_in[26];
    const float* s_ff_up_w  = (const float*)d_in[27];
    const float* s_ff_down_w= (const float*)d_in[28];
    const float* post_norm_w= (const float*)d_in[29];
    float* out = (float*)d_out;

    float *h_, *xn_, *big_, *xca_, *q_, *k_, *v_, *ht_;
    float *gi_, *gf_, *gz_, *go_, *y_, *ip_, *fp_, *slf_, *ek_, *pmx_, *wT_;
    cudaGetSymbolAddress((void**)&h_,   g_h);
    cudaGetSymbolAddress((void**)&xn_,  g_xn);
    cudaGetSymbolAddress((void**)&big_, g_big);
    cudaGetSymbolAddress((void**)&xca_, g_xca);
    cudaGetSymbolAddress((void**)&q_,   g_q);
    cudaGetSymbolAddress((void**)&k_,   g_k);
    cudaGetSymbolAddress((void**)&v_,   g_v);
    cudaGetSymbolAddress((void**)&ht_,  g_ht);
    cudaGetSymbolAddress((void**)&gi_,  g_gi);
    cudaGetSymbolAddress((void**)&gf_,  g_gf);
    cudaGetSymbolAddress((void**)&gz_,  g_gz);
    cudaGetSymbolAddress((void**)&go_,  g_go);
    cudaGetSymbolAddress((void**)&y_,   g_y);
    cudaGetSymbolAddress((void**)&ip_,  g_ip);
    cudaGetSymbolAddress((void**)&fp_,  g_fp);
    cudaGetSymbolAddress((void**)&slf_, g_slf);
    cudaGetSymbolAddress((void**)&ek_,  g_ek);
    cudaGetSymbolAddress((void**)&pmx_, g_pmx);
    cudaGetSymbolAddress((void**)&wT_,  g_wT);

    cudaFuncSetAttribute(mlstm_attn_tc, cudaFuncAttributeMaxDynamicSharedMemorySize, ATTN_SMEM_B);

    // slots 1-3: embed_ln + transposes — slot 4 = bf16 up-GEMM (ncu probe)
    embed_ln_kernel<<<BS, 128>>>(x, emb, m_ln_w, h_, xn_);
    transpose_w_kernel<<<64, 256>>>(s_ig_w, s_fg_w, s_zg_w, s_og_w, wT_, 0);
    transpose_w_kernel<<<64, 256>>>(s_ig_w, s_fg_w, s_zg_w, s_og_w, wT_, 16384);
    gemm_bf16_kernel<0><<<dim3(4, BS / 128), 256>>>(xn_, nullptr, nullptr, nullptr,
                                                    m_up_w, big_, 512, 128, 0);
    conv_silu4_kernel<512, 256><<<BS * 64 / 256, 256>>>(big_, m_conv_w, m_conv_b, xca_);
    mlstm_qkv_kernel<<<BS / 8, 256>>>(xca_, big_, m_q_w, m_k_w, m_v_w, q_, k_, v_);
    mlstm_gates_mma<<<BS / 128, 256>>>(q_, k_, v_, m_ig_w, m_ig_b, m_fg_w, m_fg_b, ip_, fp_);
    mlstm_prefix_kernel<<<64, 256>>>(ip_, fp_, slf_, ek_, pmx_);
    mlstm_attn_tc<<<BB * NHH, 256, ATTN_SMEM_B>>>(q_, k_, v_, slf_, ek_, pmx_, m_on_w, ht_);
    gemm_bf16_kernel<2><<<dim3(1, BS / 128), 256>>>(ht_, xca_, big_, m_skip,
                                                    m_down_w, h_, 128, 256, 1);

    for (int i = 0; i < 2; i++) {
        ln128_kernel<<<BS, 128>>>(h_, s_ln1_w + i * DD, xn_);
        conv_silu4_kernel<128, 128><<<BS * 32 / 256, 256>>>(xn_, s_conv_w + i * DD * 4,
                                                            s_conv_b + i * DD, xca_);
        slstm_bd_kernel<<<BS * DD / 256, 256>>>(xca_, xn_, wT_ + i * 16384,
                                                gi_, gf_, gz_, go_);
        slstm_scan_warp<<<BB, 128>>>(gi_, gf_, gz_, go_,
            s_rec_w + i * 16384, s_bias + i * 512, y_);
        slstm_post_kernel<<<BS, 128>>>(y_, s_gn_w + i * DD, s_ln2_w + i * DD, h_, xn_);
        gemm_bf16_kernel<0><<<dim3(4, BS / 128), 256>>>(xn_, nullptr, nullptr, nullptr,
                                                        s_ff_up_w + i * 512 * 128, big_, 512, 128, 0);
        gemm_bf16_kernel<1><<<dim3(1, BS / 128), 256>>>(big_, nullptr, nullptr, nullptr,
                                                        s_ff_down_w + i * 128 * 256, h_, 128, 256, 1);
    }

    ln128_kernel<<<BS, 128>>>(h_, post_norm_w, out);
}

// round 17
// speedup vs baseline: 1.7542x; 1.1295x over previous
#include <cuda_runtime.h>
#include <cuda_bf16.h>
#include <math.h>
#include <stdint.h>

#define BB   128
#define SS   256
#define DD   128
#define DIM  256
#define NHH  4
#define BS   (BB*SS)

__device__ float g_h  [BS*DD];
__device__ float g_xn [BS*DD];
__device__ float g_big[BS*512];
__device__ float g_xca[BS*DIM];
__device__ float g_q  [BS*DIM];
__device__ float g_k  [BS*DIM];
__device__ float g_v  [BS*DIM];
__device__ float g_ht [BS*DIM];
__device__ float g_gi [BS*DD];
__device__ float g_gf [BS*DD];
__device__ float g_gz [BS*DD];
__device__ float g_go [BS*DD];
__device__ float g_y  [BS*DD];
__device__ float g_ip [BB*NHH*SS];
__device__ float g_fp [BB*NHH*SS];
__device__ float g_slf[BB*NHH*SS];
__device__ float g_ek [BB*NHH*SS];
__device__ float g_pmx[BB*NHH*SS];
__device__ float g_wT [2*4*4096];

// ---------------- precision helpers ----------------
__device__ __forceinline__ uint32_t f2tf32(float f) {
    uint32_t r;
    asm("cvt.rna.tf32.f32 %0, %1;" : "=r"(r) : "f"(f));
    return r;
}
__device__ __forceinline__ void mma_tf32(float* d, const uint32_t* a, const uint32_t* b) {
    asm volatile(
        "mma.sync.aligned.m16n8k8.row.col.f32.tf32.tf32.f32 "
        "{%0,%1,%2,%3}, {%4,%5,%6,%7}, {%8,%9}, {%0,%1,%2,%3};"
        : "+f"(d[0]), "+f"(d[1]), "+f"(d[2]), "+f"(d[3])
        : "r"(a[0]), "r"(a[1]), "r"(a[2]), "r"(a[3]), "r"(b[0]), "r"(b[1]));
}
__device__ __forceinline__ uint32_t pkbf2(float lo, float hi) {
    uint32_t r;
    asm("cvt.rn.bf16x2.f32 %0, %1, %2;" : "=r"(r) : "f"(hi), "f"(lo));
    return r;
}
__device__ __forceinline__ void mma_bf16(float* d, const uint32_t* a, const uint32_t* b) {
    asm volatile(
        "mma.sync.aligned.m16n8k16.row.col.f32.bf16.bf16.f32 "
        "{%0,%1,%2,%3}, {%4,%5,%6,%7}, {%8,%9}, {%0,%1,%2,%3};"
        : "+f"(d[0]), "+f"(d[1]), "+f"(d[2]), "+f"(d[3])
        : "r"(a[0]), "r"(a[1]), "r"(a[2]), "r"(a[3]), "r"(b[0]), "r"(b[1]));
}

// ---------------- fused embedding + LayerNorm ----------------
__global__ void embed_ln_kernel(const int* __restrict__ x, const float* __restrict__ emb,
                                const float* __restrict__ w,
                                float* __restrict__ h, float* __restrict__ xn) {
    int row = blockIdx.x;
    int tid = threadIdx.x;  // 128
    __shared__ float r1[4], r2[4];
    float v = emb[x[row] * DD + tid];
    h[(size_t)row * DD + tid] = v;
    float s = v;
    #pragma unroll
    for (int o = 16; o; o >>= 1) s += __shfl_xor_sync(0xffffffffu, s, o);
    if ((tid & 31) == 0) r1[tid >> 5] = s;
    __syncthreads();
    float mu = (r1[0] + r1[1] + r1[2] + r1[3]) * (1.0f / DD);
    float d = v - mu;
    float sq = d * d;
    #pragma unroll
    for (int o = 16; o; o >>= 1) sq += __shfl_xor_sync(0xffffffffu, sq, o);
    if ((tid & 31) == 0) r2[tid >> 5] = sq;
    __syncthreads();
    float var = (r2[0] + r2[1] + r2[2] + r2[3]) * (1.0f / DD);
    xn[(size_t)row * DD + tid] = d * rsqrtf(var + 1e-5f) * w[tid];
}

// fused: groupln(y, gs=32)*gnw + h -> h ; then LN(h)*ln2w -> xn
__global__ void slstm_post_kernel(const float* __restrict__ y, const float* __restrict__ gnw,
                                  const float* __restrict__ ln2w,
                                  float* __restrict__ h, float* __restrict__ xn) {
    int row = blockIdx.x;
    int tid = threadIdx.x;  // 128
    __shared__ float r1[4], r2[4];
    float yv = y[(size_t)row * DD + tid];
    float s = yv;
    #pragma unroll
    for (int o = 16; o; o >>= 1) s += __shfl_xor_sync(0xffffffffu, s, o);
    float mu = s * (1.0f / 32.0f);
    float e = yv - mu;
    float sq = e * e;
    #pragma unroll
    for (int o = 16; o; o >>= 1) sq += __shfl_xor_sync(0xffffffffu, sq, o);
    float rr = rsqrtf(sq * (1.0f / 32.0f) + 1e-5f);
    float hv = e * rr * gnw[tid] + h[(size_t)row * DD + tid];
    h[(size_t)row * DD + tid] = hv;
    float s2 = hv;
    #pragma unroll
    for (int o = 16; o; o >>= 1) s2 += __shfl_xor_sync(0xffffffffu, s2, o);
    if ((tid & 31) == 0) r1[tid >> 5] = s2;
    __syncthreads();
    float mu2 = (r1[0] + r1[1] + r1[2] + r1[3]) * (1.0f / DD);
    float d2 = hv - mu2;
    float q2 = d2 * d2;
    #pragma unroll
    for (int o = 16; o; o >>= 1) q2 += __shfl_xor_sync(0xffffffffu, q2, o);
    if ((tid & 31) == 0) r2[tid >> 5] = q2;
    __syncthreads();
    float var2 = (r2[0] + r2[1] + r2[2] + r2[3]) * (1.0f / DD);
    xn[(size_t)row * DD + tid] = d2 * rsqrtf(var2 + 1e-5f) * ln2w[tid];
}

// float4 conv: one thread = 4 consecutive channels
template<int LDX, int C>
__global__ void conv_silu4_kernel(const float* __restrict__ x,
                                  const float* __restrict__ w, const float* __restrict__ bias,
                                  float* __restrict__ out) {
    int idx = blockIdx.x * blockDim.x + threadIdx.x;
    constexpr int NC = C / 4;
    int c4 = (idx & (NC - 1)) * 4;
    int s = (idx / NC) & (SS - 1);
    int b = idx / (NC * SS);
    const float* xp = x + ((size_t)b * SS) * LDX + c4;
    float4 acc = *(const float4*)(bias + c4);
    #pragma unroll
    for (int j = 0; j < 4; j++) {
        int sj = s + j - 3;
        if (sj >= 0) {
            float4 xv = *(const float4*)(xp + (size_t)sj * LDX);
            acc.x += xv.x * w[(c4 + 0) * 4 + j];
            acc.y += xv.y * w[(c4 + 1) * 4 + j];
            acc.z += xv.z * w[(c4 + 2) * 4 + j];
            acc.w += xv.w * w[(c4 + 3) * 4 + j];
        }
    }
    float4 o;
    o.x = acc.x / (1.0f + __expf(-acc.x));
    o.y = acc.y / (1.0f + __expf(-acc.y));
    o.z = acc.z / (1.0f + __expf(-acc.z));
    o.w = acc.w / (1.0f + __expf(-acc.w));
    *(float4*)(out + ((size_t)b * SS + s) * C + c4) = o;
}

__global__ void transpose_w_kernel(const float* __restrict__ ig, const float* __restrict__ fg,
                                   const float* __restrict__ zg, const float* __restrict__ og,
                                   float* __restrict__ wT, int off) {
    int idx = off + blockIdx.x * blockDim.x + threadIdx.x;
    int layer = idx >> 14;
    int arr = (idx >> 12) & 3;
    int r = idx & 4095;
    int h = r >> 10, e = (r >> 5) & 31, d = r & 31;
    const float* src = (arr == 0) ? ig : (arr == 1) ? fg : (arr == 2) ? zg : og;
    wT[layer * 16384 + arr * 4096 + h * 1024 + d * 32 + e] =
        src[layer * 4096 + h * 1024 + e * 32 + d];
}

// ---------------- mLSTM qkv: weights in regs, 8 rows per thread ----------------
__global__ void __launch_bounds__(256)
mlstm_qkv_kernel(const float* __restrict__ xca, const float* __restrict__ big,
                 const float* __restrict__ qw, const float* __restrict__ kw,
                 const float* __restrict__ vw,
                 float* __restrict__ q, float* __restrict__ k, float* __restrict__ v) {
    int tid = threadIdx.x;
    int blk = tid >> 3, e = tid & 7;
    size_t bs0 = (size_t)blockIdx.x * 8;
    const float* qp = qw + blk * 64 + e * 8;
    const float* kp = kw + blk * 64 + e * 8;
    const float* vp = vw + blk * 64 + e * 8;
    float4 q0 = *(const float4*)qp, q1 = *(const float4*)(qp + 4);
    float4 k0 = *(const float4*)kp, k1 = *(const float4*)(kp + 4);
    float4 v0 = *(const float4*)vp, v1 = *(const float4*)(vp + 4);
    #pragma unroll
    for (int i = 0; i < 8; i++) {
        size_t bs = bs0 + i;
        const float* xc = xca + bs * DIM + blk * 8;
        const float* xi = big + bs * 512 + blk * 8;
        float4 x0 = *(const float4*)xc, x1 = *(const float4*)(xc + 4);
        float4 i0 = *(const float4*)xi, i1 = *(const float4*)(xi + 4);
        float aq = x0.x*q0.x + x0.y*q0.y + x0.z*q0.z + x0.w*q0.w
                 + x1.x*q1.x + x1.y*q1.y + x1.z*q1.z + x1.w*q1.w;
        float ak = x0.x*k0.x + x0.y*k0.y + x0.z*k0.z + x0.w*k0.w
                 + x1.x*k1.x + x1.y*k1.y + x1.z*k1.z + x1.w*k1.w;
        float av = i0.x*v0.x + i0.y*v0.y + i0.z*v0.z + i0.w*v0.w
                 + i1.x*v1.x + i1.y*v1.y + i1.z*v1.z + i1.w*v1.w;
        q[bs * DIM + tid] = aq;
        k[bs * DIM + tid] = ak;
        v[bs * DIM + tid] = av;
    }
}

// ---------------- mLSTM gates via tf32 mma ----------------
__global__ void __launch_bounds__(256)
mlstm_gates_mma(const float* __restrict__ q, const float* __restrict__ k,
                const float* __restrict__ v,
                const float* __restrict__ igw, const float* __restrict__ igb,
                const float* __restrict__ fgw, const float* __restrict__ fgb,
                float* __restrict__ ip, float* __restrict__ fp) {
    __shared__ uint32_t sW[8][768];
    int tid = threadIdx.x;
    for (int i = tid; i < 8 * 768; i += 256) {
        int n = i / 768, kk = i - n * 768;
        float wv = (n < 4) ? igw[n * 768 + kk] : fgw[(n - 4) * 768 + kk];
        sW[n][kk] = f2tf32(wv);
    }
    __syncthreads();
    int w = tid >> 5, lane = tid & 31;
    int g = lane >> 2, t = lane & 3;
    int base = blockIdx.x * 128 + w * 16;
    float acc[4] = {0.f, 0.f, 0.f, 0.f};
    const float* arrs[3] = {q, k, v};
    #pragma unroll
    for (int seg = 0; seg < 3; seg++) {
        const float* r0 = arrs[seg] + (size_t)(base + g) * 256;
        const float* r1 = arrs[seg] + (size_t)(base + g + 8) * 256;
        const uint32_t* wrow = &sW[g][seg * 256];
        for (int ks = 0; ks < 32; ks++) {
            int k0 = ks * 8;
            uint32_t a[4], b[2];
            a[0] = f2tf32(r0[k0 + t]);
            a[1] = f2tf32(r1[k0 + t]);
            a[2] = f2tf32(r0[k0 + t + 4]);
            a[3] = f2tf32(r1[k0 + t + 4]);
            b[0] = wrow[k0 + t];
            b[1] = wrow[k0 + t + 4];
            mma_tf32(acc, a, b);
        }
    }
    int rows[2] = {base + g, base + g + 8};
    int ns[2] = {2 * t, 2 * t + 1};
    #pragma unroll
    for (int ri = 0; ri < 2; ri++) {
        #pragma unroll
        for (int ci = 0; ci < 2; ci++) {
            float val = acc[ri * 2 + ci];
            int row = rows[ri], n = ns[ci];
            int b_ = row >> 8, s = row & 255;
            if (n < 4) ip[(b_ * NHH + n) * SS + s] = val + igb[n];
            else       fp[(b_ * NHH + (n - 4)) * SS + s] = val + fgb[n - 4];
        }
    }
}

// ---------------- parallel gate prefix ----------------
__global__ void mlstm_prefix_kernel(const float* __restrict__ ip, const float* __restrict__ fp,
                                    float* __restrict__ slf, float* __restrict__ ek,
                                    float* __restrict__ pmx) {
    int warp = (blockIdx.x * blockDim.x + threadIdx.x) >> 5;
    int lane = threadIdx.x & 31;
    size_t base = (size_t)warp * SS + lane * 8;
    float fv[8], iv[8];
    {
        float4 a = *(const float4*)(fp + base);
        float4 b = *(const float4*)(fp + base + 4);
        fv[0]=a.x; fv[1]=a.y; fv[2]=a.z; fv[3]=a.w; fv[4]=b.x; fv[5]=b.y; fv[6]=b.z; fv[7]=b.w;
        float4 c = *(const float4*)(ip + base);
        float4 d = *(const float4*)(ip + base + 4);
        iv[0]=c.x; iv[1]=c.y; iv[2]=c.z; iv[3]=c.w; iv[4]=d.x; iv[5]=d.y; iv[6]=d.z; iv[7]=d.w;
    }
    float ls[8], lsum = 0.f;
    #pragma unroll
    for (int t = 0; t < 8; t++) {
        float f = fv[t];
        ls[t] = fminf(f, 0.f) - log1pf(expf(-fabsf(f)));
        lsum += ls[t];
    }
    float run = lsum;
    #pragma unroll
    for (int o = 1; o < 32; o <<= 1) {
        float vv = __shfl_up_sync(0xffffffffu, run, o);
        if (lane >= o) run += vv;
    }
    float c = run - lsum;
    float sl[8], ev[8], lmax = -1e30f;
    #pragma unroll
    for (int t = 0; t < 8; t++) {
        c += ls[t];
        sl[t] = c;
        ev[t] = iv[t] - c;
        lmax = fmaxf(lmax, ev[t]);
    }
    float rmax = lmax;
    #pragma unroll
    for (int o = 1; o < 32; o <<= 1) {
        float vv = __shfl_up_sync(0xffffffffu, rmax, o);
        if (lane >= o) rmax = fmaxf(rmax, vv);
    }
    float exclmax = __shfl_up_sync(0xffffffffu, rmax, 1);
    if (lane == 0) exclmax = -1e30f;
    float pm[8];
    float cm = exclmax;
    #pragma unroll
    for (int t = 0; t < 8; t++) {
        cm = fmaxf(cm, ev[t]);
        pm[t] = cm;
    }
    *(float4*)(slf + base)     = make_float4(sl[0], sl[1], sl[2], sl[3]);
    *(float4*)(slf + base + 4) = make_float4(sl[4], sl[5], sl[6], sl[7]);
    *(float4*)(ek + base)      = make_float4(ev[0], ev[1], ev[2], ev[3]);
    *(float4*)(ek + base + 4)  = make_float4(ev[4], ev[5], ev[6], ev[7]);
    *(float4*)(pmx + base)     = make_float4(pm[0], pm[1], pm[2], pm[3]);
    *(float4*)(pmx + base + 4) = make_float4(pm[4], pm[5], pm[6], pm[7]);
}

// ---------------- tensor-core attention + fused head group-LN epilogue ----------------
#define ATTN_SMEM_U32 (17408 + 16640 + 8*32*68 + 768)
#define ATTN_SMEM_B   (ATTN_SMEM_U32 * 4)
__global__ void __launch_bounds__(256, 1)
mlstm_attn_tc(const float* __restrict__ q, const float* __restrict__ k,
              const float* __restrict__ v,
              const float* __restrict__ slf, const float* __restrict__ ek,
              const float* __restrict__ pmx, const float* __restrict__ onw,
              float* __restrict__ out) {
    extern __shared__ uint32_t su[];
    uint32_t* sK  = su;                    // [256][68]
    uint32_t* sVT = su + 17408;            // [64][260]
    uint32_t* sC  = su + 17408 + 16640;    // [8][32][68]
    float* s_ce = (float*)(su + 17408 + 16640 + 8*32*68);
    float* s_px = s_ce + 256;
    float* s_lf = s_px + 256;

    int bh = blockIdx.x, b = bh >> 2, h = bh & 3;
    int tid = threadIdx.x, w = tid >> 5, lane = tid & 31;
    int g = lane >> 2, t = lane & 3;

    const float* kb = k + ((size_t)b * SS) * DIM + h * 64;
    const float* vb = v + ((size_t)b * SS) * DIM + h * 64;
    for (int e = tid; e < SS * 64; e += 256) {
        int kk = e >> 6, d = e & 63;
        sK [kk * 68 + d]  = f2tf32(kb[(size_t)kk * DIM + d]);
        sVT[d * 260 + kk] = f2tf32(vb[(size_t)kk * DIM + d]);
    }
    for (int i = tid; i < SS; i += 256) {
        s_ce[i] = __expf(fminf(ek[(size_t)bh * SS + i], 80.f));
        s_px[i] = pmx[(size_t)bh * SS + i];
        s_lf[i] = slf[(size_t)bh * SS + i];
    }

    int r = (w < 4) ? 2 * w : 15 - 2 * w;
    int rb = r * 32;
    const float* qb = q + ((size_t)(b * SS + rb)) * DIM + h * 64;
    uint32_t qa[2][8][4];
    #pragma unroll
    for (int mi = 0; mi < 2; mi++)
        #pragma unroll
        for (int dc = 0; dc < 8; dc++) {
            qa[mi][dc][0] = f2tf32(qb[(size_t)(mi*16+g)   * DIM + dc*8 + t]);
            qa[mi][dc][1] = f2tf32(qb[(size_t)(mi*16+g+8) * DIM + dc*8 + t]);
            qa[mi][dc][2] = f2tf32(qb[(size_t)(mi*16+g)   * DIM + dc*8 + t + 4]);
            qa[mi][dc][3] = f2tf32(qb[(size_t)(mi*16+g+8) * DIM + dc*8 + t + 4]);
        }
    __syncthreads();

    float qf[2][2];
    #pragma unroll
    for (int mi = 0; mi < 2; mi++)
        #pragma unroll
        for (int ri = 0; ri < 2; ri++)
            qf[mi][ri] = __expf(fminf(-s_px[rb + mi*16 + g + 8*ri], 80.f));

    float Oacc[2][8][4] = {};
    float rs[2][2] = {};
    uint32_t* myC = sC + w * (32 * 68);
    int ntile = (r >> 1) + 1;

    for (int tt = 0; tt < ntile; tt++) {
        int kc = tt * 64;
        float Sacc[2][8][4] = {};
        #pragma unroll
        for (int dc = 0; dc < 8; dc++) {
            uint32_t bf[8][2];
            #pragma unroll
            for (int ni = 0; ni < 8; ni++) {
                int krow = kc + ni * 8 + g;
                bf[ni][0] = sK[krow * 68 + dc * 8 + t];
                bf[ni][1] = sK[krow * 68 + dc * 8 + t + 4];
            }
            #pragma unroll
            for (int mi = 0; mi < 2; mi++)
                #pragma unroll
                for (int ni = 0; ni < 8; ni++)
                    mma_tf32(Sacc[mi][ni], qa[mi][dc], bf[ni]);
        }
        #pragma unroll
        for (int ni = 0; ni < 8; ni++) {
            int c0 = kc + ni * 8 + 2 * t;
            float ce0 = 0.125f * s_ce[c0], ce1 = 0.125f * s_ce[c0 + 1];
            #pragma unroll
            for (int mi = 0; mi < 2; mi++) {
                #pragma unroll
                for (int ri = 0; ri < 2; ri++) {
                    int lrow = mi * 16 + g + 8 * ri;
                    int qrow = rb + lrow;
                    float f = qf[mi][ri];
                    float v0 = Sacc[mi][ni][ri * 2]     * ce0 * f;
                    float v1 = Sacc[mi][ni][ri * 2 + 1] * ce1 * f;
                    if (c0 > qrow) v0 = 0.f;
                    if (c0 + 1 > qrow) v1 = 0.f;
                    rs[mi][ri] += v0 + v1;
                    myC[lrow * 68 + ni * 8 + 2 * t]     = f2tf32(v0);
                    myC[lrow * 68 + ni * 8 + 2 * t + 1] = f2tf32(v1);
                }
            }
        }
        __syncwarp();
        #pragma unroll
        for (int kch = 0; kch < 8; kch++) {
            uint32_t af[2][4];
            #pragma unroll
            for (int mi = 0; mi < 2; mi++) {
                af[mi][0] = myC[(mi*16+g)   * 68 + kch*8 + t];
                af[mi][1] = myC[(mi*16+g+8) * 68 + kch*8 + t];
                af[mi][2] = myC[(mi*16+g)   * 68 + kch*8 + t + 4];
                af[mi][3] = myC[(mi*16+g+8) * 68 + kch*8 + t + 4];
            }
            uint32_t bf2[8][2];
            #pragma unroll
            for (int dn = 0; dn < 8; dn++) {
                int drow = dn * 8 + g;
                bf2[dn][0] = sVT[drow * 260 + kc + kch * 8 + t];
                bf2[dn][1] = sVT[drow * 260 + kc + kch * 8 + t + 4];
            }
            #pragma unroll
            for (int mi = 0; mi < 2; mi++)
                #pragma unroll
                for (int dn = 0; dn < 8; dn++)
                    mma_tf32(Oacc[mi][dn], af[mi], bf2[dn]);
        }
        __syncwarp();
    }

    #pragma unroll
    for (int mi = 0; mi < 2; mi++)
        #pragma unroll
        for (int ri = 0; ri < 2; ri++) {
            float s = rs[mi][ri];
            s += __shfl_xor_sync(0xffffffffu, s, 1);
            s += __shfl_xor_sync(0xffffffffu, s, 2);
            rs[mi][ri] = s;
        }
    float wv[8][2];
    #pragma unroll
    for (int dn = 0; dn < 8; dn++) {
        wv[dn][0] = onw[h * 64 + dn * 8 + 2 * t];
        wv[dn][1] = onw[h * 64 + dn * 8 + 2 * t + 1];
    }
    #pragma unroll
    for (int mi = 0; mi < 2; mi++) {
        #pragma unroll
        for (int ri = 0; ri < 2; ri++) {
            int qrow = rb + mi * 16 + g + 8 * ri;
            float maxd = s_lf[qrow] + s_px[qrow];
            float inv = 1.0f / (fmaxf(fabsf(rs[mi][ri]), __expf(fminf(-maxd, 80.f))) + 1e-6f);
            float vals[8][2];
            float s = 0.f;
            #pragma unroll
            for (int dn = 0; dn < 8; dn++) {
                vals[dn][0] = Oacc[mi][dn][ri * 2]     * inv;
                vals[dn][1] = Oacc[mi][dn][ri * 2 + 1] * inv;
                s += vals[dn][0] + vals[dn][1];
            }
            s += __shfl_xor_sync(0xffffffffu, s, 1);
            s += __shfl_xor_sync(0xffffffffu, s, 2);
            float mu = s * (1.0f / 64.0f);
            float sq = 0.f;
            #pragma unroll
            for (int dn = 0; dn < 8; dn++) {
                float d0 = vals[dn][0] - mu, d1 = vals[dn][1] - mu;
                sq += d0 * d0 + d1 * d1;
            }
            sq += __shfl_xor_sync(0xffffffffu, sq, 1);
            sq += __shfl_xor_sync(0xffffffffu, sq, 2);
            float rr = rsqrtf(sq * (1.0f / 64.0f) + 1e-5f);
            float* ob = out + ((size_t)(b * SS + qrow)) * DIM + h * 64;
            #pragma unroll
            for (int dn = 0; dn < 8; dn++) {
                float2 o;
                o.x = (vals[dn][0] - mu) * rr * wv[dn][0];
                o.y = (vals[dn][1] - mu) * rr * wv[dn][1];
                *(float2*)(ob + dn * 8 + 2 * t) = o;
            }
        }
    }
}

// sLSTM block-diagonal gates — weights in regs, 8 rows/thread, 2 gates/thread
__global__ void __launch_bounds__(256)
slstm_bd8_kernel(const float* __restrict__ xc, const float* __restrict__ xn,
                 const float* __restrict__ wT,
                 float* __restrict__ gi, float* __restrict__ gf,
                 float* __restrict__ gz, float* __restrict__ go) {
    int tid = threadIdx.x;
    int c = tid & 127, half = tid >> 7;
    int h = c >> 5, e = c & 31;
    size_t bs0 = (size_t)blockIdx.x * 8;
    const float* w0 = wT + half * 8192 + h * 1024 + e;
    const float* w1 = w0 + 4096;
    float wa[32], wb[32];
    #pragma unroll
    for (int d = 0; d < 32; d++) { wa[d] = w0[d * 32]; wb[d] = w1[d * 32]; }
    const float* src = half ? xn : xc;
    float* o1 = half ? gz : gi;
    float* o2 = half ? go : gf;
    #pragma unroll
    for (int i = 0; i < 8; i++) {
        size_t bs = bs0 + i;
        const float* xb = src + bs * DD + h * 32;
        float a1 = 0.f, a2 = 0.f;
        #pragma unroll
        for (int d = 0; d < 32; d += 4) {
            float4 xv = *(const float4*)(xb + d);
            a1 += xv.x * wa[d] + xv.y * wa[d+1] + xv.z * wa[d+2] + xv.w * wa[d+3];
            a2 += xv.x * wb[d] + xv.y * wb[d+1] + xv.z * wb[d+2] + xv.w * wb[d+3];
        }
        o1[bs * DD + c] = a1;
        o2[bs * DD + c] = a2;
    }
}

// ---------------- register-resident warp-per-head sLSTM scan ----------------
__global__ void __launch_bounds__(128, 1)
slstm_scan_warp(const float* __restrict__ gi, const float* __restrict__ gf,
                const float* __restrict__ gz, const float* __restrict__ go,
                const float* __restrict__ rw, const float* __restrict__ bias,
                float* __restrict__ y) {
    int b = blockIdx.x;
    int lane = threadIdx.x & 31, hh = threadIdx.x >> 5;
    float wi[32], wf[32], wz[32], wo[32];
    const float* wb = rw + hh * 4096 + lane;
    #pragma unroll
    for (int d = 0; d < 32; d++) {
        wi[d] = wb[d * 128];
        wf[d] = wb[d * 128 + 32];
        wz[d] = wb[d * 128 + 64];
        wo[d] = wb[d * 128 + 96];
    }
    float bi = bias[hh * 128 + lane];
    float bfv = bias[hh * 128 + 32 + lane];
    float bz = bias[hh * 128 + 64 + lane];
    float bo = bias[hh * 128 + 96 + lane];
    float hs = 0.f, cs = 0.f, ns = 0.f, ms = 0.f;
    size_t base = (size_t)b * SS * DD + hh * 32 + lane;
    float ngi = gi[base], ngf = gf[base], ngz = gz[base], ngo = go[base];
    for (int t = 0; t < SS; t++) {
        float ixt = ngi, fxt = ngf, zxt = ngz, oxt = ngo;
        if (t + 1 < SS) {
            size_t nb = base + (size_t)(t + 1) * DD;
            ngi = gi[nb]; ngf = gf[nb]; ngz = gz[nb]; ngo = go[nb];
        }
        float ri0 = 0, ri1 = 0, rf0 = 0, rf1 = 0, rz0 = 0, rz1 = 0, ro0 = 0, ro1 = 0;
        #pragma unroll
        for (int d = 0; d < 32; d += 2) {
            float h0 = __shfl_sync(0xffffffffu, hs, d);
            float h1 = __shfl_sync(0xffffffffu, hs, d + 1);
            ri0 += h0 * wi[d]; ri1 += h1 * wi[d + 1];
            rf0 += h0 * wf[d]; rf1 += h1 * wf[d + 1];
            rz0 += h0 * wz[d]; rz1 += h1 * wz[d + 1];
            ro0 += h0 * wo[d]; ro1 += h1 * wo[d + 1];
        }
        float ix = ixt + (ri0 + ri1) + bi;
        float fx = fxt + (rf0 + rf1) + bfv;
        float zx = zxt + (rz0 + rz1) + bz;
        float ox = oxt + (ro0 + ro1) + bo;
        float ls  = fminf(fx, 0.f) - log1pf(__expf(-fabsf(fx)));
        float lpm = ms + ls;
        float mn  = fmaxf(ix, lpm);
        float ig  = __expf(ix - mn);
        float fg  = __expf(lpm - mn);
        float cn  = fg * cs + ig * tanhf(zx);
        float nn  = fg * ns + ig;
        float hn  = cn / (nn * (1.0f + __expf(-ox)));
        cs = cn; ns = nn; ms = mn; hs = hn;
        y[base + (size_t)t * DD] = hn;
    }
}

// ---------------- bf16 GEMM: 128x128 tile, m16n8k16; optional fused row-LN epilogue ----
// EPILN=1 requires N==128 and gridDim.x==1. LN scratch ALIASES sA/sB (dead after
// last compute) to stay under the 48KB static smem limit.
template<int AOP, int EPILN>
__global__ void __launch_bounds__(256)
gemm_bf16_kernel(const float* __restrict__ A, const float* __restrict__ A2,
                 const float* __restrict__ A3, const float* __restrict__ Askip,
                 const float* __restrict__ W, float* __restrict__ C,
                 int N, int Kd, int accum,
                 const float* __restrict__ lnw, float* __restrict__ xnout) {
    __shared__ __align__(16) uint32_t sA[2][128][20];
    __shared__ __align__(16) uint32_t sB[2][128][20];
    const int bm = blockIdx.y * 128, bn = blockIdx.x * 128;
    const int tid = threadIdx.x;
    const int wid = tid >> 5, lane = tid & 31;
    const int wm = wid & 1, wn = wid >> 1;
    const int g = lane >> 2, t = lane & 3;
    const int arow = tid >> 1;
    const int half = tid & 1;
    float acc[4][4][4] = {};

    auto loadA4 = [&](int gr, int gk) -> float4 {
        float4 r;
        if (AOP == 0) {
            r = *(const float4*)(A + (size_t)gr * Kd + gk);
        } else if (AOP == 1) {
            float4 gg = *(const float4*)(A + (size_t)gr * 512 + gk);
            float4 u  = *(const float4*)(A + (size_t)gr * 512 + 256 + gk);
            r.x = 0.5f * gg.x * (1.0f + erff(gg.x * 0.70710678f)) * u.x;
            r.y = 0.5f * gg.y * (1.0f + erff(gg.y * 0.70710678f)) * u.y;
            r.z = 0.5f * gg.z * (1.0f + erff(gg.z * 0.70710678f)) * u.z;
            r.w = 0.5f * gg.w * (1.0f + erff(gg.w * 0.70710678f)) * u.w;
        } else {
            float4 hv = *(const float4*)(A  + (size_t)gr * 256 + gk);
            float4 xv = *(const float4*)(A2 + (size_t)gr * 256 + gk);
            float4 sk = *(const float4*)(Askip + gk);
            float4 zv = *(const float4*)(A3 + (size_t)gr * 512 + 256 + gk);
            r.x = (hv.x + sk.x * xv.x) * (zv.x / (1.0f + __expf(-zv.x)));
            r.y = (hv.y + sk.y * xv.y) * (zv.y / (1.0f + __expf(-zv.y)));
            r.z = (hv.z + sk.z * xv.z) * (zv.z / (1.0f + __expf(-zv.z)));
            r.w = (hv.w + sk.w * xv.w) * (zv.w / (1.0f + __expf(-zv.w)));
        }
        return r;
    };

    auto stage = [&](int bf, int chunk) {
        int gk = chunk * 32 + half * 16;
        int wb = half * 8;
        float4 a0 = loadA4(bm + arow, gk);
        float4 a1 = loadA4(bm + arow, gk + 4);
        float4 a2 = loadA4(bm + arow, gk + 8);
        float4 a3 = loadA4(bm + arow, gk + 12);
        sA[bf][arow][wb+0] = pkbf2(a0.x, a0.y); sA[bf][arow][wb+1] = pkbf2(a0.z, a0.w);
        sA[bf][arow][wb+2] = pkbf2(a1.x, a1.y); sA[bf][arow][wb+3] = pkbf2(a1.z, a1.w);
        sA[bf][arow][wb+4] = pkbf2(a2.x, a2.y); sA[bf][arow][wb+5] = pkbf2(a2.z, a2.w);
        sA[bf][arow][wb+6] = pkbf2(a3.x, a3.y); sA[bf][arow][wb+7] = pkbf2(a3.z, a3.w);
        const float* wr = W + (size_t)(bn + arow) * Kd + gk;
        float4 b0 = *(const float4*)wr;
        float4 b1 = *(const float4*)(wr + 4);
        float4 b2 = *(const float4*)(wr + 8);
        float4 b3 = *(const float4*)(wr + 12);
        sB[bf][arow][wb+0] = pkbf2(b0.x, b0.y); sB[bf][arow][wb+1] = pkbf2(b0.z, b0.w);
        sB[bf][arow][wb+2] = pkbf2(b1.x, b1.y); sB[bf][arow][wb+3] = pkbf2(b1.z, b1.w);
        sB[bf][arow][wb+4] = pkbf2(b2.x, b2.y); sB[bf][arow][wb+5] = pkbf2(b2.z, b2.w);
        sB[bf][arow][wb+6] = pkbf2(b3.x, b3.y); sB[bf][arow][wb+7] = pkbf2(b3.z, b3.w);
    };

    auto compute = [&](int bf) {
        #pragma unroll
        for (int ks = 0; ks < 2; ks++) {
            int kb = ks * 8;
            uint32_t af[4][4], bfr[4][2];
            #pragma unroll
            for (int mi = 0; mi < 4; mi++) {
                int r0 = wm * 64 + mi * 16 + g;
                af[mi][0] = sA[bf][r0][kb + t];
                af[mi][1] = sA[bf][r0 + 8][kb + t];
                af[mi][2] = sA[bf][r0][kb + t + 4];
                af[mi][3] = sA[bf][r0 + 8][kb + t + 4];
            }
            #pragma unroll
            for (int ni = 0; ni < 4; ni++) {
                int c0 = wn * 32 + ni * 8 + g;
                bfr[ni][0] = sB[bf][c0][kb + t];
                bfr[ni][1] = sB[bf][c0][kb + t + 4];
            }
            #pragma unroll
            for (int mi = 0; mi < 4; mi++)
                #pragma unroll
                for (int ni = 0; ni < 4; ni++)
                    mma_bf16(acc[mi][ni], af[mi], bfr[ni]);
        }
    };

    stage(0, 0);
    __syncthreads();
    int buf = 0;
    int nchunks = Kd >> 5;
    for (int ch = 1; ch < nchunks; ch++) {
        int nb = buf ^ 1;
        stage(nb, ch);
        compute(buf);
        __syncthreads();
        buf = nb;
    }
    compute(buf);

    // epilogue: write C (h), with residual add into acc if accum
    #pragma unroll
    for (int mi = 0; mi < 4; mi++) {
        #pragma unroll
        for (int ni = 0; ni < 4; ni++) {
            int grow = bm + wm * 64 + mi * 16 + g;
            int gcol = bn + wn * 32 + ni * 8 + t * 2;
            float* p0 = C + (size_t)grow * N + gcol;
            float* p1 = C + (size_t)(grow + 8) * N + gcol;
            if (accum) {
                float2 x0 = *(float2*)p0, x1 = *(float2*)p1;
                acc[mi][ni][0] += x0.x; acc[mi][ni][1] += x0.y;
                acc[mi][ni][2] += x1.x; acc[mi][ni][3] += x1.y;
            }
            *(float2*)p0 = make_float2(acc[mi][ni][0], acc[mi][ni][1]);
            *(float2*)p1 = make_float2(acc[mi][ni][2], acc[mi][ni][3]);
        }
    }

    if (EPILN) {
        // LN scratch aliased onto dead sA/sB (sA: 20480B >= 8704B; sB >= 1024B)
        float* sP    = (float*)sA;            // [128][17]
        float* sMu   = (float*)sB;            // [128]
        float* sRstd = sMu + 128;             // [128]
        int slot = wn * 4 + t;
        __syncthreads();   // all smem reads of sA/sB done before reuse
        #pragma unroll
        for (int mi = 0; mi < 4; mi++)
            #pragma unroll
            for (int ri = 0; ri < 2; ri++) {
                int rl = wm * 64 + mi * 16 + g + 8 * ri;
                float ps = 0.f;
                #pragma unroll
                for (int ni = 0; ni < 4; ni++)
                    ps += acc[mi][ni][ri * 2] + acc[mi][ni][ri * 2 + 1];
                sP[rl * 17 + slot] = ps;
            }
        __syncthreads();
        if (tid < 128) {
            float s = 0.f;
            #pragma unroll
            for (int i = 0; i < 16; i++) s += sP[tid * 17 + i];
            sMu[tid] = s * (1.0f / 128.0f);
        }
        __syncthreads();
        #pragma unroll
        for (int mi = 0; mi < 4; mi++)
            #pragma unroll
            for (int ri = 0; ri < 2; ri++) {
                int rl = wm * 64 + mi * 16 + g + 8 * ri;
                float mu = sMu[rl];
                float pv = 0.f;
                #pragma unroll
                for (int ni = 0; ni < 4; ni++) {
                    float d0 = acc[mi][ni][ri * 2] - mu;
                    float d1 = acc[mi][ni][ri * 2 + 1] - mu;
                    pv += d0 * d0 + d1 * d1;
                }
                sP[rl * 17 + slot] = pv;
            }
        __syncthreads();
        if (tid < 128) {
            float s = 0.f;
            #pragma unroll
            for (int i = 0; i < 16; i++) s += sP[tid * 17 + i];
            sRstd[tid] = rsqrtf(s * (1.0f / 128.0f) + 1e-5f);
        }
        __syncthreads();
        #pragma unroll
        for (int mi = 0; mi < 4; mi++)
            #pragma unroll
            for (int ri = 0; ri < 2; ri++) {
                int rl = wm * 64 + mi * 16 + g + 8 * ri;
                float mu = sMu[rl], rstd = sRstd[rl];
                #pragma unroll
                for (int ni = 0; ni < 4; ni++) {
                    int gcol = wn * 32 + ni * 8 + t * 2;
                    float2 o;
                    o.x = (acc[mi][ni][ri * 2]     - mu) * rstd * lnw[gcol];
                    o.y = (acc[mi][ni][ri * 2 + 1] - mu) * rstd * lnw[gcol + 1];
                    *(float2*)(xnout + (size_t)(bm + rl) * 128 + gcol) = o;
                }
            }
    }
}

extern "C" void kernel_launch(void* const* d_in, const int* in_sizes, int n_in,
                              void* d_out, int out_size) {
    const int*   x          = (const int*)  d_in[0];
    const float* emb        = (const float*)d_in[1];
    const float* m_ln_w     = (const float*)d_in[2];
    const float* m_up_w     = (const float*)d_in[3];
    const float* m_conv_w   = (const float*)d_in[4];
    const float* m_conv_b   = (const float*)d_in[5];
    const float* m_q_w      = (const float*)d_in[6];
    const float* m_k_w      = (const float*)d_in[7];
    const float* m_v_w      = (const float*)d_in[8];
    const float* m_ig_w     = (const float*)d_in[9];
    const float* m_ig_b     = (const float*)d_in[10];
    const float* m_fg_w     = (const float*)d_in[11];
    const float* m_fg_b     = (const float*)d_in[12];
    const float* m_on_w     = (const float*)d_in[13];
    const float* m_skip     = (const float*)d_in[14];
    const float* m_down_w   = (const float*)d_in[15];
    const float* s_ln1_w    = (const float*)d_in[16];
    const float* s_conv_w   = (const float*)d_in[17];
    const float* s_conv_b   = (const float*)d_in[18];
    const float* s_ig_w     = (const float*)d_in[19];
    const float* s_fg_w     = (const float*)d_in[20];
    const float* s_zg_w     = (const float*)d_in[21];
    const float* s_og_w     = (const float*)d_in[22];
    const float* s_rec_w    = (const float*)d_in[23];
    const float* s_bias     = (const float*)d_in[24];
    const float* s_gn_w     = (const float*)d_in[25];
    const float* s_ln2_w    = (const float*)d_in[26];
    const float* s_ff_up_w  = (const float*)d_in[27];
    const float* s_ff_down_w= (const float*)d_in[28];
    const float* post_norm_w= (const float*)d_in[29];
    float* out = (float*)d_out;

    float *h_, *xn_, *big_, *xca_, *q_, *k_, *v_, *ht_;
    float *gi_, *gf_, *gz_, *go_, *y_, *ip_, *fp_, *slf_, *ek_, *pmx_, *wT_;
    cudaGetSymbolAddress((void**)&h_,   g_h);
    cudaGetSymbolAddress((void**)&xn_,  g_xn);
    cudaGetSymbolAddress((void**)&big_, g_big);
    cudaGetSymbolAddress((void**)&xca_, g_xca);
    cudaGetSymbolAddress((void**)&q_,   g_q);
    cudaGetSymbolAddress((void**)&k_,   g_k);
    cudaGetSymbolAddress((void**)&v_,   g_v);
    cudaGetSymbolAddress((void**)&ht_,  g_ht);
    cudaGetSymbolAddress((void**)&gi_,  g_gi);
    cudaGetSymbolAddress((void**)&gf_,  g_gf);
    cudaGetSymbolAddress((void**)&gz_,  g_gz);
    cudaGetSymbolAddress((void**)&go_,  g_go);
    cudaGetSymbolAddress((void**)&y_,   g_y);
    cudaGetSymbolAddress((void**)&ip_,  g_ip);
    cudaGetSymbolAddress((void**)&fp_,  g_fp);
    cudaGetSymbolAddress((void**)&slf_, g_slf);
    cudaGetSymbolAddress((void**)&ek_,  g_ek);
    cudaGetSymbolAddress((void**)&pmx_, g_pmx);
    cudaGetSymbolAddress((void**)&wT_,  g_wT);

    cudaFuncSetAttribute(mlstm_attn_tc, cudaFuncAttributeMaxDynamicSharedMemorySize, ATTN_SMEM_B);

    // slots 1-3: embed_ln + transposes — slot 4 = bf16 up-GEMM (ncu probe)
    embed_ln_kernel<<<BS, 128>>>(x, emb, m_ln_w, h_, xn_);
    transpose_w_kernel<<<64, 256>>>(s_ig_w, s_fg_w, s_zg_w, s_og_w, wT_, 0);
    transpose_w_kernel<<<64, 256>>>(s_ig_w, s_fg_w, s_zg_w, s_og_w, wT_, 16384);
    gemm_bf16_kernel<0, 0><<<dim3(4, BS / 128), 256>>>(xn_, nullptr, nullptr, nullptr,
                                                       m_up_w, big_, 512, 128, 0, nullptr, nullptr);
    conv_silu4_kernel<512, 256><<<BS * 64 / 256, 256>>>(big_, m_conv_w, m_conv_b, xca_);
    mlstm_qkv_kernel<<<BS / 8, 256>>>(xca_, big_, m_q_w, m_k_w, m_v_w, q_, k_, v_);
    mlstm_gates_mma<<<BS / 128, 256>>>(q_, k_, v_, m_ig_w, m_ig_b, m_fg_w, m_fg_b, ip_, fp_);
    mlstm_prefix_kernel<<<64, 256>>>(ip_, fp_, slf_, ek_, pmx_);
    mlstm_attn_tc<<<BB * NHH, 256, ATTN_SMEM_B>>>(q_, k_, v_, slf_, ek_, pmx_, m_on_w, ht_);
    // down-proj + residual + fused LN (ln1 of sLSTM layer 0) -> h, xn
    gemm_bf16_kernel<2, 1><<<dim3(1, BS / 128), 256>>>(ht_, xca_, big_, m_skip,
                                                       m_down_w, h_, 128, 256, 1,
                                                       s_ln1_w, xn_);

    for (int i = 0; i < 2; i++) {
        conv_silu4_kernel<128, 128><<<BS * 32 / 256, 256>>>(xn_, s_conv_w + i * DD * 4,
                                                            s_conv_b + i * DD, xca_);
        slstm_bd8_kernel<<<BS / 8, 256>>>(xca_, xn_, wT_ + i * 16384,
                                          gi_, gf_, gz_, go_);
        slstm_scan_warp<<<BB, 128>>>(gi_, gf_, gz_, go_,
            s_rec_w + i * 16384, s_bias + i * 512, y_);
        slstm_post_kernel<<<BS, 128>>>(y_, s_gn_w + i * DD, s_ln2_w + i * DD, h_, xn_);
        gemm_bf16_kernel<0, 0><<<dim3(4, BS / 128), 256>>>(xn_, nullptr, nullptr, nullptr,
                                                           s_ff_up_w + i * 512 * 128, big_, 512, 128, 0,
                                                           nullptr, nullptr);
        // ffn-down + residual + fused LN: layer0 -> ln1 of layer1 into xn; layer1 -> post_norm into out
        const float* lnw = (i == 0) ? (s_ln1_w + DD) : post_norm_w;
        float* xnout = (i == 0) ? xn_ : out;
        gemm_bf16_kernel<1, 1><<<dim3(1, BS / 128), 256>>>(big_, nullptr, nullptr, nullptr,
                                                           s_ff_down_w + i * 128 * 256, h_, 128, 256, 1,
                                                           lnw, xnout);
    }
}